// round 1
// baseline (speedup 1.0000x reference)
#include <cuda_runtime.h>
#include <math.h>

#define B_  8
#define L_  4096
#define D_  1024
#define M_  64
#define BL_ (B_*L_)
#define C_  64   // chunks per batch
#define T_  64   // chunk length

// ---------------- scratch (static device globals: allowed) ----------------
__device__ float g_Q   [BL_*M_];        // 8 MB
__device__ float g_GK  [BL_*M_];        // gated k
__device__ float g_GV  [BL_*M_];        // gated v
__device__ float g_gate[BL_];
__device__ float g_A   [B_*C_*M_*M_];   // chunk summaries
__device__ float g_Spre[B_*C_*M_*M_];   // state BEFORE each chunk
__device__ float g_O   [BL_*M_];        // pre-Wo outputs

__device__ __forceinline__ float decay_val(const float* dp) {
    // DECAY_MIN + sigmoid(p)*(DECAY_MAX-DECAY_MIN)
    return 0.9f + 0.099f / (1.0f + expf(-dp[0]));
}

// ---------------- kernel 1: gates g = sigmoid(x @ Wg + bg) ----------------
__global__ void gate_kernel(const float* __restrict__ x,
                            const float* __restrict__ Wg,
                            const float* __restrict__ bg) {
    int warp = (blockIdx.x * blockDim.x + threadIdx.x) >> 5;
    int lane = threadIdx.x & 31;
    if (warp >= BL_) return;
    const float4* xr = (const float4*)(x + (size_t)warp * D_);
    const float4* wg = (const float4*)Wg;
    float sum = 0.f;
#pragma unroll
    for (int it = 0; it < D_/128; ++it) {          // 8 iters of float4
        float4 a = xr[lane + it*32];
        float4 b = wg[lane + it*32];
        sum += a.x*b.x + a.y*b.y + a.z*b.z + a.w*b.w;
    }
#pragma unroll
    for (int off = 16; off; off >>= 1) sum += __shfl_xor_sync(0xffffffffu, sum, off);
    if (lane == 0) g_gate[warp] = 1.0f / (1.0f + expf(-(sum + bg[0])));
}

// ------------- kernel 2: Q / gated-K / gated-V projections -----------------
// grid.x: row tiles of 128, grid.y in {0,1,2} selects projection.
__global__ void qkv_kernel(const float* __restrict__ x,
                           const float* __restrict__ Wq,
                           const float* __restrict__ Wk,
                           const float* __restrict__ Wv) {
    __shared__ float Xt[16][136];   // transposed X slab [k][row], pad 136
    __shared__ float Ws[16][64];

    const float* W   = (blockIdx.y == 0) ? Wq : (blockIdx.y == 1 ? Wk : Wv);
    float*       Out = (blockIdx.y == 0) ? g_Q : (blockIdx.y == 1 ? g_GK : g_GV);

    int t  = threadIdx.x;
    int ty = t >> 4, tx = t & 15;          // 16x16 threads, tile 8 rows x 4 cols
    int r0 = blockIdx.x * 128;

    float acc[8][4];
#pragma unroll
    for (int i = 0; i < 8; ++i)
#pragma unroll
        for (int j = 0; j < 4; ++j) acc[i][j] = 0.f;

#pragma unroll 1
    for (int k0 = 0; k0 < D_; k0 += 16) {
        __syncthreads();
        {   // load X tile 128x16 -> transposed
            int c4  = t & 3;
            int row = t >> 2;
#pragma unroll
            for (int p = 0; p < 2; ++p) {
                int r = row + p*64;
                float4 v = *(const float4*)(x + (size_t)(r0 + r)*D_ + k0 + c4*4);
                Xt[c4*4+0][r] = v.x;  Xt[c4*4+1][r] = v.y;
                Xt[c4*4+2][r] = v.z;  Xt[c4*4+3][r] = v.w;
            }
        }
        {   // load W tile 16x64
            int kk = t >> 4, c = t & 15;
            *(float4*)&Ws[kk][c*4] = *(const float4*)(W + (size_t)(k0+kk)*M_ + c*4);
        }
        __syncthreads();
#pragma unroll
        for (int kk = 0; kk < 16; ++kk) {
            float4 a0 = *(const float4*)&Xt[kk][ty*8];
            float4 a1 = *(const float4*)&Xt[kk][ty*8+4];
            float4 b  = *(const float4*)&Ws[kk][tx*4];
            float av[8] = {a0.x,a0.y,a0.z,a0.w,a1.x,a1.y,a1.z,a1.w};
            float bv[4] = {b.x,b.y,b.z,b.w};
#pragma unroll
            for (int i = 0; i < 8; ++i)
#pragma unroll
                for (int j = 0; j < 4; ++j) acc[i][j] += av[i]*bv[j];
        }
    }
    // epilogue: gate for K,V
#pragma unroll
    for (int i = 0; i < 8; ++i) {
        int row = r0 + ty*8 + i;
        float g = (blockIdx.y == 0) ? 1.0f : g_gate[row];
        float4 o = make_float4(acc[i][0]*g, acc[i][1]*g, acc[i][2]*g, acc[i][3]*g);
        *(float4*)(Out + (size_t)row*M_ + tx*4) = o;
    }
}

// --------- kernel 3: chunk summaries A_c[i][j] = sum_s d^{63-s} gk[s][i] gv[s][j]
__global__ void chunk_sum_kernel(const float* __restrict__ dp) {
    __shared__ float GKs[64][64];
    __shared__ float GVs[64][64];
    int b = blockIdx.y, c = blockIdx.x;
    int t = threadIdx.x;
    float d = decay_val(dp);
    size_t base = ((size_t)b*L_ + (size_t)c*T_) * M_;
    {
        int c4 = t & 15, sr = t >> 4;
#pragma unroll
        for (int p = 0; p < 4; ++p) {
            int s = sr + p*16;
            float w = powf(d, (float)(63 - s));
            float4 kv = *(const float4*)(g_GK + base + (size_t)s*M_ + c4*4);
            kv.x *= w; kv.y *= w; kv.z *= w; kv.w *= w;
            *(float4*)&GKs[s][c4*4] = kv;
            *(float4*)&GVs[s][c4*4] = *(const float4*)(g_GV + base + (size_t)s*M_ + c4*4);
        }
    }
    __syncthreads();
    int ty = t >> 4, tx = t & 15;
    float acc[4][4];
#pragma unroll
    for (int i = 0; i < 4; ++i)
#pragma unroll
        for (int j = 0; j < 4; ++j) acc[i][j] = 0.f;
#pragma unroll 8
    for (int s = 0; s < 64; ++s) {
        float4 a4 = *(const float4*)&GKs[s][ty*4];
        float4 b4 = *(const float4*)&GVs[s][tx*4];
        float av[4] = {a4.x,a4.y,a4.z,a4.w};
        float bv[4] = {b4.x,b4.y,b4.z,b4.w};
#pragma unroll
        for (int i = 0; i < 4; ++i)
#pragma unroll
            for (int j = 0; j < 4; ++j) acc[i][j] += av[i]*bv[j];
    }
    size_t ab = (size_t)(b*C_ + c) * (M_*M_);
#pragma unroll
    for (int i = 0; i < 4; ++i)
        *(float4*)(g_A + ab + (size_t)(ty*4+i)*M_ + tx*4) =
            make_float4(acc[i][0], acc[i][1], acc[i][2], acc[i][3]);
}

// --------- kernel 4: inter-chunk prefix scan: Spre[c]=S; S = d^T * S + A[c]
__global__ void chunk_scan_kernel(const float* __restrict__ dp,
                                  float* __restrict__ sfinal) {
    int b = blockIdx.x;
    float d  = decay_val(dp);
    float dT = powf(d, 64.0f);
    size_t eb = (size_t)threadIdx.x * 8;    // 512 threads * 8 = 4096 elems
    float4 S0 = make_float4(0,0,0,0), S1 = make_float4(0,0,0,0);
#pragma unroll 1
    for (int c = 0; c < C_; ++c) {
        size_t idx = (size_t)(b*C_ + c) * (M_*M_) + eb;
        *(float4*)(g_Spre + idx)     = S0;
        *(float4*)(g_Spre + idx + 4) = S1;
        float4 A0 = *(const float4*)(g_A + idx);
        float4 A1 = *(const float4*)(g_A + idx + 4);
        S0.x = dT*S0.x + A0.x;  S0.y = dT*S0.y + A0.y;
        S0.z = dT*S0.z + A0.z;  S0.w = dT*S0.w + A0.w;
        S1.x = dT*S1.x + A1.x;  S1.y = dT*S1.y + A1.y;
        S1.z = dT*S1.z + A1.z;  S1.w = dT*S1.w + A1.w;
    }
    *(float4*)(sfinal + (size_t)b*(M_*M_) + eb)     = S0;
    *(float4*)(sfinal + (size_t)b*(M_*M_) + eb + 4) = S1;
}

// --------- kernel 5: per-chunk outputs: O = d^{s+1} Q@Spre + (QK^T ⊙ mask)V
__global__ void chunk_out_kernel(const float* __restrict__ dp) {
    __shared__ float Qs [64][64];   // natural [s][m]
    __shared__ float Ps [64][64];   // masked P, [s][s']
    __shared__ float Buf[64][64];   // GK^T [m][s'] -> Spre [m][j] -> GV [s'][j]
    int b = blockIdx.y, c = blockIdx.x;
    int t = threadIdx.x, ty = t >> 4, tx = t & 15;
    float d = decay_val(dp);
    size_t rbase = (size_t)b*L_ + (size_t)c*T_;

    {   // load Q natural, GK transposed
        int c4 = t & 15, sr = t >> 4;
#pragma unroll
        for (int p = 0; p < 4; ++p) {
            int s = sr + p*16;
            *(float4*)&Qs[s][c4*4] = *(const float4*)(g_Q + (rbase+s)*M_ + c4*4);
            float4 k4 = *(const float4*)(g_GK + (rbase+s)*M_ + c4*4);
            Buf[c4*4+0][s] = k4.x;  Buf[c4*4+1][s] = k4.y;
            Buf[c4*4+2][s] = k4.z;  Buf[c4*4+3][s] = k4.w;
        }
    }
    __syncthreads();

    // phase 1: P = Q @ GK^T
    float pacc[4][4];
#pragma unroll
    for (int i = 0; i < 4; ++i)
#pragma unroll
        for (int j = 0; j < 4; ++j) pacc[i][j] = 0.f;
#pragma unroll 8
    for (int m = 0; m < 64; ++m) {
        float av[4];
#pragma unroll
        for (int i = 0; i < 4; ++i) av[i] = Qs[ty*4+i][m];
        float4 b4 = *(const float4*)&Buf[m][tx*4];
        float bv[4] = {b4.x,b4.y,b4.z,b4.w};
#pragma unroll
        for (int i = 0; i < 4; ++i)
#pragma unroll
            for (int j = 0; j < 4; ++j) pacc[i][j] += av[i]*bv[j];
    }
    // causal decay mask
#pragma unroll
    for (int i = 0; i < 4; ++i) {
        int s = ty*4 + i;
#pragma unroll
        for (int j = 0; j < 4; ++j) {
            int sp = tx*4 + j;
            Ps[s][sp] = (sp <= s) ? pacc[i][j] * powf(d, (float)(s - sp)) : 0.f;
        }
    }
    __syncthreads();

    // load Spre into Buf
    size_t sbase = (size_t)(b*C_ + c) * (M_*M_);
    {
        int c4 = t & 15, mr = t >> 4;
#pragma unroll
        for (int p = 0; p < 4; ++p) {
            int m = mr + p*16;
            *(float4*)&Buf[m][c4*4] = *(const float4*)(g_Spre + sbase + (size_t)m*M_ + c4*4);
        }
    }
    __syncthreads();

    // pass B (inter): acc = Q @ Spre, then scale by d^{s+1}
    float acc[4][4];
#pragma unroll
    for (int i = 0; i < 4; ++i)
#pragma unroll
        for (int j = 0; j < 4; ++j) acc[i][j] = 0.f;
#pragma unroll 8
    for (int m = 0; m < 64; ++m) {
        float av[4];
#pragma unroll
        for (int i = 0; i < 4; ++i) av[i] = Qs[ty*4+i][m];
        float4 b4 = *(const float4*)&Buf[m][tx*4];
        float bv[4] = {b4.x,b4.y,b4.z,b4.w};
#pragma unroll
        for (int i = 0; i < 4; ++i)
#pragma unroll
            for (int j = 0; j < 4; ++j) acc[i][j] += av[i]*bv[j];
    }
#pragma unroll
    for (int i = 0; i < 4; ++i) {
        float sc = powf(d, (float)(ty*4 + i + 1));
#pragma unroll
        for (int j = 0; j < 4; ++j) acc[i][j] *= sc;
    }
    __syncthreads();

    // load GV into Buf (natural)
    {
        int c4 = t & 15, sr = t >> 4;
#pragma unroll
        for (int p = 0; p < 4; ++p) {
            int s = sr + p*16;
            *(float4*)&Buf[s][c4*4] = *(const float4*)(g_GV + (rbase+s)*M_ + c4*4);
        }
    }
    __syncthreads();

    // pass A (intra): acc += P @ GV
#pragma unroll 8
    for (int sp = 0; sp < 64; ++sp) {
        float av[4];
#pragma unroll
        for (int i = 0; i < 4; ++i) av[i] = Ps[ty*4+i][sp];
        float4 b4 = *(const float4*)&Buf[sp][tx*4];
        float bv[4] = {b4.x,b4.y,b4.z,b4.w};
#pragma unroll
        for (int i = 0; i < 4; ++i)
#pragma unroll
            for (int j = 0; j < 4; ++j) acc[i][j] += av[i]*bv[j];
    }
#pragma unroll
    for (int i = 0; i < 4; ++i)
        *(float4*)(g_O + (rbase + ty*4 + i)*M_ + tx*4) =
            make_float4(acc[i][0], acc[i][1], acc[i][2], acc[i][3]);
}

// ---------------- kernel 6: y = O @ Wo + bo ----------------
__global__ void out_kernel(const float* __restrict__ Wo,
                           const float* __restrict__ bo,
                           float* __restrict__ y) {
    __shared__ float Os [64][68];   // padded: conflict-free scalar a-reads
    __shared__ float Ws2[64][64];
    int r0 = blockIdx.x * 64;
    int n0 = blockIdx.y * 64;
    int t = threadIdx.x, ty = t >> 4, tx = t & 15;
    {
        int c4 = t & 15, rr = t >> 4;
#pragma unroll
        for (int p = 0; p < 4; ++p) {
            int r = rr + p*16;
            *(float4*)&Os [r][c4*4] = *(const float4*)(g_O + (size_t)(r0+r)*M_ + c4*4);
            *(float4*)&Ws2[r][c4*4] = *(const float4*)(Wo  + (size_t)r*D_ + n0 + c4*4);
        }
    }
    __syncthreads();
    float acc[4][4];
#pragma unroll
    for (int i = 0; i < 4; ++i)
#pragma unroll
        for (int j = 0; j < 4; ++j) acc[i][j] = 0.f;
#pragma unroll 8
    for (int k = 0; k < 64; ++k) {
        float av[4];
#pragma unroll
        for (int i = 0; i < 4; ++i) av[i] = Os[ty*4+i][k];
        float4 b4 = *(const float4*)&Ws2[k][tx*4];
        float bv[4] = {b4.x,b4.y,b4.z,b4.w};
#pragma unroll
        for (int i = 0; i < 4; ++i)
#pragma unroll
            for (int j = 0; j < 4; ++j) acc[i][j] += av[i]*bv[j];
    }
    float4 bias = *(const float4*)(bo + n0 + tx*4);
#pragma unroll
    for (int i = 0; i < 4; ++i) {
        float4 o = make_float4(acc[i][0]+bias.x, acc[i][1]+bias.y,
                               acc[i][2]+bias.z, acc[i][3]+bias.w);
        *(float4*)(y + (size_t)(r0 + ty*4 + i)*D_ + n0 + tx*4) = o;
    }
}

// ---------------- launcher ----------------
extern "C" void kernel_launch(void* const* d_in, const int* in_sizes, int n_in,
                              void* d_out, int out_size) {
    const float* x  = (const float*)d_in[0];
    const float* Wq = (const float*)d_in[1];
    const float* Wk = (const float*)d_in[2];
    const float* Wv = (const float*)d_in[3];
    const float* Wo = (const float*)d_in[4];
    const float* bo = (const float*)d_in[5];
    const float* Wg = (const float*)d_in[6];
    const float* bg = (const float*)d_in[7];
    const float* dp = (const float*)d_in[8];
    float* y      = (float*)d_out;
    float* sfinal = y + (size_t)BL_ * D_;   // S_final appended after y

    gate_kernel     <<<BL_/8, 256>>>(x, Wg, bg);
    qkv_kernel      <<<dim3(BL_/128, 3), 256>>>(x, Wq, Wk, Wv);
    chunk_sum_kernel<<<dim3(C_, B_), 256>>>(dp);
    chunk_scan_kernel<<<B_, 512>>>(dp, sfinal);
    chunk_out_kernel<<<dim3(C_, B_), 256>>>(dp);
    out_kernel      <<<dim3(BL_/64, D_/64), 256>>>(Wo, bo, y);
}

// round 2
// speedup vs baseline: 1.0460x; 1.0460x over previous
#include <cuda_runtime.h>
#include <math.h>

#define B_  8
#define L_  4096
#define D_  1024
#define M_  64
#define BL_ (B_*L_)
#define C_  64   // chunks per batch
#define T_  64   // chunk length

typedef unsigned long long u64;

// ---------------- scratch ----------------
__device__ float g_Q   [BL_*M_];
__device__ float g_GK  [BL_*M_];
__device__ float g_GV  [BL_*M_];
__device__ float g_gate[BL_];
__device__ float g_A   [B_*C_*M_*M_];
__device__ float g_Spre[B_*C_*M_*M_];
__device__ float g_O   [BL_*M_];

__device__ __forceinline__ float decay_val(const float* dp) {
    return 0.9f + 0.099f / (1.0f + expf(-dp[0]));
}

// ---- packed f32x2 helpers ----
__device__ __forceinline__ u64 pk2(float lo, float hi) {
    u64 r; asm("mov.b64 %0,{%1,%2};" : "=l"(r) : "f"(lo), "f"(hi)); return r;
}
__device__ __forceinline__ u64 dup2(float v) {
    u64 r; asm("mov.b64 %0,{%1,%1};" : "=l"(r) : "f"(v)); return r;
}
__device__ __forceinline__ void upk2(u64 v, float& lo, float& hi) {
    asm("mov.b64 {%0,%1},%2;" : "=f"(lo), "=f"(hi) : "l"(v));
}
__device__ __forceinline__ u64 fma2(u64 a, u64 b, u64 c) {
    u64 d; asm("fma.rn.f32x2 %0,%1,%2,%3;" : "=l"(d) : "l"(a), "l"(b), "l"(c)); return d;
}
__device__ __forceinline__ u64 mul2(u64 a, u64 b) {
    u64 d; asm("mul.rn.f32x2 %0,%1,%2;" : "=l"(d) : "l"(a), "l"(b)); return d;
}

// ---------------- kernel 1: gates ----------------
__global__ void gate_kernel(const float* __restrict__ x,
                            const float* __restrict__ Wg,
                            const float* __restrict__ bg) {
    int warp = (blockIdx.x * blockDim.x + threadIdx.x) >> 5;
    int lane = threadIdx.x & 31;
    if (warp >= BL_) return;
    const float4* xr = (const float4*)(x + (size_t)warp * D_);
    const float4* wg = (const float4*)Wg;
    float sum = 0.f;
#pragma unroll
    for (int it = 0; it < D_/128; ++it) {
        float4 a = xr[lane + it*32];
        float4 b = wg[lane + it*32];
        sum += a.x*b.x + a.y*b.y + a.z*b.z + a.w*b.w;
    }
#pragma unroll
    for (int off = 16; off; off >>= 1) sum += __shfl_xor_sync(0xffffffffu, sum, off);
    if (lane == 0) g_gate[warp] = 1.0f / (1.0f + expf(-(sum + bg[0])));
}

// ------------- kernel 2: QKV projections (f32x2, packed along rows) --------
__global__ void qkv_kernel(const float* __restrict__ x,
                           const float* __restrict__ Wq,
                           const float* __restrict__ Wk,
                           const float* __restrict__ Wv) {
    __shared__ float Xt[16][136];   // transposed X slab [k][row]
    __shared__ float Ws[16][64];

    const float* W   = (blockIdx.y == 0) ? Wq : (blockIdx.y == 1 ? Wk : Wv);
    float*       Out = (blockIdx.y == 0) ? g_Q : (blockIdx.y == 1 ? g_GK : g_GV);

    int t  = threadIdx.x;
    int ty = t >> 4, tx = t & 15;          // 8 rows x 4 cols per thread
    int r0 = blockIdx.x * 128;

    u64 acc2[4][4];                        // [row-pair][col], packed over rows
#pragma unroll
    for (int i = 0; i < 4; ++i)
#pragma unroll
        for (int j = 0; j < 4; ++j) acc2[i][j] = 0ull;

#pragma unroll 1
    for (int k0 = 0; k0 < D_; k0 += 16) {
        __syncthreads();
        {   // X tile 128x16 -> transposed
            int c4  = t & 3;
            int row = t >> 2;
#pragma unroll
            for (int p = 0; p < 2; ++p) {
                int r = row + p*64;
                float4 v = *(const float4*)(x + (size_t)(r0 + r)*D_ + k0 + c4*4);
                Xt[c4*4+0][r] = v.x;  Xt[c4*4+1][r] = v.y;
                Xt[c4*4+2][r] = v.z;  Xt[c4*4+3][r] = v.w;
            }
        }
        {   // W tile 16x64
            int kk = t >> 4, c = t & 15;
            *(float4*)&Ws[kk][c*4] = *(const float4*)(W + (size_t)(k0+kk)*M_ + c*4);
        }
        __syncthreads();
#pragma unroll
        for (int kk = 0; kk < 16; ++kk) {
            u64 a2[4];
#pragma unroll
            for (int i = 0; i < 4; ++i)
                a2[i] = *(const u64*)&Xt[kk][ty*8 + i*2];
            float4 b = *(const float4*)&Ws[kk][tx*4];
            u64 bd[4] = {dup2(b.x), dup2(b.y), dup2(b.z), dup2(b.w)};
#pragma unroll
            for (int i = 0; i < 4; ++i)
#pragma unroll
                for (int j = 0; j < 4; ++j) acc2[i][j] = fma2(a2[i], bd[j], acc2[i][j]);
        }
    }
    // epilogue: unpack + gate
#pragma unroll
    for (int i = 0; i < 4; ++i) {
        int rlo = r0 + ty*8 + i*2;
        float glo = (blockIdx.y == 0) ? 1.0f : g_gate[rlo];
        float ghi = (blockIdx.y == 0) ? 1.0f : g_gate[rlo+1];
        float lo[4], hi[4];
#pragma unroll
        for (int j = 0; j < 4; ++j) upk2(acc2[i][j], lo[j], hi[j]);
        *(float4*)(Out + (size_t)rlo*M_ + tx*4) =
            make_float4(lo[0]*glo, lo[1]*glo, lo[2]*glo, lo[3]*glo);
        *(float4*)(Out + (size_t)(rlo+1)*M_ + tx*4) =
            make_float4(hi[0]*ghi, hi[1]*ghi, hi[2]*ghi, hi[3]*ghi);
    }
}

// --------- kernel 3: chunk summaries (f32x2, packed along cols) -----------
__global__ void chunk_sum_kernel(const float* __restrict__ dp) {
    __shared__ float GKs[64][64];
    __shared__ float GVs[64][64];
    int b = blockIdx.y, c = blockIdx.x;
    int t = threadIdx.x;
    float d = decay_val(dp);
    size_t base = ((size_t)b*L_ + (size_t)c*T_) * M_;
    {
        int c4 = t & 15, sr = t >> 4;
#pragma unroll
        for (int p = 0; p < 4; ++p) {
            int s = sr + p*16;
            float w = powf(d, (float)(63 - s));
            float4 kv = *(const float4*)(g_GK + base + (size_t)s*M_ + c4*4);
            kv.x *= w; kv.y *= w; kv.z *= w; kv.w *= w;
            *(float4*)&GKs[s][c4*4] = kv;
            *(float4*)&GVs[s][c4*4] = *(const float4*)(g_GV + base + (size_t)s*M_ + c4*4);
        }
    }
    __syncthreads();
    int ty = t >> 4, tx = t & 15;
    u64 acc2[4][2];
#pragma unroll
    for (int i = 0; i < 4; ++i) { acc2[i][0] = 0ull; acc2[i][1] = 0ull; }
#pragma unroll 8
    for (int s = 0; s < 64; ++s) {
        u64 b0 = *(const u64*)&GVs[s][tx*4];
        u64 b1 = *(const u64*)&GVs[s][tx*4+2];
        float4 a4 = *(const float4*)&GKs[s][ty*4];
        u64 ad[4] = {dup2(a4.x), dup2(a4.y), dup2(a4.z), dup2(a4.w)};
#pragma unroll
        for (int i = 0; i < 4; ++i) {
            acc2[i][0] = fma2(ad[i], b0, acc2[i][0]);
            acc2[i][1] = fma2(ad[i], b1, acc2[i][1]);
        }
    }
    size_t ab = (size_t)(b*C_ + c) * (M_*M_);
#pragma unroll
    for (int i = 0; i < 4; ++i) {
        float v0,v1,v2,v3;
        upk2(acc2[i][0], v0, v1);
        upk2(acc2[i][1], v2, v3);
        *(float4*)(g_A + ab + (size_t)(ty*4+i)*M_ + tx*4) = make_float4(v0,v1,v2,v3);
    }
}

// --------- kernel 4: inter-chunk scan, elementwise parallel ---------------
__global__ void chunk_scan_kernel(const float* __restrict__ dp,
                                  float* __restrict__ sfinal) {
    int gid = blockIdx.x * blockDim.x + threadIdx.x;   // 32768 threads
    int b = gid >> 12;
    int e = gid & 4095;
    float d  = decay_val(dp);
    float dT = powf(d, 64.0f);
    float S = 0.f;
#pragma unroll 8
    for (int c = 0; c < C_; ++c) {
        size_t idx = ((size_t)(b*C_ + c) << 12) + e;
        g_Spre[idx] = S;
        S = dT*S + g_A[idx];
    }
    sfinal[((size_t)b << 12) + e] = S;
}

// --------- kernel 5: per-chunk outputs (f32x2) -----------------------------
__global__ void chunk_out_kernel(const float* __restrict__ dp) {
    __shared__ float Qs [64][64];
    __shared__ float Ps [64][64];
    __shared__ float Buf[64][64];
    int b = blockIdx.y, c = blockIdx.x;
    int t = threadIdx.x, ty = t >> 4, tx = t & 15;
    float d = decay_val(dp);
    size_t rbase = (size_t)b*L_ + (size_t)c*T_;

    {   // Q natural, GK transposed
        int c4 = t & 15, sr = t >> 4;
#pragma unroll
        for (int p = 0; p < 4; ++p) {
            int s = sr + p*16;
            *(float4*)&Qs[s][c4*4] = *(const float4*)(g_Q + (rbase+s)*M_ + c4*4);
            float4 k4 = *(const float4*)(g_GK + (rbase+s)*M_ + c4*4);
            Buf[c4*4+0][s] = k4.x;  Buf[c4*4+1][s] = k4.y;
            Buf[c4*4+2][s] = k4.z;  Buf[c4*4+3][s] = k4.w;
        }
    }
    __syncthreads();

    // phase 1: P = Q @ GK^T
    u64 pacc[4][2];
#pragma unroll
    for (int i = 0; i < 4; ++i) { pacc[i][0] = 0ull; pacc[i][1] = 0ull; }
#pragma unroll 8
    for (int m = 0; m < 64; ++m) {
        u64 b0 = *(const u64*)&Buf[m][tx*4];
        u64 b1 = *(const u64*)&Buf[m][tx*4+2];
#pragma unroll
        for (int i = 0; i < 4; ++i) {
            u64 ad = dup2(Qs[ty*4+i][m]);
            pacc[i][0] = fma2(ad, b0, pacc[i][0]);
            pacc[i][1] = fma2(ad, b1, pacc[i][1]);
        }
    }
    // causal decay mask
#pragma unroll
    for (int i = 0; i < 4; ++i) {
        int s = ty*4 + i;
        float v[4];
        upk2(pacc[i][0], v[0], v[1]);
        upk2(pacc[i][1], v[2], v[3]);
#pragma unroll
        for (int j = 0; j < 4; ++j) {
            int sp = tx*4 + j;
            Ps[s][sp] = (sp <= s) ? v[j] * powf(d, (float)(s - sp)) : 0.f;
        }
    }
    __syncthreads();

    // Spre into Buf
    size_t sbase = (size_t)(b*C_ + c) * (M_*M_);
    {
        int c4 = t & 15, mr = t >> 4;
#pragma unroll
        for (int p = 0; p < 4; ++p) {
            int m = mr + p*16;
            *(float4*)&Buf[m][c4*4] = *(const float4*)(g_Spre + sbase + (size_t)m*M_ + c4*4);
        }
    }
    __syncthreads();

    // inter: acc = Q @ Spre, scaled by d^{s+1}
    u64 acc[4][2];
#pragma unroll
    for (int i = 0; i < 4; ++i) { acc[i][0] = 0ull; acc[i][1] = 0ull; }
#pragma unroll 8
    for (int m = 0; m < 64; ++m) {
        u64 b0 = *(const u64*)&Buf[m][tx*4];
        u64 b1 = *(const u64*)&Buf[m][tx*4+2];
#pragma unroll
        for (int i = 0; i < 4; ++i) {
            u64 ad = dup2(Qs[ty*4+i][m]);
            acc[i][0] = fma2(ad, b0, acc[i][0]);
            acc[i][1] = fma2(ad, b1, acc[i][1]);
        }
    }
#pragma unroll
    for (int i = 0; i < 4; ++i) {
        u64 sc = dup2(powf(d, (float)(ty*4 + i + 1)));
        acc[i][0] = mul2(acc[i][0], sc);
        acc[i][1] = mul2(acc[i][1], sc);
    }
    __syncthreads();

    // GV into Buf (natural)
    {
        int c4 = t & 15, sr = t >> 4;
#pragma unroll
        for (int p = 0; p < 4; ++p) {
            int s = sr + p*16;
            *(float4*)&Buf[s][c4*4] = *(const float4*)(g_GV + (rbase+s)*M_ + c4*4);
        }
    }
    __syncthreads();

    // intra: acc += P @ GV
#pragma unroll 8
    for (int sp = 0; sp < 64; ++sp) {
        u64 b0 = *(const u64*)&Buf[sp][tx*4];
        u64 b1 = *(const u64*)&Buf[sp][tx*4+2];
#pragma unroll
        for (int i = 0; i < 4; ++i) {
            u64 ad = dup2(Ps[ty*4+i][sp]);
            acc[i][0] = fma2(ad, b0, acc[i][0]);
            acc[i][1] = fma2(ad, b1, acc[i][1]);
        }
    }
#pragma unroll
    for (int i = 0; i < 4; ++i) {
        float v0,v1,v2,v3;
        upk2(acc[i][0], v0, v1);
        upk2(acc[i][1], v2, v3);
        *(float4*)(g_O + (rbase + ty*4 + i)*M_ + tx*4) = make_float4(v0,v1,v2,v3);
    }
}

// ---------------- kernel 6: y = O @ Wo + bo (f32x2, row-packed) -----------
__global__ void out_kernel(const float* __restrict__ Wo,
                           const float* __restrict__ bo,
                           float* __restrict__ y) {
    __shared__ float Ot [64][136];   // transposed O: [k][row], 128 rows
    __shared__ float Ws2[64][64];
    int r0 = blockIdx.x * 128;
    int n0 = blockIdx.y * 64;
    int t = threadIdx.x, ty = t >> 4, tx = t & 15;

    {   // O tile 128x64 -> transposed
        int c4 = t & 15, rr = t >> 4;
#pragma unroll
        for (int p = 0; p < 8; ++p) {
            int r = rr + p*16;
            float4 v = *(const float4*)(g_O + (size_t)(r0+r)*M_ + c4*4);
            Ot[c4*4+0][r] = v.x;  Ot[c4*4+1][r] = v.y;
            Ot[c4*4+2][r] = v.z;  Ot[c4*4+3][r] = v.w;
        }
    }
    {   // W tile 64x64
        int c4 = t & 15, kr = t >> 4;
#pragma unroll
        for (int p = 0; p < 4; ++p) {
            int k = kr + p*16;
            *(float4*)&Ws2[k][c4*4] = *(const float4*)(Wo + (size_t)k*D_ + n0 + c4*4);
        }
    }
    __syncthreads();

    u64 acc2[4][4];     // [row-pair][col]
#pragma unroll
    for (int i = 0; i < 4; ++i)
#pragma unroll
        for (int j = 0; j < 4; ++j) acc2[i][j] = 0ull;

#pragma unroll 8
    for (int k = 0; k < 64; ++k) {
        u64 a2[4];
#pragma unroll
        for (int i = 0; i < 4; ++i)
            a2[i] = *(const u64*)&Ot[k][ty*8 + i*2];
        float4 b = *(const float4*)&Ws2[k][tx*4];
        u64 bd[4] = {dup2(b.x), dup2(b.y), dup2(b.z), dup2(b.w)};
#pragma unroll
        for (int i = 0; i < 4; ++i)
#pragma unroll
            for (int j = 0; j < 4; ++j) acc2[i][j] = fma2(a2[i], bd[j], acc2[i][j]);
    }
    float4 bias = *(const float4*)(bo + n0 + tx*4);
#pragma unroll
    for (int i = 0; i < 4; ++i) {
        int rlo = r0 + ty*8 + i*2;
        float lo[4], hi[4];
#pragma unroll
        for (int j = 0; j < 4; ++j) upk2(acc2[i][j], lo[j], hi[j]);
        *(float4*)(y + (size_t)rlo*D_ + n0 + tx*4) =
            make_float4(lo[0]+bias.x, lo[1]+bias.y, lo[2]+bias.z, lo[3]+bias.w);
        *(float4*)(y + (size_t)(rlo+1)*D_ + n0 + tx*4) =
            make_float4(hi[0]+bias.x, hi[1]+bias.y, hi[2]+bias.z, hi[3]+bias.w);
    }
}

// ---------------- launcher ----------------
extern "C" void kernel_launch(void* const* d_in, const int* in_sizes, int n_in,
                              void* d_out, int out_size) {
    const float* x  = (const float*)d_in[0];
    const float* Wq = (const float*)d_in[1];
    const float* Wk = (const float*)d_in[2];
    const float* Wv = (const float*)d_in[3];
    const float* Wo = (const float*)d_in[4];
    const float* bo = (const float*)d_in[5];
    const float* Wg = (const float*)d_in[6];
    const float* bg = (const float*)d_in[7];
    const float* dp = (const float*)d_in[8];
    float* y      = (float*)d_out;
    float* sfinal = y + (size_t)BL_ * D_;

    gate_kernel      <<<BL_/8, 256>>>(x, Wg, bg);
    qkv_kernel       <<<dim3(BL_/128, 3), 256>>>(x, Wq, Wk, Wv);
    chunk_sum_kernel <<<dim3(C_, B_), 256>>>(dp);
    chunk_scan_kernel<<<(B_*M_*M_)/256, 256>>>(dp, sfinal);
    chunk_out_kernel <<<dim3(C_, B_), 256>>>(dp);
    out_kernel       <<<dim3(BL_/128, D_/64), 256>>>(Wo, bo, y);
}

// round 3
// speedup vs baseline: 1.1205x; 1.0713x over previous
#include <cuda_runtime.h>
#include <math.h>

#define B_  8
#define L_  4096
#define D_  1024
#define M_  64
#define BL_ (B_*L_)
#define C_  64
#define T_  64

typedef unsigned long long u64;

// ---------------- scratch ----------------
__device__ float g_Q   [BL_*M_];
__device__ float g_GK  [BL_*M_];
__device__ float g_GV  [BL_*M_];
__device__ float g_A   [B_*C_*M_*M_];
__device__ float g_Spre[B_*C_*M_*M_];
__device__ float g_O   [BL_*M_];

__device__ __forceinline__ float decay_val(const float* dp) {
    return 0.9f + 0.099f / (1.0f + expf(-dp[0]));
}

// ---- packed f32x2 helpers ----
__device__ __forceinline__ u64 dup2(float v) {
    u64 r; asm("mov.b64 %0,{%1,%1};" : "=l"(r) : "f"(v)); return r;
}
__device__ __forceinline__ void upk2(u64 v, float& lo, float& hi) {
    asm("mov.b64 {%0,%1},%2;" : "=f"(lo), "=f"(hi) : "l"(v));
}
__device__ __forceinline__ u64 fma2(u64 a, u64 b, u64 c) {
    u64 d; asm("fma.rn.f32x2 %0,%1,%2,%3;" : "=l"(d) : "l"(a), "l"(b), "l"(c)); return d;
}
__device__ __forceinline__ u64 mul2(u64 a, u64 b) {
    u64 d; asm("mul.rn.f32x2 %0,%1,%2;" : "=l"(d) : "l"(a), "l"(b)); return d;
}

// ========== kernel 1: fused gate + Q/K/V projections (x read ONCE) ==========
// 512 threads: ty=t>>4 (32 groups of 4 rows), tx=t&15 (4 cols). 128-row tiles.
__global__ void __launch_bounds__(512) qkvg_kernel(
        const float* __restrict__ x,
        const float* __restrict__ Wq, const float* __restrict__ Wk,
        const float* __restrict__ Wv, const float* __restrict__ Wg,
        const float* __restrict__ bg) {
    __shared__ float Xt[32][136];      // transposed x slab [k][row]
    __shared__ float Ws[3][32][64];    // W tiles for q,k,v
    __shared__ float Wgs[32];

    int t  = threadIdx.x;
    int ty = t >> 4, tx = t & 15;
    int r0 = blockIdx.x * 128;

    u64 acc[3][2][4];                  // [proj][row-pair][col]
#pragma unroll
    for (int p = 0; p < 3; ++p)
#pragma unroll
        for (int i = 0; i < 2; ++i)
#pragma unroll
            for (int j = 0; j < 4; ++j) acc[p][i][j] = 0ull;
    float gacc[4] = {0.f, 0.f, 0.f, 0.f};

    const float* Wp[3] = {Wq, Wk, Wv};

#pragma unroll 1
    for (int k0 = 0; k0 < D_; k0 += 32) {
        __syncthreads();
        {   // X tile 128x32 -> transposed (8 float4 per row, 64 rows/pass)
            int c8  = t & 7;
            int row = t >> 3;
#pragma unroll
            for (int p = 0; p < 2; ++p) {
                int r = row + p*64;
                float4 v = *(const float4*)(x + (size_t)(r0 + r)*D_ + k0 + c8*4);
                Xt[c8*4+0][r] = v.x;  Xt[c8*4+1][r] = v.y;
                Xt[c8*4+2][r] = v.z;  Xt[c8*4+3][r] = v.w;
            }
        }
        {   // W tiles: 3 x (32x64) ; 512 float4 per proj = 1 per thread
            int kk = t >> 4, c = t & 15;
#pragma unroll
            for (int p = 0; p < 3; ++p)
                *(float4*)&Ws[p][kk][c*4] = *(const float4*)(Wp[p] + (size_t)(k0+kk)*M_ + c*4);
            if (t < 32) Wgs[t] = Wg[k0 + t];
        }
        __syncthreads();

#pragma unroll
        for (int kk = 0; kk < 32; ++kk) {
            u64 a0 = *(const u64*)&Xt[kk][ty*4];
            u64 a1 = *(const u64*)&Xt[kk][ty*4+2];
#pragma unroll
            for (int p = 0; p < 3; ++p) {
                float4 b = *(const float4*)&Ws[p][kk][tx*4];
                u64 bd[4] = {dup2(b.x), dup2(b.y), dup2(b.z), dup2(b.w)};
#pragma unroll
                for (int j = 0; j < 4; ++j) {
                    acc[p][0][j] = fma2(a0, bd[j], acc[p][0][j]);
                    acc[p][1][j] = fma2(a1, bd[j], acc[p][1][j]);
                }
            }
        }
        // gate partials: lane tx covers kk = tx and tx+16
        {
            float w0 = Wgs[tx], w1 = Wgs[tx+16];
#pragma unroll
            for (int i = 0; i < 4; ++i)
                gacc[i] += Xt[tx][ty*4+i]*w0 + Xt[tx+16][ty*4+i]*w1;
        }
    }

    // reduce gate across the 16 tx lanes (same ty group)
#pragma unroll
    for (int off = 8; off; off >>= 1)
#pragma unroll
        for (int i = 0; i < 4; ++i)
            gacc[i] += __shfl_xor_sync(0xffffffffu, gacc[i], off);
    float bgv = bg[0];
    float g[4];
#pragma unroll
    for (int i = 0; i < 4; ++i)
        g[i] = 1.0f / (1.0f + expf(-(gacc[i] + bgv)));

    // epilogue: write Q (ungated), GK/GV (gated)
#pragma unroll
    for (int pr = 0; pr < 2; ++pr) {
        int rlo = r0 + ty*4 + pr*2;
        float glo = g[pr*2], ghi = g[pr*2+1];
        float qlo[4], qhi[4], klo[4], khi[4], vlo[4], vhi[4];
#pragma unroll
        for (int j = 0; j < 4; ++j) {
            upk2(acc[0][pr][j], qlo[j], qhi[j]);
            upk2(acc[1][pr][j], klo[j], khi[j]);
            upk2(acc[2][pr][j], vlo[j], vhi[j]);
        }
        *(float4*)(g_Q  + (size_t)rlo*M_ + tx*4) = make_float4(qlo[0],qlo[1],qlo[2],qlo[3]);
        *(float4*)(g_Q  + (size_t)(rlo+1)*M_ + tx*4) = make_float4(qhi[0],qhi[1],qhi[2],qhi[3]);
        *(float4*)(g_GK + (size_t)rlo*M_ + tx*4) =
            make_float4(klo[0]*glo, klo[1]*glo, klo[2]*glo, klo[3]*glo);
        *(float4*)(g_GK + (size_t)(rlo+1)*M_ + tx*4) =
            make_float4(khi[0]*ghi, khi[1]*ghi, khi[2]*ghi, khi[3]*ghi);
        *(float4*)(g_GV + (size_t)rlo*M_ + tx*4) =
            make_float4(vlo[0]*glo, vlo[1]*glo, vlo[2]*glo, vlo[3]*glo);
        *(float4*)(g_GV + (size_t)(rlo+1)*M_ + tx*4) =
            make_float4(vhi[0]*ghi, vhi[1]*ghi, vhi[2]*ghi, vhi[3]*ghi);
    }
}

// --------- kernel 3: chunk summaries (f32x2) -----------
__global__ void chunk_sum_kernel(const float* __restrict__ dp) {
    __shared__ float GKs[64][64];
    __shared__ float GVs[64][64];
    int b = blockIdx.y, c = blockIdx.x;
    int t = threadIdx.x;
    float d = decay_val(dp);
    size_t base = ((size_t)b*L_ + (size_t)c*T_) * M_;
    {
        int c4 = t & 15, sr = t >> 4;
#pragma unroll
        for (int p = 0; p < 4; ++p) {
            int s = sr + p*16;
            float w = powf(d, (float)(63 - s));
            float4 kv = *(const float4*)(g_GK + base + (size_t)s*M_ + c4*4);
            kv.x *= w; kv.y *= w; kv.z *= w; kv.w *= w;
            *(float4*)&GKs[s][c4*4] = kv;
            *(float4*)&GVs[s][c4*4] = *(const float4*)(g_GV + base + (size_t)s*M_ + c4*4);
        }
    }
    __syncthreads();
    int ty = t >> 4, tx = t & 15;
    u64 acc2[4][2];
#pragma unroll
    for (int i = 0; i < 4; ++i) { acc2[i][0] = 0ull; acc2[i][1] = 0ull; }
#pragma unroll 8
    for (int s = 0; s < 64; ++s) {
        u64 b0 = *(const u64*)&GVs[s][tx*4];
        u64 b1 = *(const u64*)&GVs[s][tx*4+2];
        float4 a4 = *(const float4*)&GKs[s][ty*4];
        u64 ad[4] = {dup2(a4.x), dup2(a4.y), dup2(a4.z), dup2(a4.w)};
#pragma unroll
        for (int i = 0; i < 4; ++i) {
            acc2[i][0] = fma2(ad[i], b0, acc2[i][0]);
            acc2[i][1] = fma2(ad[i], b1, acc2[i][1]);
        }
    }
    size_t ab = (size_t)(b*C_ + c) * (M_*M_);
#pragma unroll
    for (int i = 0; i < 4; ++i) {
        float v0,v1,v2,v3;
        upk2(acc2[i][0], v0, v1);
        upk2(acc2[i][1], v2, v3);
        *(float4*)(g_A + ab + (size_t)(ty*4+i)*M_ + tx*4) = make_float4(v0,v1,v2,v3);
    }
}

// --------- kernel 4: inter-chunk scan, MLP-8 prefetch ----------------------
__global__ void chunk_scan_kernel(const float* __restrict__ dp,
                                  float* __restrict__ sfinal) {
    int gid = blockIdx.x * blockDim.x + threadIdx.x;
    int b = gid >> 12;
    int e = gid & 4095;
    float d  = decay_val(dp);
    float dT = powf(d, 64.0f);
    float S = 0.f;
#pragma unroll 1
    for (int c0 = 0; c0 < C_; c0 += 8) {
        float a[8];
#pragma unroll
        for (int j = 0; j < 8; ++j)
            a[j] = g_A[((size_t)(b*C_ + c0 + j) << 12) + e];
#pragma unroll
        for (int j = 0; j < 8; ++j) {
            g_Spre[((size_t)(b*C_ + c0 + j) << 12) + e] = S;
            S = dT*S + a[j];
        }
    }
    sfinal[((size_t)b << 12) + e] = S;
}

// --------- kernel 5: per-chunk outputs (f32x2) ------------------------------
__global__ void chunk_out_kernel(const float* __restrict__ dp) {
    __shared__ float Qs [64][64];
    __shared__ float Ps [64][64];
    __shared__ float Buf[64][64];
    int b = blockIdx.y, c = blockIdx.x;
    int t = threadIdx.x, ty = t >> 4, tx = t & 15;
    float d = decay_val(dp);
    size_t rbase = (size_t)b*L_ + (size_t)c*T_;

    {   // Q natural, GK transposed
        int c4 = t & 15, sr = t >> 4;
#pragma unroll
        for (int p = 0; p < 4; ++p) {
            int s = sr + p*16;
            *(float4*)&Qs[s][c4*4] = *(const float4*)(g_Q + (rbase+s)*M_ + c4*4);
            float4 k4 = *(const float4*)(g_GK + (rbase+s)*M_ + c4*4);
            Buf[c4*4+0][s] = k4.x;  Buf[c4*4+1][s] = k4.y;
            Buf[c4*4+2][s] = k4.z;  Buf[c4*4+3][s] = k4.w;
        }
    }
    __syncthreads();

    // P = Q @ GK^T
    u64 pacc[4][2];
#pragma unroll
    for (int i = 0; i < 4; ++i) { pacc[i][0] = 0ull; pacc[i][1] = 0ull; }
#pragma unroll 8
    for (int m = 0; m < 64; ++m) {
        u64 b0 = *(const u64*)&Buf[m][tx*4];
        u64 b1 = *(const u64*)&Buf[m][tx*4+2];
#pragma unroll
        for (int i = 0; i < 4; ++i) {
            u64 ad = dup2(Qs[ty*4+i][m]);
            pacc[i][0] = fma2(ad, b0, pacc[i][0]);
            pacc[i][1] = fma2(ad, b1, pacc[i][1]);
        }
    }
#pragma unroll
    for (int i = 0; i < 4; ++i) {
        int s = ty*4 + i;
        float v[4];
        upk2(pacc[i][0], v[0], v[1]);
        upk2(pacc[i][1], v[2], v[3]);
#pragma unroll
        for (int j = 0; j < 4; ++j) {
            int sp = tx*4 + j;
            Ps[s][sp] = (sp <= s) ? v[j] * powf(d, (float)(s - sp)) : 0.f;
        }
    }
    __syncthreads();

    // Spre into Buf
    size_t sbase = (size_t)(b*C_ + c) * (M_*M_);
    {
        int c4 = t & 15, mr = t >> 4;
#pragma unroll
        for (int p = 0; p < 4; ++p) {
            int m = mr + p*16;
            *(float4*)&Buf[m][c4*4] = *(const float4*)(g_Spre + sbase + (size_t)m*M_ + c4*4);
        }
    }
    __syncthreads();

    // inter: Q @ Spre, scaled by d^{s+1}
    u64 acc[4][2];
#pragma unroll
    for (int i = 0; i < 4; ++i) { acc[i][0] = 0ull; acc[i][1] = 0ull; }
#pragma unroll 8
    for (int m = 0; m < 64; ++m) {
        u64 b0 = *(const u64*)&Buf[m][tx*4];
        u64 b1 = *(const u64*)&Buf[m][tx*4+2];
#pragma unroll
        for (int i = 0; i < 4; ++i) {
            u64 ad = dup2(Qs[ty*4+i][m]);
            acc[i][0] = fma2(ad, b0, acc[i][0]);
            acc[i][1] = fma2(ad, b1, acc[i][1]);
        }
    }
#pragma unroll
    for (int i = 0; i < 4; ++i) {
        u64 sc = dup2(powf(d, (float)(ty*4 + i + 1)));
        acc[i][0] = mul2(acc[i][0], sc);
        acc[i][1] = mul2(acc[i][1], sc);
    }
    __syncthreads();

    // GV natural
    {
        int c4 = t & 15, sr = t >> 4;
#pragma unroll
        for (int p = 0; p < 4; ++p) {
            int s = sr + p*16;
            *(float4*)&Buf[s][c4*4] = *(const float4*)(g_GV + (rbase+s)*M_ + c4*4);
        }
    }
    __syncthreads();

    // intra: += P @ GV
#pragma unroll 8
    for (int sp = 0; sp < 64; ++sp) {
        u64 b0 = *(const u64*)&Buf[sp][tx*4];
        u64 b1 = *(const u64*)&Buf[sp][tx*4+2];
#pragma unroll
        for (int i = 0; i < 4; ++i) {
            u64 ad = dup2(Ps[ty*4+i][sp]);
            acc[i][0] = fma2(ad, b0, acc[i][0]);
            acc[i][1] = fma2(ad, b1, acc[i][1]);
        }
    }
#pragma unroll
    for (int i = 0; i < 4; ++i) {
        float v0,v1,v2,v3;
        upk2(acc[i][0], v0, v1);
        upk2(acc[i][1], v2, v3);
        *(float4*)(g_O + (rbase + ty*4 + i)*M_ + tx*4) = make_float4(v0,v1,v2,v3);
    }
}

// ---------------- kernel 6: y = O @ Wo + bo -------------------------------
__global__ void out_kernel(const float* __restrict__ Wo,
                           const float* __restrict__ bo,
                           float* __restrict__ y) {
    __shared__ float Ot [64][136];
    __shared__ float Ws2[64][64];
    int r0 = blockIdx.x * 128;
    int n0 = blockIdx.y * 64;
    int t = threadIdx.x, ty = t >> 4, tx = t & 15;

    {
        int c4 = t & 15, rr = t >> 4;
#pragma unroll
        for (int p = 0; p < 8; ++p) {
            int r = rr + p*16;
            float4 v = *(const float4*)(g_O + (size_t)(r0+r)*M_ + c4*4);
            Ot[c4*4+0][r] = v.x;  Ot[c4*4+1][r] = v.y;
            Ot[c4*4+2][r] = v.z;  Ot[c4*4+3][r] = v.w;
        }
    }
    {
        int c4 = t & 15, kr = t >> 4;
#pragma unroll
        for (int p = 0; p < 4; ++p) {
            int k = kr + p*16;
            *(float4*)&Ws2[k][c4*4] = *(const float4*)(Wo + (size_t)k*D_ + n0 + c4*4);
        }
    }
    __syncthreads();

    u64 acc2[4][4];
#pragma unroll
    for (int i = 0; i < 4; ++i)
#pragma unroll
        for (int j = 0; j < 4; ++j) acc2[i][j] = 0ull;

#pragma unroll 8
    for (int k = 0; k < 64; ++k) {
        u64 a2[4];
#pragma unroll
        for (int i = 0; i < 4; ++i)
            a2[i] = *(const u64*)&Ot[k][ty*8 + i*2];
        float4 b = *(const float4*)&Ws2[k][tx*4];
        u64 bd[4] = {dup2(b.x), dup2(b.y), dup2(b.z), dup2(b.w)};
#pragma unroll
        for (int i = 0; i < 4; ++i)
#pragma unroll
            for (int j = 0; j < 4; ++j) acc2[i][j] = fma2(a2[i], bd[j], acc2[i][j]);
    }
    float4 bias = *(const float4*)(bo + n0 + tx*4);
#pragma unroll
    for (int i = 0; i < 4; ++i) {
        int rlo = r0 + ty*8 + i*2;
        float lo[4], hi[4];
#pragma unroll
        for (int j = 0; j < 4; ++j) upk2(acc2[i][j], lo[j], hi[j]);
        *(float4*)(y + (size_t)rlo*D_ + n0 + tx*4) =
            make_float4(lo[0]+bias.x, lo[1]+bias.y, lo[2]+bias.z, lo[3]+bias.w);
        *(float4*)(y + (size_t)(rlo+1)*D_ + n0 + tx*4) =
            make_float4(hi[0]+bias.x, hi[1]+bias.y, hi[2]+bias.z, hi[3]+bias.w);
    }
}

// ---------------- launcher ----------------
extern "C" void kernel_launch(void* const* d_in, const int* in_sizes, int n_in,
                              void* d_out, int out_size) {
    const float* x  = (const float*)d_in[0];
    const float* Wq = (const float*)d_in[1];
    const float* Wk = (const float*)d_in[2];
    const float* Wv = (const float*)d_in[3];
    const float* Wo = (const float*)d_in[4];
    const float* bo = (const float*)d_in[5];
    const float* Wg = (const float*)d_in[6];
    const float* bg = (const float*)d_in[7];
    const float* dp = (const float*)d_in[8];
    float* y      = (float*)d_out;
    float* sfinal = y + (size_t)BL_ * D_;

    qkvg_kernel      <<<BL_/128, 512>>>(x, Wq, Wk, Wv, Wg, bg);
    chunk_sum_kernel <<<dim3(C_, B_), 256>>>(dp);
    chunk_scan_kernel<<<(B_*M_*M_)/256, 256>>>(dp, sfinal);
    chunk_out_kernel <<<dim3(C_, B_), 256>>>(dp);
    out_kernel       <<<dim3(BL_/128, D_/64), 256>>>(Wo, bo, y);
}

// round 6
// speedup vs baseline: 1.3278x; 1.1850x over previous
#include <cuda_runtime.h>
#include <cuda_bf16.h>
#include <cstdint>
#include <math.h>

#define B_  8
#define L_  4096
#define D_  1024
#define M_  64
#define BL_ (B_*L_)
#define C_  64
#define T_  64

typedef unsigned long long u64;
typedef unsigned int u32;
typedef unsigned short u16;

// ---------------- scratch ----------------
__device__ float g_Q   [BL_*M_];
__device__ float g_GK  [BL_*M_];
__device__ float g_GV  [BL_*M_];
__device__ float g_A   [B_*C_*M_*M_];
__device__ float g_Spre[B_*C_*M_*M_];
__device__ float g_O   [BL_*M_];

__device__ __forceinline__ float decay_val(const float* dp) {
    return 0.9f + 0.099f / (1.0f + expf(-dp[0]));
}

// ---- packed f32x2 helpers (scalar kernels) ----
__device__ __forceinline__ u64 dup2(float v) {
    u64 r; asm("mov.b64 %0,{%1,%1};" : "=l"(r) : "f"(v)); return r;
}
__device__ __forceinline__ void upk2(u64 v, float& lo, float& hi) {
    asm("mov.b64 {%0,%1},%2;" : "=f"(lo), "=f"(hi) : "l"(v));
}
__device__ __forceinline__ u64 fma2(u64 a, u64 b, u64 c) {
    u64 d; asm("fma.rn.f32x2 %0,%1,%2,%3;" : "=l"(d) : "l"(a), "l"(b), "l"(c)); return d;
}
__device__ __forceinline__ u64 mul2(u64 a, u64 b) {
    u64 d; asm("mul.rn.f32x2 %0,%1,%2;" : "=l"(d) : "l"(a), "l"(b)); return d;
}

// ---- warp MMA helpers (baseline sm_80 ISA: works on compute_103 PTX) ----
__device__ __forceinline__ u32 smem_u32(const void* p) {
    u32 a;
    asm("{ .reg .u64 t; cvta.to.shared.u64 t, %1; cvt.u32.u64 %0, t; }" : "=r"(a) : "l"(p));
    return a;
}
__device__ __forceinline__ void ldsm4(u32& r0, u32& r1, u32& r2, u32& r3, u32 a) {
    asm volatile("ldmatrix.sync.aligned.m8n8.x4.shared.b16 {%0,%1,%2,%3},[%4];"
                 : "=r"(r0), "=r"(r1), "=r"(r2), "=r"(r3) : "r"(a));
}
__device__ __forceinline__ void mma_bf16(float* d, const u32* a, const u32* b) {
    asm volatile(
        "mma.sync.aligned.m16n8k16.row.col.f32.bf16.bf16.f32 "
        "{%0,%1,%2,%3},{%4,%5,%6,%7},{%8,%9},{%0,%1,%2,%3};"
        : "+f"(d[0]), "+f"(d[1]), "+f"(d[2]), "+f"(d[3])
        : "r"(a[0]), "r"(a[1]), "r"(a[2]), "r"(a[3]), "r"(b[0]), "r"(b[1]));
}
__device__ __forceinline__ void split2(float x0, float x1, u32& hi, u32& lo) {
    __nv_bfloat162 h = __floats2bfloat162_rn(x0, x1);
    float r0 = x0 - __bfloat162float(h.x);
    float r1 = x1 - __bfloat162float(h.y);
    __nv_bfloat162 l = __floats2bfloat162_rn(r0, r1);
    hi = *(u32*)&h;  lo = *(u32*)&l;
}
__device__ __forceinline__ void split1(float x, u16& hi, u16& lo) {
    __nv_bfloat16 h = __float2bfloat16(x);
    __nv_bfloat16 l = __float2bfloat16(x - __bfloat162float(h));
    hi = *(u16*)&h;  lo = *(u16*)&l;
}

// SMEM layout for qkv (bytes). Row stride 80 B (40 bf16) -> 16B-aligned rows.
#define XH_OFF 0
#define XL_OFF 10240
#define WH_OFF 20480
#define WL_OFF 35840
#define WGV_OFF 51200     /* 1024 floats */
#define GATE_OFF 55296    /* 128 floats */
#define QKV_SMEM 55808
#define RS 80             /* row stride bytes */

// ========== kernel 1: fused QKV+gate, warp-level bf16 MMA (3-term split) ====
// X[128 x 1024] @ [Wq|Wk|Wv][1024 x 192]; 512 threads = 16 warps (4x4 tiling).
__global__ void __launch_bounds__(512, 1) qkv_mma_kernel(
        const float* __restrict__ x,
        const float* __restrict__ Wq, const float* __restrict__ Wk,
        const float* __restrict__ Wv, const float* __restrict__ Wg,
        const float* __restrict__ bg) {
    extern __shared__ char smem[];
    u32 sb = smem_u32(smem);
    int t = threadIdx.x;
    int lane = t & 31, wid = t >> 5;
    int warp_m = wid >> 2, warp_n = wid & 3;
    int r0 = blockIdx.x * 128;

    if (t < 256) *(float4*)(smem + WGV_OFF + t*16) = *(const float4*)(Wg + t*4);
    const float* wgs = (const float*)(smem + WGV_OFF);
    __syncthreads();

    // staging indices
    int rowX = t >> 3;             // 0..63 (and +64 on rep 1)
    int c4   = t & 7;              // k float4 index in 32-wide tile
    int kW   = t >> 4;             // 0..31
    int n4   = t & 15;             // W col float4

    // fragment lane offsets
    int laneA_row = lane & 15;
    int laneA_kb  = (lane >> 4) * 16;                    // bytes
    int laneB_n   = (lane & 7) + ((lane >> 4) << 3);
    int laneB_kb  = ((lane >> 3) & 1) * 16;              // bytes

    float acc[2][6][4];
#pragma unroll
    for (int i = 0; i < 2; ++i)
#pragma unroll
        for (int j = 0; j < 6; ++j)
#pragma unroll
            for (int k = 0; k < 4; ++k) acc[i][j][k] = 0.f;
    float gacc[2] = {0.f, 0.f};

    const float* Wp[3] = {Wq, Wk, Wv};

#pragma unroll 1
    for (int it = 0; it < 32; ++it) {
        int k0 = it * 32;
        __syncthreads();
        // ---- stage X[128x32] -> split bf16 (hi/lo) ----
#pragma unroll
        for (int rep = 0; rep < 2; ++rep) {
            int row = rowX + rep*64;
            float4 v = *(const float4*)(x + (size_t)(r0 + row)*D_ + k0 + c4*4);
            gacc[rep] += v.x*wgs[k0+c4*4] + v.y*wgs[k0+c4*4+1]
                       + v.z*wgs[k0+c4*4+2] + v.w*wgs[k0+c4*4+3];
            u32 h0,l0,h1,l1;
            split2(v.x, v.y, h0, l0);
            split2(v.z, v.w, h1, l1);
            int off = row*RS + c4*8;
            *(u32*)(smem + XH_OFF + off)   = h0;
            *(u32*)(smem + XH_OFF + off+4) = h1;
            *(u32*)(smem + XL_OFF + off)   = l0;
            *(u32*)(smem + XL_OFF + off+4) = l1;
        }
        // ---- stage W[32 x 192] transposed -> Wt[n][k] split bf16 ----
#pragma unroll
        for (int p = 0; p < 3; ++p) {
            float4 w = *(const float4*)(Wp[p] + (size_t)(k0 + kW)*M_ + n4*4);
            float wv[4] = {w.x, w.y, w.z, w.w};
#pragma unroll
            for (int i = 0; i < 4; ++i) {
                u16 hi, lo;
                split1(wv[i], hi, lo);
                int off = (p*64 + n4*4 + i)*RS + kW*2;
                *(u16*)(smem + WH_OFF + off) = hi;
                *(u16*)(smem + WL_OFF + off) = lo;
            }
        }
        __syncthreads();

        // ---- compute: 2 k16-steps x 3 terms ----
#pragma unroll
        for (int ko = 0; ko < 2; ++ko) {
            int kb = ko*32;   // byte offset of k16 step (16 bf16 = 32B)
            u32 Ah[2][4], Al[2][4], Bb[6][2];
#pragma unroll
            for (int mt = 0; mt < 2; ++mt) {
                u32 aoff = (u32)((warp_m*32 + mt*16 + laneA_row)*RS + kb + laneA_kb);
                ldsm4(Ah[mt][0], Ah[mt][1], Ah[mt][2], Ah[mt][3], sb + XH_OFF + aoff);
                ldsm4(Al[mt][0], Al[mt][1], Al[mt][2], Al[mt][3], sb + XL_OFF + aoff);
            }
#pragma unroll
            for (int np = 0; np < 3; ++np) {
                u32 boff = (u32)((warp_n*48 + np*16 + laneB_n)*RS + kb + laneB_kb);
                ldsm4(Bb[2*np][0], Bb[2*np][1], Bb[2*np+1][0], Bb[2*np+1][1],
                      sb + WH_OFF + boff);
            }
#pragma unroll
            for (int mt = 0; mt < 2; ++mt)
#pragma unroll
                for (int nt = 0; nt < 6; ++nt) mma_bf16(acc[mt][nt], Ah[mt], Bb[nt]);
#pragma unroll
            for (int mt = 0; mt < 2; ++mt)
#pragma unroll
                for (int nt = 0; nt < 6; ++nt) mma_bf16(acc[mt][nt], Al[mt], Bb[nt]);
#pragma unroll
            for (int np = 0; np < 3; ++np) {
                u32 boff = (u32)((warp_n*48 + np*16 + laneB_n)*RS + kb + laneB_kb);
                ldsm4(Bb[2*np][0], Bb[2*np][1], Bb[2*np+1][0], Bb[2*np+1][1],
                      sb + WL_OFF + boff);
            }
#pragma unroll
            for (int mt = 0; mt < 2; ++mt)
#pragma unroll
                for (int nt = 0; nt < 6; ++nt) mma_bf16(acc[mt][nt], Ah[mt], Bb[nt]);
        }
    }

    // ---- gates: reduce over the 8 lanes sharing each row ----
#pragma unroll
    for (int off = 4; off; off >>= 1)
#pragma unroll
        for (int rep = 0; rep < 2; ++rep)
            gacc[rep] += __shfl_xor_sync(0xffffffffu, gacc[rep], off);
    if ((t & 7) == 0) {
        float bgv = bg[0];
        ((float*)(smem + GATE_OFF))[rowX]      = 1.0f/(1.0f + expf(-(gacc[0] + bgv)));
        ((float*)(smem + GATE_OFF))[rowX + 64] = 1.0f/(1.0f + expf(-(gacc[1] + bgv)));
    }
    __syncthreads();
    const float* gate = (const float*)(smem + GATE_OFF);

    // ---- epilogue: write Q / gated-K / gated-V ----
    int g8 = lane >> 2, t2 = lane & 3;
#pragma unroll
    for (int mt = 0; mt < 2; ++mt) {
        int rl0 = warp_m*32 + mt*16 + g8;       // local row (and +8)
#pragma unroll
        for (int nt = 0; nt < 6; ++nt) {
            int col = warp_n*48 + nt*8 + t2*2;
            int proj = col >> 6, lc = col & 63;
            float* Out = (proj == 0) ? g_Q : (proj == 1) ? g_GK : g_GV;
            float ga = (proj == 0) ? 1.0f : gate[rl0];
            float gb = (proj == 0) ? 1.0f : gate[rl0 + 8];
            float2 o0 = make_float2(acc[mt][nt][0]*ga, acc[mt][nt][1]*ga);
            float2 o1 = make_float2(acc[mt][nt][2]*gb, acc[mt][nt][3]*gb);
            *(float2*)(Out + (size_t)(r0 + rl0)*M_ + lc)     = o0;
            *(float2*)(Out + (size_t)(r0 + rl0 + 8)*M_ + lc) = o1;
        }
    }
}

// --------- kernel 3: chunk summaries (f32x2) -----------
__global__ void chunk_sum_kernel(const float* __restrict__ dp) {
    __shared__ float GKs[64][64];
    __shared__ float GVs[64][64];
    int b = blockIdx.y, c = blockIdx.x;
    int t = threadIdx.x;
    float d = decay_val(dp);
    size_t base = ((size_t)b*L_ + (size_t)c*T_) * M_;
    {
        int c4 = t & 15, sr = t >> 4;
#pragma unroll
        for (int p = 0; p < 4; ++p) {
            int s = sr + p*16;
            float w = powf(d, (float)(63 - s));
            float4 kv = *(const float4*)(g_GK + base + (size_t)s*M_ + c4*4);
            kv.x *= w; kv.y *= w; kv.z *= w; kv.w *= w;
            *(float4*)&GKs[s][c4*4] = kv;
            *(float4*)&GVs[s][c4*4] = *(const float4*)(g_GV + base + (size_t)s*M_ + c4*4);
        }
    }
    __syncthreads();
    int ty = t >> 4, tx = t & 15;
    u64 acc2[4][2];
#pragma unroll
    for (int i = 0; i < 4; ++i) { acc2[i][0] = 0ull; acc2[i][1] = 0ull; }
#pragma unroll 8
    for (int s = 0; s < 64; ++s) {
        u64 b0 = *(const u64*)&GVs[s][tx*4];
        u64 b1 = *(const u64*)&GVs[s][tx*4+2];
        float4 a4 = *(const float4*)&GKs[s][ty*4];
        u64 ad[4] = {dup2(a4.x), dup2(a4.y), dup2(a4.z), dup2(a4.w)};
#pragma unroll
        for (int i = 0; i < 4; ++i) {
            acc2[i][0] = fma2(ad[i], b0, acc2[i][0]);
            acc2[i][1] = fma2(ad[i], b1, acc2[i][1]);
        }
    }
    size_t ab = (size_t)(b*C_ + c) * (M_*M_);
#pragma unroll
    for (int i = 0; i < 4; ++i) {
        float v0,v1,v2,v3;
        upk2(acc2[i][0], v0, v1);
        upk2(acc2[i][1], v2, v3);
        *(float4*)(g_A + ab + (size_t)(ty*4+i)*M_ + tx*4) = make_float4(v0,v1,v2,v3);
    }
}

// --------- kernel 4: inter-chunk scan (MLP-8) ----------
__global__ void chunk_scan_kernel(const float* __restrict__ dp,
                                  float* __restrict__ sfinal) {
    int gid = blockIdx.x * blockDim.x + threadIdx.x;
    int b = gid >> 12;
    int e = gid & 4095;
    float d  = decay_val(dp);
    float dT = powf(d, 64.0f);
    float S = 0.f;
#pragma unroll 1
    for (int c0 = 0; c0 < C_; c0 += 8) {
        float a[8];
#pragma unroll
        for (int j = 0; j < 8; ++j)
            a[j] = g_A[((size_t)(b*C_ + c0 + j) << 12) + e];
#pragma unroll
        for (int j = 0; j < 8; ++j) {
            g_Spre[((size_t)(b*C_ + c0 + j) << 12) + e] = S;
            S = dT*S + a[j];
        }
    }
    sfinal[((size_t)b << 12) + e] = S;
}

// --------- kernel 5: per-chunk outputs (f32x2) ----------
__global__ void chunk_out_kernel(const float* __restrict__ dp) {
    __shared__ float Qs [64][64];
    __shared__ float Ps [64][64];
    __shared__ float Buf[64][64];
    int b = blockIdx.y, c = blockIdx.x;
    int t = threadIdx.x, ty = t >> 4, tx = t & 15;
    float d = decay_val(dp);
    size_t rbase = (size_t)b*L_ + (size_t)c*T_;

    {
        int c4 = t & 15, sr = t >> 4;
#pragma unroll
        for (int p = 0; p < 4; ++p) {
            int s = sr + p*16;
            *(float4*)&Qs[s][c4*4] = *(const float4*)(g_Q + (rbase+s)*M_ + c4*4);
            float4 k4 = *(const float4*)(g_GK + (rbase+s)*M_ + c4*4);
            Buf[c4*4+0][s] = k4.x;  Buf[c4*4+1][s] = k4.y;
            Buf[c4*4+2][s] = k4.z;  Buf[c4*4+3][s] = k4.w;
        }
    }
    __syncthreads();

    u64 pacc[4][2];
#pragma unroll
    for (int i = 0; i < 4; ++i) { pacc[i][0] = 0ull; pacc[i][1] = 0ull; }
#pragma unroll 8
    for (int m = 0; m < 64; ++m) {
        u64 b0 = *(const u64*)&Buf[m][tx*4];
        u64 b1 = *(const u64*)&Buf[m][tx*4+2];
#pragma unroll
        for (int i = 0; i < 4; ++i) {
            u64 ad = dup2(Qs[ty*4+i][m]);
            pacc[i][0] = fma2(ad, b0, pacc[i][0]);
            pacc[i][1] = fma2(ad, b1, pacc[i][1]);
        }
    }
#pragma unroll
    for (int i = 0; i < 4; ++i) {
        int s = ty*4 + i;
        float v[4];
        upk2(pacc[i][0], v[0], v[1]);
        upk2(pacc[i][1], v[2], v[3]);
#pragma unroll
        for (int j = 0; j < 4; ++j) {
            int sp = tx*4 + j;
            Ps[s][sp] = (sp <= s) ? v[j] * powf(d, (float)(s - sp)) : 0.f;
        }
    }
    __syncthreads();

    size_t sbase = (size_t)(b*C_ + c) * (M_*M_);
    {
        int c4 = t & 15, mr = t >> 4;
#pragma unroll
        for (int p = 0; p < 4; ++p) {
            int m = mr + p*16;
            *(float4*)&Buf[m][c4*4] = *(const float4*)(g_Spre + sbase + (size_t)m*M_ + c4*4);
        }
    }
    __syncthreads();

    u64 acc[4][2];
#pragma unroll
    for (int i = 0; i < 4; ++i) { acc[i][0] = 0ull; acc[i][1] = 0ull; }
#pragma unroll 8
    for (int m = 0; m < 64; ++m) {
        u64 b0 = *(const u64*)&Buf[m][tx*4];
        u64 b1 = *(const u64*)&Buf[m][tx*4+2];
#pragma unroll
        for (int i = 0; i < 4; ++i) {
            u64 ad = dup2(Qs[ty*4+i][m]);
            acc[i][0] = fma2(ad, b0, acc[i][0]);
            acc[i][1] = fma2(ad, b1, acc[i][1]);
        }
    }
#pragma unroll
    for (int i = 0; i < 4; ++i) {
        u64 sc = dup2(powf(d, (float)(ty*4 + i + 1)));
        acc[i][0] = mul2(acc[i][0], sc);
        acc[i][1] = mul2(acc[i][1], sc);
    }
    __syncthreads();

    {
        int c4 = t & 15, sr = t >> 4;
#pragma unroll
        for (int p = 0; p < 4; ++p) {
            int s = sr + p*16;
            *(float4*)&Buf[s][c4*4] = *(const float4*)(g_GV + (rbase+s)*M_ + c4*4);
        }
    }
    __syncthreads();

#pragma unroll 8
    for (int sp = 0; sp < 64; ++sp) {
        u64 b0 = *(const u64*)&Buf[sp][tx*4];
        u64 b1 = *(const u64*)&Buf[sp][tx*4+2];
#pragma unroll
        for (int i = 0; i < 4; ++i) {
            u64 ad = dup2(Ps[ty*4+i][sp]);
            acc[i][0] = fma2(ad, b0, acc[i][0]);
            acc[i][1] = fma2(ad, b1, acc[i][1]);
        }
    }
#pragma unroll
    for (int i = 0; i < 4; ++i) {
        float v0,v1,v2,v3;
        upk2(acc[i][0], v0, v1);
        upk2(acc[i][1], v2, v3);
        *(float4*)(g_O + (rbase + ty*4 + i)*M_ + tx*4) = make_float4(v0,v1,v2,v3);
    }
}

// ---------------- kernel 6: y = O @ Wo + bo -------------
__global__ void out_kernel(const float* __restrict__ Wo,
                           const float* __restrict__ bo,
                           float* __restrict__ y) {
    __shared__ float Ot [64][136];
    __shared__ float Ws2[64][64];
    int r0 = blockIdx.x * 128;
    int n0 = blockIdx.y * 64;
    int t = threadIdx.x, ty = t >> 4, tx = t & 15;

    {
        int c4 = t & 15, rr = t >> 4;
#pragma unroll
        for (int p = 0; p < 8; ++p) {
            int r = rr + p*16;
            float4 v = *(const float4*)(g_O + (size_t)(r0+r)*M_ + c4*4);
            Ot[c4*4+0][r] = v.x;  Ot[c4*4+1][r] = v.y;
            Ot[c4*4+2][r] = v.z;  Ot[c4*4+3][r] = v.w;
        }
    }
    {
        int c4 = t & 15, kr = t >> 4;
#pragma unroll
        for (int p = 0; p < 4; ++p) {
            int k = kr + p*16;
            *(float4*)&Ws2[k][c4*4] = *(const float4*)(Wo + (size_t)k*D_ + n0 + c4*4);
        }
    }
    __syncthreads();

    u64 acc2[4][4];
#pragma unroll
    for (int i = 0; i < 4; ++i)
#pragma unroll
        for (int j = 0; j < 4; ++j) acc2[i][j] = 0ull;

#pragma unroll 8
    for (int k = 0; k < 64; ++k) {
        u64 a2[4];
#pragma unroll
        for (int i = 0; i < 4; ++i)
            a2[i] = *(const u64*)&Ot[k][ty*8 + i*2];
        float4 b = *(const float4*)&Ws2[k][tx*4];
        u64 bd[4] = {dup2(b.x), dup2(b.y), dup2(b.z), dup2(b.w)};
#pragma unroll
        for (int i = 0; i < 4; ++i)
#pragma unroll
            for (int j = 0; j < 4; ++j) acc2[i][j] = fma2(a2[i], bd[j], acc2[i][j]);
    }
    float4 bias = *(const float4*)(bo + n0 + tx*4);
#pragma unroll
    for (int i = 0; i < 4; ++i) {
        int rlo = r0 + ty*8 + i*2;
        float lo[4], hi[4];
#pragma unroll
        for (int j = 0; j < 4; ++j) upk2(acc2[i][j], lo[j], hi[j]);
        *(float4*)(y + (size_t)rlo*D_ + n0 + tx*4) =
            make_float4(lo[0]+bias.x, lo[1]+bias.y, lo[2]+bias.z, lo[3]+bias.w);
        *(float4*)(y + (size_t)(rlo+1)*D_ + n0 + tx*4) =
            make_float4(hi[0]+bias.x, hi[1]+bias.y, hi[2]+bias.z, hi[3]+bias.w);
    }
}

// ---------------- launcher ----------------
extern "C" void kernel_launch(void* const* d_in, const int* in_sizes, int n_in,
                              void* d_out, int out_size) {
    const float* x  = (const float*)d_in[0];
    const float* Wq = (const float*)d_in[1];
    const float* Wk = (const float*)d_in[2];
    const float* Wv = (const float*)d_in[3];
    const float* Wo = (const float*)d_in[4];
    const float* bo = (const float*)d_in[5];
    const float* Wg = (const float*)d_in[6];
    const float* bg = (const float*)d_in[7];
    const float* dp = (const float*)d_in[8];
    float* y      = (float*)d_out;
    float* sfinal = y + (size_t)BL_ * D_;

    cudaFuncSetAttribute(qkv_mma_kernel,
                         cudaFuncAttributeMaxDynamicSharedMemorySize, QKV_SMEM);

    qkv_mma_kernel   <<<BL_/128, 512, QKV_SMEM>>>(x, Wq, Wk, Wv, Wg, bg);
    chunk_sum_kernel <<<dim3(C_, B_), 256>>>(dp);
    chunk_scan_kernel<<<(B_*M_*M_)/256, 256>>>(dp, sfinal);
    chunk_out_kernel <<<dim3(C_, B_), 256>>>(dp);
    out_kernel       <<<dim3(BL_/128, D_/64), 256>>>(Wo, bo, y);
}

// round 7
// speedup vs baseline: 1.5648x; 1.1785x over previous
#include <cuda_runtime.h>
#include <cuda_bf16.h>
#include <cstdint>
#include <math.h>

#define B_  8
#define L_  4096
#define D_  1024
#define M_  64
#define BL_ (B_*L_)
#define C_  64
#define T_  64

typedef unsigned long long u64;
typedef unsigned int u32;
typedef unsigned short u16;

// ---------------- scratch ----------------
__device__ float g_Q   [BL_*M_];
__device__ float g_GK  [BL_*M_];
__device__ float g_GV  [BL_*M_];
__device__ float g_A   [B_*C_*M_*M_];
__device__ float g_Spre[B_*C_*M_*M_];
__device__ float g_O   [BL_*M_];

__device__ __forceinline__ float decay_val(const float* dp) {
    return 0.9f + 0.099f / (1.0f + expf(-dp[0]));
}

// ---- packed f32x2 helpers (scalar kernels) ----
__device__ __forceinline__ u64 dup2(float v) {
    u64 r; asm("mov.b64 %0,{%1,%1};" : "=l"(r) : "f"(v)); return r;
}
__device__ __forceinline__ void upk2(u64 v, float& lo, float& hi) {
    asm("mov.b64 {%0,%1},%2;" : "=f"(lo), "=f"(hi) : "l"(v));
}
__device__ __forceinline__ u64 fma2(u64 a, u64 b, u64 c) {
    u64 d; asm("fma.rn.f32x2 %0,%1,%2,%3;" : "=l"(d) : "l"(a), "l"(b), "l"(c)); return d;
}
__device__ __forceinline__ u64 mul2(u64 a, u64 b) {
    u64 d; asm("mul.rn.f32x2 %0,%1,%2;" : "=l"(d) : "l"(a), "l"(b)); return d;
}

// ---- warp MMA helpers ----
__device__ __forceinline__ u32 smem_u32(const void* p) {
    u32 a;
    asm("{ .reg .u64 t; cvta.to.shared.u64 t, %1; cvt.u32.u64 %0, t; }" : "=r"(a) : "l"(p));
    return a;
}
__device__ __forceinline__ void ldsm4(u32& r0, u32& r1, u32& r2, u32& r3, u32 a) {
    asm volatile("ldmatrix.sync.aligned.m8n8.x4.shared.b16 {%0,%1,%2,%3},[%4];"
                 : "=r"(r0), "=r"(r1), "=r"(r2), "=r"(r3) : "r"(a));
}
__device__ __forceinline__ void mma_bf16(float* d, const u32* a, const u32* b) {
    asm volatile(
        "mma.sync.aligned.m16n8k16.row.col.f32.bf16.bf16.f32 "
        "{%0,%1,%2,%3},{%4,%5,%6,%7},{%8,%9},{%0,%1,%2,%3};"
        : "+f"(d[0]), "+f"(d[1]), "+f"(d[2]), "+f"(d[3])
        : "r"(a[0]), "r"(a[1]), "r"(a[2]), "r"(a[3]), "r"(b[0]), "r"(b[1]));
}
__device__ __forceinline__ void split2(float x0, float x1, u32& hi, u32& lo) {
    __nv_bfloat162 h = __floats2bfloat162_rn(x0, x1);
    float r0 = x0 - __bfloat162float(h.x);
    float r1 = x1 - __bfloat162float(h.y);
    __nv_bfloat162 l = __floats2bfloat162_rn(r0, r1);
    hi = *(u32*)&h;  lo = *(u32*)&l;
}
__device__ __forceinline__ void split1(float x, u16& hi, u16& lo) {
    __nv_bfloat16 h = __float2bfloat16(x);
    __nv_bfloat16 l = __float2bfloat16(x - __bfloat162float(h));
    hi = *(u16*)&h;  lo = *(u16*)&l;
}

// SMEM layout for qkv (bytes). Row stride 80 B.
#define XH_OFF 0
#define XL_OFF 10240
#define WH_OFF 20480
#define WL_OFF 35840
#define WGV_OFF 51200
#define GATE_OFF 55296
#define QKV_SMEM 55808
#define RS 80

// ========== kernel 1: fused QKV+gate, warp MMA (3-term split) ====
__global__ void __launch_bounds__(512, 1) qkv_mma_kernel(
        const float* __restrict__ x,
        const float* __restrict__ Wq, const float* __restrict__ Wk,
        const float* __restrict__ Wv, const float* __restrict__ Wg,
        const float* __restrict__ bg) {
    extern __shared__ char smem[];
    u32 sb = smem_u32(smem);
    int t = threadIdx.x;
    int lane = t & 31, wid = t >> 5;
    int warp_m = wid >> 2, warp_n = wid & 3;
    int r0 = blockIdx.x * 128;

    if (t < 256) *(float4*)(smem + WGV_OFF + t*16) = *(const float4*)(Wg + t*4);
    const float* wgs = (const float*)(smem + WGV_OFF);
    __syncthreads();

    int rowX = t >> 3;
    int c4   = t & 7;
    int kW   = t >> 4;
    int n4   = t & 15;

    int laneA_row = lane & 15;
    int laneA_kb  = (lane >> 4) * 16;
    int laneB_n   = (lane & 7) + ((lane >> 4) << 3);
    int laneB_kb  = ((lane >> 3) & 1) * 16;

    float acc[2][6][4];
#pragma unroll
    for (int i = 0; i < 2; ++i)
#pragma unroll
        for (int j = 0; j < 6; ++j)
#pragma unroll
            for (int k = 0; k < 4; ++k) acc[i][j][k] = 0.f;
    float gacc[2] = {0.f, 0.f};

    const float* Wp[3] = {Wq, Wk, Wv};

#pragma unroll 1
    for (int it = 0; it < 32; ++it) {
        int k0 = it * 32;
        __syncthreads();
#pragma unroll
        for (int rep = 0; rep < 2; ++rep) {
            int row = rowX + rep*64;
            float4 v = *(const float4*)(x + (size_t)(r0 + row)*D_ + k0 + c4*4);
            gacc[rep] += v.x*wgs[k0+c4*4] + v.y*wgs[k0+c4*4+1]
                       + v.z*wgs[k0+c4*4+2] + v.w*wgs[k0+c4*4+3];
            u32 h0,l0,h1,l1;
            split2(v.x, v.y, h0, l0);
            split2(v.z, v.w, h1, l1);
            int off = row*RS + c4*8;
            *(u32*)(smem + XH_OFF + off)   = h0;
            *(u32*)(smem + XH_OFF + off+4) = h1;
            *(u32*)(smem + XL_OFF + off)   = l0;
            *(u32*)(smem + XL_OFF + off+4) = l1;
        }
#pragma unroll
        for (int p = 0; p < 3; ++p) {
            float4 w = *(const float4*)(Wp[p] + (size_t)(k0 + kW)*M_ + n4*4);
            float wv[4] = {w.x, w.y, w.z, w.w};
#pragma unroll
            for (int i = 0; i < 4; ++i) {
                u16 hi, lo;
                split1(wv[i], hi, lo);
                int off = (p*64 + n4*4 + i)*RS + kW*2;
                *(u16*)(smem + WH_OFF + off) = hi;
                *(u16*)(smem + WL_OFF + off) = lo;
            }
        }
        __syncthreads();

#pragma unroll
        for (int ko = 0; ko < 2; ++ko) {
            int kb = ko*32;
            u32 Ah[2][4], Al[2][4], Bb[6][2];
#pragma unroll
            for (int mt = 0; mt < 2; ++mt) {
                u32 aoff = (u32)((warp_m*32 + mt*16 + laneA_row)*RS + kb + laneA_kb);
                ldsm4(Ah[mt][0], Ah[mt][1], Ah[mt][2], Ah[mt][3], sb + XH_OFF + aoff);
                ldsm4(Al[mt][0], Al[mt][1], Al[mt][2], Al[mt][3], sb + XL_OFF + aoff);
            }
#pragma unroll
            for (int np = 0; np < 3; ++np) {
                u32 boff = (u32)((warp_n*48 + np*16 + laneB_n)*RS + kb + laneB_kb);
                ldsm4(Bb[2*np][0], Bb[2*np][1], Bb[2*np+1][0], Bb[2*np+1][1],
                      sb + WH_OFF + boff);
            }
#pragma unroll
            for (int mt = 0; mt < 2; ++mt)
#pragma unroll
                for (int nt = 0; nt < 6; ++nt) mma_bf16(acc[mt][nt], Ah[mt], Bb[nt]);
#pragma unroll
            for (int mt = 0; mt < 2; ++mt)
#pragma unroll
                for (int nt = 0; nt < 6; ++nt) mma_bf16(acc[mt][nt], Al[mt], Bb[nt]);
#pragma unroll
            for (int np = 0; np < 3; ++np) {
                u32 boff = (u32)((warp_n*48 + np*16 + laneB_n)*RS + kb + laneB_kb);
                ldsm4(Bb[2*np][0], Bb[2*np][1], Bb[2*np+1][0], Bb[2*np+1][1],
                      sb + WL_OFF + boff);
            }
#pragma unroll
            for (int mt = 0; mt < 2; ++mt)
#pragma unroll
                for (int nt = 0; nt < 6; ++nt) mma_bf16(acc[mt][nt], Ah[mt], Bb[nt]);
        }
    }

#pragma unroll
    for (int off = 4; off; off >>= 1)
#pragma unroll
        for (int rep = 0; rep < 2; ++rep)
            gacc[rep] += __shfl_xor_sync(0xffffffffu, gacc[rep], off);
    if ((t & 7) == 0) {
        float bgv = bg[0];
        ((float*)(smem + GATE_OFF))[rowX]      = 1.0f/(1.0f + expf(-(gacc[0] + bgv)));
        ((float*)(smem + GATE_OFF))[rowX + 64] = 1.0f/(1.0f + expf(-(gacc[1] + bgv)));
    }
    __syncthreads();
    const float* gate = (const float*)(smem + GATE_OFF);

    int g8 = lane >> 2, t2 = lane & 3;
#pragma unroll
    for (int mt = 0; mt < 2; ++mt) {
        int rl0 = warp_m*32 + mt*16 + g8;
#pragma unroll
        for (int nt = 0; nt < 6; ++nt) {
            int col = warp_n*48 + nt*8 + t2*2;
            int proj = col >> 6, lc = col & 63;
            float* Out = (proj == 0) ? g_Q : (proj == 1) ? g_GK : g_GV;
            float ga = (proj == 0) ? 1.0f : gate[rl0];
            float gb = (proj == 0) ? 1.0f : gate[rl0 + 8];
            float2 o0 = make_float2(acc[mt][nt][0]*ga, acc[mt][nt][1]*ga);
            float2 o1 = make_float2(acc[mt][nt][2]*gb, acc[mt][nt][3]*gb);
            *(float2*)(Out + (size_t)(r0 + rl0)*M_ + lc)     = o0;
            *(float2*)(Out + (size_t)(r0 + rl0 + 8)*M_ + lc) = o1;
        }
    }
}

// --------- kernel 3: chunk summaries (f32x2) -----------
__global__ void chunk_sum_kernel(const float* __restrict__ dp) {
    __shared__ float GKs[64][64];
    __shared__ float GVs[64][64];
    int b = blockIdx.y, c = blockIdx.x;
    int t = threadIdx.x;
    float d = decay_val(dp);
    size_t base = ((size_t)b*L_ + (size_t)c*T_) * M_;
    {
        int c4 = t & 15, sr = t >> 4;
#pragma unroll
        for (int p = 0; p < 4; ++p) {
            int s = sr + p*16;
            float w = powf(d, (float)(63 - s));
            float4 kv = *(const float4*)(g_GK + base + (size_t)s*M_ + c4*4);
            kv.x *= w; kv.y *= w; kv.z *= w; kv.w *= w;
            *(float4*)&GKs[s][c4*4] = kv;
            *(float4*)&GVs[s][c4*4] = *(const float4*)(g_GV + base + (size_t)s*M_ + c4*4);
        }
    }
    __syncthreads();
    int ty = t >> 4, tx = t & 15;
    u64 acc2[4][2];
#pragma unroll
    for (int i = 0; i < 4; ++i) { acc2[i][0] = 0ull; acc2[i][1] = 0ull; }
#pragma unroll 8
    for (int s = 0; s < 64; ++s) {
        u64 b0 = *(const u64*)&GVs[s][tx*4];
        u64 b1 = *(const u64*)&GVs[s][tx*4+2];
        float4 a4 = *(const float4*)&GKs[s][ty*4];
        u64 ad[4] = {dup2(a4.x), dup2(a4.y), dup2(a4.z), dup2(a4.w)};
#pragma unroll
        for (int i = 0; i < 4; ++i) {
            acc2[i][0] = fma2(ad[i], b0, acc2[i][0]);
            acc2[i][1] = fma2(ad[i], b1, acc2[i][1]);
        }
    }
    size_t ab = (size_t)(b*C_ + c) * (M_*M_);
#pragma unroll
    for (int i = 0; i < 4; ++i) {
        float v0,v1,v2,v3;
        upk2(acc2[i][0], v0, v1);
        upk2(acc2[i][1], v2, v3);
        *(float4*)(g_A + ab + (size_t)(ty*4+i)*M_ + tx*4) = make_float4(v0,v1,v2,v3);
    }
}

// --------- kernel 4: inter-chunk scan (MLP-8) ----------
__global__ void chunk_scan_kernel(const float* __restrict__ dp,
                                  float* __restrict__ sfinal) {
    int gid = blockIdx.x * blockDim.x + threadIdx.x;
    int b = gid >> 12;
    int e = gid & 4095;
    float d  = decay_val(dp);
    float dT = powf(d, 64.0f);
    float S = 0.f;
#pragma unroll 1
    for (int c0 = 0; c0 < C_; c0 += 8) {
        float a[8];
#pragma unroll
        for (int j = 0; j < 8; ++j)
            a[j] = g_A[((size_t)(b*C_ + c0 + j) << 12) + e];
#pragma unroll
        for (int j = 0; j < 8; ++j) {
            g_Spre[((size_t)(b*C_ + c0 + j) << 12) + e] = S;
            S = dT*S + a[j];
        }
    }
    sfinal[((size_t)b << 12) + e] = S;
}

// --------- kernel 5: per-chunk outputs (f32x2) ----------
__global__ void chunk_out_kernel(const float* __restrict__ dp) {
    __shared__ float Qs [64][64];
    __shared__ float Ps [64][64];
    __shared__ float Buf[64][64];
    int b = blockIdx.y, c = blockIdx.x;
    int t = threadIdx.x, ty = t >> 4, tx = t & 15;
    float d = decay_val(dp);
    size_t rbase = (size_t)b*L_ + (size_t)c*T_;

    {
        int c4 = t & 15, sr = t >> 4;
#pragma unroll
        for (int p = 0; p < 4; ++p) {
            int s = sr + p*16;
            *(float4*)&Qs[s][c4*4] = *(const float4*)(g_Q + (rbase+s)*M_ + c4*4);
            float4 k4 = *(const float4*)(g_GK + (rbase+s)*M_ + c4*4);
            Buf[c4*4+0][s] = k4.x;  Buf[c4*4+1][s] = k4.y;
            Buf[c4*4+2][s] = k4.z;  Buf[c4*4+3][s] = k4.w;
        }
    }
    __syncthreads();

    u64 pacc[4][2];
#pragma unroll
    for (int i = 0; i < 4; ++i) { pacc[i][0] = 0ull; pacc[i][1] = 0ull; }
#pragma unroll 8
    for (int m = 0; m < 64; ++m) {
        u64 b0 = *(const u64*)&Buf[m][tx*4];
        u64 b1 = *(const u64*)&Buf[m][tx*4+2];
#pragma unroll
        for (int i = 0; i < 4; ++i) {
            u64 ad = dup2(Qs[ty*4+i][m]);
            pacc[i][0] = fma2(ad, b0, pacc[i][0]);
            pacc[i][1] = fma2(ad, b1, pacc[i][1]);
        }
    }
#pragma unroll
    for (int i = 0; i < 4; ++i) {
        int s = ty*4 + i;
        float v[4];
        upk2(pacc[i][0], v[0], v[1]);
        upk2(pacc[i][1], v[2], v[3]);
#pragma unroll
        for (int j = 0; j < 4; ++j) {
            int sp = tx*4 + j;
            Ps[s][sp] = (sp <= s) ? v[j] * powf(d, (float)(s - sp)) : 0.f;
        }
    }
    __syncthreads();

    size_t sbase = (size_t)(b*C_ + c) * (M_*M_);
    {
        int c4 = t & 15, mr = t >> 4;
#pragma unroll
        for (int p = 0; p < 4; ++p) {
            int m = mr + p*16;
            *(float4*)&Buf[m][c4*4] = *(const float4*)(g_Spre + sbase + (size_t)m*M_ + c4*4);
        }
    }
    __syncthreads();

    u64 acc[4][2];
#pragma unroll
    for (int i = 0; i < 4; ++i) { acc[i][0] = 0ull; acc[i][1] = 0ull; }
#pragma unroll 8
    for (int m = 0; m < 64; ++m) {
        u64 b0 = *(const u64*)&Buf[m][tx*4];
        u64 b1 = *(const u64*)&Buf[m][tx*4+2];
#pragma unroll
        for (int i = 0; i < 4; ++i) {
            u64 ad = dup2(Qs[ty*4+i][m]);
            acc[i][0] = fma2(ad, b0, acc[i][0]);
            acc[i][1] = fma2(ad, b1, acc[i][1]);
        }
    }
#pragma unroll
    for (int i = 0; i < 4; ++i) {
        u64 sc = dup2(powf(d, (float)(ty*4 + i + 1)));
        acc[i][0] = mul2(acc[i][0], sc);
        acc[i][1] = mul2(acc[i][1], sc);
    }
    __syncthreads();

    {
        int c4 = t & 15, sr = t >> 4;
#pragma unroll
        for (int p = 0; p < 4; ++p) {
            int s = sr + p*16;
            *(float4*)&Buf[s][c4*4] = *(const float4*)(g_GV + (rbase+s)*M_ + c4*4);
        }
    }
    __syncthreads();

#pragma unroll 8
    for (int sp = 0; sp < 64; ++sp) {
        u64 b0 = *(const u64*)&Buf[sp][tx*4];
        u64 b1 = *(const u64*)&Buf[sp][tx*4+2];
#pragma unroll
        for (int i = 0; i < 4; ++i) {
            u64 ad = dup2(Ps[ty*4+i][sp]);
            acc[i][0] = fma2(ad, b0, acc[i][0]);
            acc[i][1] = fma2(ad, b1, acc[i][1]);
        }
    }
#pragma unroll
    for (int i = 0; i < 4; ++i) {
        float v0,v1,v2,v3;
        upk2(acc[i][0], v0, v1);
        upk2(acc[i][1], v2, v3);
        *(float4*)(g_O + (rbase + ty*4 + i)*M_ + tx*4) = make_float4(v0,v1,v2,v3);
    }
}

// ---------- kernel 6: y = O @ Wo + bo via warp MMA (3-term split) ----------
// grid (256, 8): 128-row x 128-col tiles; 256 threads = 8 warps (4m x 2n).
#define OH_OFF 0
#define OL_OFF 18432
#define WHO_OFF 36864
#define WLO_OFF 55296
#define OUT_SMEM 73728
#define ORS 144      /* row stride bytes: 64 bf16 = 128 B + 16 pad */

__global__ void __launch_bounds__(256, 2) out_mma_kernel(
        const float* __restrict__ Wo, const float* __restrict__ bo,
        float* __restrict__ y) {
    extern __shared__ char smem[];
    u32 sb = smem_u32(smem);
    int t = threadIdx.x;
    int lane = t & 31, wid = t >> 5;
    int warp_m = wid >> 1, warp_n = wid & 1;
    int r0 = blockIdx.x * 128;
    int n0 = blockIdx.y * 128;

    // ---- stage O[128 x 64] hi/lo ----
#pragma unroll
    for (int rep = 0; rep < 8; ++rep) {
        int idx = t + rep*256;
        int row = idx >> 4, c4 = idx & 15;
        float4 v = *(const float4*)(g_O + (size_t)(r0 + row)*M_ + c4*4);
        u32 h0,l0,h1,l1;
        split2(v.x, v.y, h0, l0);
        split2(v.z, v.w, h1, l1);
        int off = row*ORS + c4*8;
        *(u32*)(smem + OH_OFF + off)   = h0;
        *(u32*)(smem + OH_OFF + off+4) = h1;
        *(u32*)(smem + OL_OFF + off)   = l0;
        *(u32*)(smem + OL_OFF + off+4) = l1;
    }
    // ---- stage Wo[64 x 128] -> [n][k] hi/lo, k-pairs packed as u32 ----
#pragma unroll
    for (int p = 0; p < 4; ++p) {
        int idx = t + p*256;
        int kp = idx & 31;      // k-pair 0..31 (k = 2kp, 2kp+1)
        int nf = idx >> 5;      // n float4 0..31
        float4 a = *(const float4*)(Wo + (size_t)(2*kp)*D_   + n0 + nf*4);
        float4 b = *(const float4*)(Wo + (size_t)(2*kp+1)*D_ + n0 + nf*4);
        float av[4] = {a.x, a.y, a.z, a.w};
        float bv[4] = {b.x, b.y, b.z, b.w};
#pragma unroll
        for (int i = 0; i < 4; ++i) {
            u32 hi, lo;
            split2(av[i], bv[i], hi, lo);
            int off = (nf*4 + i)*ORS + kp*4;
            *(u32*)(smem + WHO_OFF + off) = hi;
            *(u32*)(smem + WLO_OFF + off) = lo;
        }
    }
    __syncthreads();

    int laneA_row = lane & 15;
    int laneA_kb  = (lane >> 4) * 16;
    int laneB_n   = (lane & 7) + ((lane >> 4) << 3);
    int laneB_kb  = ((lane >> 3) & 1) * 16;

    float acc[2][8][4];
#pragma unroll
    for (int i = 0; i < 2; ++i)
#pragma unroll
        for (int j = 0; j < 8; ++j)
#pragma unroll
            for (int k = 0; k < 4; ++k) acc[i][j][k] = 0.f;

#pragma unroll
    for (int ko = 0; ko < 4; ++ko) {
        int kb = ko*32;
        u32 Ah[2][4], Al[2][4], Bb[8][2];
#pragma unroll
        for (int mt = 0; mt < 2; ++mt) {
            u32 aoff = (u32)((warp_m*32 + mt*16 + laneA_row)*ORS + kb + laneA_kb);
            ldsm4(Ah[mt][0], Ah[mt][1], Ah[mt][2], Ah[mt][3], sb + OH_OFF + aoff);
            ldsm4(Al[mt][0], Al[mt][1], Al[mt][2], Al[mt][3], sb + OL_OFF + aoff);
        }
#pragma unroll
        for (int np = 0; np < 4; ++np) {
            u32 boff = (u32)((warp_n*64 + np*16 + laneB_n)*ORS + kb + laneB_kb);
            ldsm4(Bb[2*np][0], Bb[2*np][1], Bb[2*np+1][0], Bb[2*np+1][1],
                  sb + WHO_OFF + boff);
        }
#pragma unroll
        for (int mt = 0; mt < 2; ++mt)
#pragma unroll
            for (int nt = 0; nt < 8; ++nt) mma_bf16(acc[mt][nt], Ah[mt], Bb[nt]);
#pragma unroll
        for (int mt = 0; mt < 2; ++mt)
#pragma unroll
            for (int nt = 0; nt < 8; ++nt) mma_bf16(acc[mt][nt], Al[mt], Bb[nt]);
#pragma unroll
        for (int np = 0; np < 4; ++np) {
            u32 boff = (u32)((warp_n*64 + np*16 + laneB_n)*ORS + kb + laneB_kb);
            ldsm4(Bb[2*np][0], Bb[2*np][1], Bb[2*np+1][0], Bb[2*np+1][1],
                  sb + WLO_OFF + boff);
        }
#pragma unroll
        for (int mt = 0; mt < 2; ++mt)
#pragma unroll
            for (int nt = 0; nt < 8; ++nt) mma_bf16(acc[mt][nt], Ah[mt], Bb[nt]);
    }

    // ---- epilogue: + bias, write y ----
    int g8 = lane >> 2, t2 = lane & 3;
#pragma unroll
    for (int mt = 0; mt < 2; ++mt) {
        int row = r0 + warp_m*32 + mt*16 + g8;
#pragma unroll
        for (int nt = 0; nt < 8; ++nt) {
            int col = n0 + warp_n*64 + nt*8 + t2*2;
            float2 bias = *(const float2*)(bo + col);
            *(float2*)(y + (size_t)row*D_ + col) =
                make_float2(acc[mt][nt][0] + bias.x, acc[mt][nt][1] + bias.y);
            *(float2*)(y + (size_t)(row + 8)*D_ + col) =
                make_float2(acc[mt][nt][2] + bias.x, acc[mt][nt][3] + bias.y);
        }
    }
}

// ---------------- launcher ----------------
extern "C" void kernel_launch(void* const* d_in, const int* in_sizes, int n_in,
                              void* d_out, int out_size) {
    const float* x  = (const float*)d_in[0];
    const float* Wq = (const float*)d_in[1];
    const float* Wk = (const float*)d_in[2];
    const float* Wv = (const float*)d_in[3];
    const float* Wo = (const float*)d_in[4];
    const float* bo = (const float*)d_in[5];
    const float* Wg = (const float*)d_in[6];
    const float* bg = (const float*)d_in[7];
    const float* dp = (const float*)d_in[8];
    float* y      = (float*)d_out;
    float* sfinal = y + (size_t)BL_ * D_;

    cudaFuncSetAttribute(qkv_mma_kernel,
                         cudaFuncAttributeMaxDynamicSharedMemorySize, QKV_SMEM);
    cudaFuncSetAttribute(out_mma_kernel,
                         cudaFuncAttributeMaxDynamicSharedMemorySize, OUT_SMEM);

    qkv_mma_kernel   <<<BL_/128, 512, QKV_SMEM>>>(x, Wq, Wk, Wv, Wg, bg);
    chunk_sum_kernel <<<dim3(C_, B_), 256>>>(dp);
    chunk_scan_kernel<<<(B_*M_*M_)/256, 256>>>(dp, sfinal);
    chunk_out_kernel <<<dim3(C_, B_), 256>>>(dp);
    out_mma_kernel   <<<dim3(BL_/128, D_/128), 256, OUT_SMEM>>>(Wo, bo, y);
}

// round 8
// speedup vs baseline: 2.3667x; 1.5125x over previous
#include <cuda_runtime.h>
#include <cuda_bf16.h>
#include <cstdint>
#include <math.h>

#define B_  8
#define L_  4096
#define D_  1024
#define M_  64
#define BL_ (B_*L_)
#define C_  64
#define T_  64

typedef unsigned long long u64;
typedef unsigned int u32;
typedef unsigned short u16;

// ---------------- scratch ----------------
__device__ float g_Q   [BL_*M_];
__device__ float g_GK  [BL_*M_];
__device__ float g_GV  [BL_*M_];
__device__ float g_A   [B_*C_*M_*M_];
__device__ float g_Spre[B_*C_*M_*M_];
__device__ float g_O   [BL_*M_];
__device__ u16   g_Wh  [32*192*32];   // split W hi, [it][n][k]
__device__ u16   g_Wl  [32*192*32];   // split W lo

__device__ __forceinline__ float decay_val(const float* dp) {
    return 0.9f + 0.099f / (1.0f + expf(-dp[0]));
}

// ---- packed f32x2 helpers ----
__device__ __forceinline__ u64 dup2(float v) {
    u64 r; asm("mov.b64 %0,{%1,%1};" : "=l"(r) : "f"(v)); return r;
}
__device__ __forceinline__ void upk2(u64 v, float& lo, float& hi) {
    asm("mov.b64 {%0,%1},%2;" : "=f"(lo), "=f"(hi) : "l"(v));
}
__device__ __forceinline__ u64 fma2(u64 a, u64 b, u64 c) {
    u64 d; asm("fma.rn.f32x2 %0,%1,%2,%3;" : "=l"(d) : "l"(a), "l"(b), "l"(c)); return d;
}
__device__ __forceinline__ u64 mul2(u64 a, u64 b) {
    u64 d; asm("mul.rn.f32x2 %0,%1,%2;" : "=l"(d) : "l"(a), "l"(b)); return d;
}

// ---- warp MMA helpers ----
__device__ __forceinline__ u32 smem_u32(const void* p) {
    u32 a;
    asm("{ .reg .u64 t; cvta.to.shared.u64 t, %1; cvt.u32.u64 %0, t; }" : "=r"(a) : "l"(p));
    return a;
}
__device__ __forceinline__ void ldsm4(u32& r0, u32& r1, u32& r2, u32& r3, u32 a) {
    asm volatile("ldmatrix.sync.aligned.m8n8.x4.shared.b16 {%0,%1,%2,%3},[%4];"
                 : "=r"(r0), "=r"(r1), "=r"(r2), "=r"(r3) : "r"(a));
}
__device__ __forceinline__ void mma_bf16(float* d, const u32* a, const u32* b) {
    asm volatile(
        "mma.sync.aligned.m16n8k16.row.col.f32.bf16.bf16.f32 "
        "{%0,%1,%2,%3},{%4,%5,%6,%7},{%8,%9},{%0,%1,%2,%3};"
        : "+f"(d[0]), "+f"(d[1]), "+f"(d[2]), "+f"(d[3])
        : "r"(a[0]), "r"(a[1]), "r"(a[2]), "r"(a[3]), "r"(b[0]), "r"(b[1]));
}
__device__ __forceinline__ void split2(float x0, float x1, u32& hi, u32& lo) {
    __nv_bfloat162 h = __floats2bfloat162_rn(x0, x1);
    float r0 = x0 - __bfloat162float(h.x);
    float r1 = x1 - __bfloat162float(h.y);
    __nv_bfloat162 l = __floats2bfloat162_rn(r0, r1);
    hi = *(u32*)&h;  lo = *(u32*)&l;
}
__device__ __forceinline__ void split1(float x, u16& hi, u16& lo) {
    __nv_bfloat16 h = __float2bfloat16(x);
    __nv_bfloat16 l = __float2bfloat16(x - __bfloat162float(h));
    hi = *(u16*)&h;  lo = *(u16*)&l;
}
__device__ __forceinline__ void cpasync16(u32 dst, const void* src) {
    asm volatile("cp.async.cg.shared.global [%0], [%1], 16;" :: "r"(dst), "l"(src));
}

// ---------- kernel 0: W prep — split bf16, staged layout [it][n][k] --------
__global__ void wprep_kernel(const float* __restrict__ Wq,
                             const float* __restrict__ Wk,
                             const float* __restrict__ Wv) {
    int idx = blockIdx.x*256 + threadIdx.x;     // 0..196607
    int kk = idx & 31;
    int r  = idx >> 5;
    int n  = r % 192;
    int it = r / 192;
    int col = n & 63;
    const float* Wp = (n < 64) ? Wq : (n < 128) ? Wk : Wv;
    float w = Wp[(size_t)(it*32 + kk)*M_ + col];
    u16 hi, lo;
    split1(w, hi, lo);
    g_Wh[idx] = hi;
    g_Wl[idx] = lo;
}

// SMEM layout for qkv (bytes), double-buffered. Row stride 80 B.
#define RS 80
#define XHo(b)  ((b)*10240)
#define XLo(b)  (20480 + (b)*10240)
#define WHo(b)  (40960 + (b)*15360)
#define WLo(b)  (71680 + (b)*15360)
#define WGV_OFF 102400
#define GATE_OFF 106496
#define QKV_SMEM 107008

// ========== kernel 1: fused QKV+gate, warp MMA, double-buffered ====
__global__ void __launch_bounds__(512, 1) qkv_mma_kernel(
        const float* __restrict__ x,
        const float* __restrict__ Wg, const float* __restrict__ bg) {
    extern __shared__ char smem[];
    u32 sb = smem_u32(smem);
    int t = threadIdx.x;
    int lane = t & 31, wid = t >> 5;
    int warp_m = wid >> 2, warp_n = wid & 3;
    int r0 = blockIdx.x * 128;

    if (t < 256) *(float4*)(smem + WGV_OFF + t*16) = *(const float4*)(Wg + t*4);
    const float* wgs = (const float*)(smem + WGV_OFF);

    int rowX = t >> 3;
    int c4   = t & 7;

    // W cp.async per-thread targets (3 chunks each)
    int wn[3], wc[3], wterm[3];
#pragma unroll
    for (int rr = 0; rr < 3; ++rr) {
        int idx = t + rr*512;
        wterm[rr] = (idx >= 768);
        int rem = idx - wterm[rr]*768;
        wn[rr] = rem >> 2;
        wc[rr] = rem & 3;
    }

    int laneA_row = lane & 15;
    int laneA_kb  = (lane >> 4) * 16;
    int laneB_n   = (lane & 7) + ((lane >> 4) << 3);
    int laneB_kb  = ((lane >> 3) & 1) * 16;

    float acc[2][6][4];
#pragma unroll
    for (int i = 0; i < 2; ++i)
#pragma unroll
        for (int j = 0; j < 6; ++j)
#pragma unroll
            for (int k = 0; k < 4; ++k) acc[i][j][k] = 0.f;
    float gacc[2] = {0.f, 0.f};

    __syncthreads();   // wgs visible

    // ---- prologue: X regs for it=0, cp.async W[0] into buf 0 ----
    float4 xr0 = *(const float4*)(x + (size_t)(r0 + rowX)*D_ + c4*4);
    float4 xr1 = *(const float4*)(x + (size_t)(r0 + rowX + 64)*D_ + c4*4);
#pragma unroll
    for (int rr = 0; rr < 3; ++rr) {
        u32 dst = sb + (wterm[rr] ? WLo(0) : WHo(0)) + wn[rr]*RS + wc[rr]*16;
        const u16* src = (wterm[rr] ? g_Wl : g_Wh) + ((0*192 + wn[rr])*32 + wc[rr]*8);
        cpasync16(dst, src);
    }
    asm volatile("cp.async.commit_group;" ::: "memory");

#pragma unroll 1
    for (int it = 0; it < 32; ++it) {
        int buf = it & 1;
        int k0 = it * 32;
        // ---- (a) gate partial + split X -> smem[buf] ----
        {
            const float* wg4 = wgs + k0 + c4*4;
            gacc[0] += xr0.x*wg4[0] + xr0.y*wg4[1] + xr0.z*wg4[2] + xr0.w*wg4[3];
            gacc[1] += xr1.x*wg4[0] + xr1.y*wg4[1] + xr1.z*wg4[2] + xr1.w*wg4[3];
            u32 h0,l0,h1,l1;
            split2(xr0.x, xr0.y, h0, l0);
            split2(xr0.z, xr0.w, h1, l1);
            int off = rowX*RS + c4*8;
            *(u32*)(smem + XHo(buf) + off)   = h0;
            *(u32*)(smem + XHo(buf) + off+4) = h1;
            *(u32*)(smem + XLo(buf) + off)   = l0;
            *(u32*)(smem + XLo(buf) + off+4) = l1;
            split2(xr1.x, xr1.y, h0, l0);
            split2(xr1.z, xr1.w, h1, l1);
            off = (rowX + 64)*RS + c4*8;
            *(u32*)(smem + XHo(buf) + off)   = h0;
            *(u32*)(smem + XHo(buf) + off+4) = h1;
            *(u32*)(smem + XLo(buf) + off)   = l0;
            *(u32*)(smem + XLo(buf) + off+4) = l1;
        }
        // ---- (a') wait W[buf] copies, then sync ----
        asm volatile("cp.async.wait_group 0;" ::: "memory");
        __syncthreads();
        // ---- (c) prefetch next X regs + issue W[buf^1] copies ----
        if (it < 31) {
            int k1 = k0 + 32;
            xr0 = *(const float4*)(x + (size_t)(r0 + rowX)*D_ + k1 + c4*4);
            xr1 = *(const float4*)(x + (size_t)(r0 + rowX + 64)*D_ + k1 + c4*4);
#pragma unroll
            for (int rr = 0; rr < 3; ++rr) {
                u32 dst = sb + (wterm[rr] ? WLo(buf^1) : WHo(buf^1)) + wn[rr]*RS + wc[rr]*16;
                const u16* src = (wterm[rr] ? g_Wl : g_Wh)
                               + (((it+1)*192 + wn[rr])*32 + wc[rr]*8);
                cpasync16(dst, src);
            }
            asm volatile("cp.async.commit_group;" ::: "memory");
        }
        // ---- (d) compute from buf ----
#pragma unroll
        for (int ko = 0; ko < 2; ++ko) {
            int kb = ko*32;
            u32 Ah[2][4], Al[2][4], Bb[6][2];
#pragma unroll
            for (int mt = 0; mt < 2; ++mt) {
                u32 aoff = (u32)((warp_m*32 + mt*16 + laneA_row)*RS + kb + laneA_kb);
                ldsm4(Ah[mt][0], Ah[mt][1], Ah[mt][2], Ah[mt][3], sb + XHo(buf) + aoff);
                ldsm4(Al[mt][0], Al[mt][1], Al[mt][2], Al[mt][3], sb + XLo(buf) + aoff);
            }
#pragma unroll
            for (int np = 0; np < 3; ++np) {
                u32 boff = (u32)((warp_n*48 + np*16 + laneB_n)*RS + kb + laneB_kb);
                ldsm4(Bb[2*np][0], Bb[2*np][1], Bb[2*np+1][0], Bb[2*np+1][1],
                      sb + WHo(buf) + boff);
            }
#pragma unroll
            for (int mt = 0; mt < 2; ++mt)
#pragma unroll
                for (int nt = 0; nt < 6; ++nt) mma_bf16(acc[mt][nt], Ah[mt], Bb[nt]);
#pragma unroll
            for (int mt = 0; mt < 2; ++mt)
#pragma unroll
                for (int nt = 0; nt < 6; ++nt) mma_bf16(acc[mt][nt], Al[mt], Bb[nt]);
#pragma unroll
            for (int np = 0; np < 3; ++np) {
                u32 boff = (u32)((warp_n*48 + np*16 + laneB_n)*RS + kb + laneB_kb);
                ldsm4(Bb[2*np][0], Bb[2*np][1], Bb[2*np+1][0], Bb[2*np+1][1],
                      sb + WLo(buf) + boff);
            }
#pragma unroll
            for (int mt = 0; mt < 2; ++mt)
#pragma unroll
                for (int nt = 0; nt < 6; ++nt) mma_bf16(acc[mt][nt], Ah[mt], Bb[nt]);
        }
    }

    // ---- gates: reduce over 8 lanes per row ----
#pragma unroll
    for (int off = 4; off; off >>= 1)
#pragma unroll
        for (int rep = 0; rep < 2; ++rep)
            gacc[rep] += __shfl_xor_sync(0xffffffffu, gacc[rep], off);
    if ((t & 7) == 0) {
        float bgv = bg[0];
        ((float*)(smem + GATE_OFF))[rowX]      = 1.0f/(1.0f + expf(-(gacc[0] + bgv)));
        ((float*)(smem + GATE_OFF))[rowX + 64] = 1.0f/(1.0f + expf(-(gacc[1] + bgv)));
    }
    __syncthreads();
    const float* gate = (const float*)(smem + GATE_OFF);

    int g8 = lane >> 2, t2 = lane & 3;
#pragma unroll
    for (int mt = 0; mt < 2; ++mt) {
        int rl0 = warp_m*32 + mt*16 + g8;
#pragma unroll
        for (int nt = 0; nt < 6; ++nt) {
            int col = warp_n*48 + nt*8 + t2*2;
            int proj = col >> 6, lc = col & 63;
            float* Out = (proj == 0) ? g_Q : (proj == 1) ? g_GK : g_GV;
            float ga = (proj == 0) ? 1.0f : gate[rl0];
            float gb = (proj == 0) ? 1.0f : gate[rl0 + 8];
            float2 o0 = make_float2(acc[mt][nt][0]*ga, acc[mt][nt][1]*ga);
            float2 o1 = make_float2(acc[mt][nt][2]*gb, acc[mt][nt][3]*gb);
            *(float2*)(Out + (size_t)(r0 + rl0)*M_ + lc)     = o0;
            *(float2*)(Out + (size_t)(r0 + rl0 + 8)*M_ + lc) = o1;
        }
    }
}

// --------- kernel 3: chunk summaries (f32x2) -----------
__global__ void chunk_sum_kernel(const float* __restrict__ dp) {
    __shared__ float GKs[64][64];
    __shared__ float GVs[64][64];
    int b = blockIdx.y, c = blockIdx.x;
    int t = threadIdx.x;
    float d = decay_val(dp);
    size_t base = ((size_t)b*L_ + (size_t)c*T_) * M_;
    {
        int c4 = t & 15, sr = t >> 4;
#pragma unroll
        for (int p = 0; p < 4; ++p) {
            int s = sr + p*16;
            float w = powf(d, (float)(63 - s));
            float4 kv = *(const float4*)(g_GK + base + (size_t)s*M_ + c4*4);
            kv.x *= w; kv.y *= w; kv.z *= w; kv.w *= w;
            *(float4*)&GKs[s][c4*4] = kv;
            *(float4*)&GVs[s][c4*4] = *(const float4*)(g_GV + base + (size_t)s*M_ + c4*4);
        }
    }
    __syncthreads();
    int ty = t >> 4, tx = t & 15;
    u64 acc2[4][2];
#pragma unroll
    for (int i = 0; i < 4; ++i) { acc2[i][0] = 0ull; acc2[i][1] = 0ull; }
#pragma unroll 8
    for (int s = 0; s < 64; ++s) {
        u64 b0 = *(const u64*)&GVs[s][tx*4];
        u64 b1 = *(const u64*)&GVs[s][tx*4+2];
        float4 a4 = *(const float4*)&GKs[s][ty*4];
        u64 ad[4] = {dup2(a4.x), dup2(a4.y), dup2(a4.z), dup2(a4.w)};
#pragma unroll
        for (int i = 0; i < 4; ++i) {
            acc2[i][0] = fma2(ad[i], b0, acc2[i][0]);
            acc2[i][1] = fma2(ad[i], b1, acc2[i][1]);
        }
    }
    size_t ab = (size_t)(b*C_ + c) * (M_*M_);
#pragma unroll
    for (int i = 0; i < 4; ++i) {
        float v0,v1,v2,v3;
        upk2(acc2[i][0], v0, v1);
        upk2(acc2[i][1], v2, v3);
        *(float4*)(g_A + ab + (size_t)(ty*4+i)*M_ + tx*4) = make_float4(v0,v1,v2,v3);
    }
}

// --------- kernel 4: inter-chunk scan (MLP-8) ----------
__global__ void chunk_scan_kernel(const float* __restrict__ dp,
                                  float* __restrict__ sfinal) {
    int gid = blockIdx.x * blockDim.x + threadIdx.x;
    int b = gid >> 12;
    int e = gid & 4095;
    float d  = decay_val(dp);
    float dT = powf(d, 64.0f);
    float S = 0.f;
#pragma unroll 1
    for (int c0 = 0; c0 < C_; c0 += 8) {
        float a[8];
#pragma unroll
        for (int j = 0; j < 8; ++j)
            a[j] = g_A[((size_t)(b*C_ + c0 + j) << 12) + e];
#pragma unroll
        for (int j = 0; j < 8; ++j) {
            g_Spre[((size_t)(b*C_ + c0 + j) << 12) + e] = S;
            S = dT*S + a[j];
        }
    }
    sfinal[((size_t)b << 12) + e] = S;
}

// --------- kernel 5: per-chunk outputs (f32x2) ----------
__global__ void chunk_out_kernel(const float* __restrict__ dp) {
    __shared__ float Qs [64][64];
    __shared__ float Ps [64][64];
    __shared__ float Buf[64][64];
    int b = blockIdx.y, c = blockIdx.x;
    int t = threadIdx.x, ty = t >> 4, tx = t & 15;
    float d = decay_val(dp);
    size_t rbase = (size_t)b*L_ + (size_t)c*T_;

    {
        int c4 = t & 15, sr = t >> 4;
#pragma unroll
        for (int p = 0; p < 4; ++p) {
            int s = sr + p*16;
            *(float4*)&Qs[s][c4*4] = *(const float4*)(g_Q + (rbase+s)*M_ + c4*4);
            float4 k4 = *(const float4*)(g_GK + (rbase+s)*M_ + c4*4);
            Buf[c4*4+0][s] = k4.x;  Buf[c4*4+1][s] = k4.y;
            Buf[c4*4+2][s] = k4.z;  Buf[c4*4+3][s] = k4.w;
        }
    }
    __syncthreads();

    u64 pacc[4][2];
#pragma unroll
    for (int i = 0; i < 4; ++i) { pacc[i][0] = 0ull; pacc[i][1] = 0ull; }
#pragma unroll 8
    for (int m = 0; m < 64; ++m) {
        u64 b0 = *(const u64*)&Buf[m][tx*4];
        u64 b1 = *(const u64*)&Buf[m][tx*4+2];
#pragma unroll
        for (int i = 0; i < 4; ++i) {
            u64 ad = dup2(Qs[ty*4+i][m]);
            pacc[i][0] = fma2(ad, b0, pacc[i][0]);
            pacc[i][1] = fma2(ad, b1, pacc[i][1]);
        }
    }
#pragma unroll
    for (int i = 0; i < 4; ++i) {
        int s = ty*4 + i;
        float v[4];
        upk2(pacc[i][0], v[0], v[1]);
        upk2(pacc[i][1], v[2], v[3]);
#pragma unroll
        for (int j = 0; j < 4; ++j) {
            int sp = tx*4 + j;
            Ps[s][sp] = (sp <= s) ? v[j] * powf(d, (float)(s - sp)) : 0.f;
        }
    }
    __syncthreads();

    size_t sbase = (size_t)(b*C_ + c) * (M_*M_);
    {
        int c4 = t & 15, mr = t >> 4;
#pragma unroll
        for (int p = 0; p < 4; ++p) {
            int m = mr + p*16;
            *(float4*)&Buf[m][c4*4] = *(const float4*)(g_Spre + sbase + (size_t)m*M_ + c4*4);
        }
    }
    __syncthreads();

    u64 acc[4][2];
#pragma unroll
    for (int i = 0; i < 4; ++i) { acc[i][0] = 0ull; acc[i][1] = 0ull; }
#pragma unroll 8
    for (int m = 0; m < 64; ++m) {
        u64 b0 = *(const u64*)&Buf[m][tx*4];
        u64 b1 = *(const u64*)&Buf[m][tx*4+2];
#pragma unroll
        for (int i = 0; i < 4; ++i) {
            u64 ad = dup2(Qs[ty*4+i][m]);
            acc[i][0] = fma2(ad, b0, acc[i][0]);
            acc[i][1] = fma2(ad, b1, acc[i][1]);
        }
    }
#pragma unroll
    for (int i = 0; i < 4; ++i) {
        u64 sc = dup2(powf(d, (float)(ty*4 + i + 1)));
        acc[i][0] = mul2(acc[i][0], sc);
        acc[i][1] = mul2(acc[i][1], sc);
    }
    __syncthreads();

    {
        int c4 = t & 15, sr = t >> 4;
#pragma unroll
        for (int p = 0; p < 4; ++p) {
            int s = sr + p*16;
            *(float4*)&Buf[s][c4*4] = *(const float4*)(g_GV + (rbase+s)*M_ + c4*4);
        }
    }
    __syncthreads();

#pragma unroll 8
    for (int sp = 0; sp < 64; ++sp) {
        u64 b0 = *(const u64*)&Buf[sp][tx*4];
        u64 b1 = *(const u64*)&Buf[sp][tx*4+2];
#pragma unroll
        for (int i = 0; i < 4; ++i) {
            u64 ad = dup2(Ps[ty*4+i][sp]);
            acc[i][0] = fma2(ad, b0, acc[i][0]);
            acc[i][1] = fma2(ad, b1, acc[i][1]);
        }
    }
#pragma unroll
    for (int i = 0; i < 4; ++i) {
        float v0,v1,v2,v3;
        upk2(acc[i][0], v0, v1);
        upk2(acc[i][1], v2, v3);
        *(float4*)(g_O + (rbase + ty*4 + i)*M_ + tx*4) = make_float4(v0,v1,v2,v3);
    }
}

// ---------- kernel 6: y = O @ Wo + bo via warp MMA (3-term split) ----------
#define OH_OFF 0
#define OL_OFF 18432
#define WHO_OFF 36864
#define WLO_OFF 55296
#define OUT_SMEM 73728
#define ORS 144

__global__ void __launch_bounds__(256, 2) out_mma_kernel(
        const float* __restrict__ Wo, const float* __restrict__ bo,
        float* __restrict__ y) {
    extern __shared__ char smem[];
    u32 sb = smem_u32(smem);
    int t = threadIdx.x;
    int lane = t & 31, wid = t >> 5;
    int warp_m = wid >> 1, warp_n = wid & 1;
    int r0 = blockIdx.x * 128;
    int n0 = blockIdx.y * 128;

#pragma unroll
    for (int rep = 0; rep < 8; ++rep) {
        int idx = t + rep*256;
        int row = idx >> 4, c4 = idx & 15;
        float4 v = *(const float4*)(g_O + (size_t)(r0 + row)*M_ + c4*4);
        u32 h0,l0,h1,l1;
        split2(v.x, v.y, h0, l0);
        split2(v.z, v.w, h1, l1);
        int off = row*ORS + c4*8;
        *(u32*)(smem + OH_OFF + off)   = h0;
        *(u32*)(smem + OH_OFF + off+4) = h1;
        *(u32*)(smem + OL_OFF + off)   = l0;
        *(u32*)(smem + OL_OFF + off+4) = l1;
    }
#pragma unroll
    for (int p = 0; p < 4; ++p) {
        int idx = t + p*256;
        int kp = idx & 31;
        int nf = idx >> 5;
        float4 a = *(const float4*)(Wo + (size_t)(2*kp)*D_   + n0 + nf*4);
        float4 b = *(const float4*)(Wo + (size_t)(2*kp+1)*D_ + n0 + nf*4);
        float av[4] = {a.x, a.y, a.z, a.w};
        float bv[4] = {b.x, b.y, b.z, b.w};
#pragma unroll
        for (int i = 0; i < 4; ++i) {
            u32 hi, lo;
            split2(av[i], bv[i], hi, lo);
            int off = (nf*4 + i)*ORS + kp*4;
            *(u32*)(smem + WHO_OFF + off) = hi;
            *(u32*)(smem + WLO_OFF + off) = lo;
        }
    }
    __syncthreads();

    int laneA_row = lane & 15;
    int laneA_kb  = (lane >> 4) * 16;
    int laneB_n   = (lane & 7) + ((lane >> 4) << 3);
    int laneB_kb  = ((lane >> 3) & 1) * 16;

    float acc[2][8][4];
#pragma unroll
    for (int i = 0; i < 2; ++i)
#pragma unroll
        for (int j = 0; j < 8; ++j)
#pragma unroll
            for (int k = 0; k < 4; ++k) acc[i][j][k] = 0.f;

#pragma unroll
    for (int ko = 0; ko < 4; ++ko) {
        int kb = ko*32;
        u32 Ah[2][4], Al[2][4], Bb[8][2];
#pragma unroll
        for (int mt = 0; mt < 2; ++mt) {
            u32 aoff = (u32)((warp_m*32 + mt*16 + laneA_row)*ORS + kb + laneA_kb);
            ldsm4(Ah[mt][0], Ah[mt][1], Ah[mt][2], Ah[mt][3], sb + OH_OFF + aoff);
            ldsm4(Al[mt][0], Al[mt][1], Al[mt][2], Al[mt][3], sb + OL_OFF + aoff);
        }
#pragma unroll
        for (int np = 0; np < 4; ++np) {
            u32 boff = (u32)((warp_n*64 + np*16 + laneB_n)*ORS + kb + laneB_kb);
            ldsm4(Bb[2*np][0], Bb[2*np][1], Bb[2*np+1][0], Bb[2*np+1][1],
                  sb + WHO_OFF + boff);
        }
#pragma unroll
        for (int mt = 0; mt < 2; ++mt)
#pragma unroll
            for (int nt = 0; nt < 8; ++nt) mma_bf16(acc[mt][nt], Ah[mt], Bb[nt]);
#pragma unroll
        for (int mt = 0; mt < 2; ++mt)
#pragma unroll
            for (int nt = 0; nt < 8; ++nt) mma_bf16(acc[mt][nt], Al[mt], Bb[nt]);
#pragma unroll
        for (int np = 0; np < 4; ++np) {
            u32 boff = (u32)((warp_n*64 + np*16 + laneB_n)*ORS + kb + laneB_kb);
            ldsm4(Bb[2*np][0], Bb[2*np][1], Bb[2*np+1][0], Bb[2*np+1][1],
                  sb + WLO_OFF + boff);
        }
#pragma unroll
        for (int mt = 0; mt < 2; ++mt)
#pragma unroll
            for (int nt = 0; nt < 8; ++nt) mma_bf16(acc[mt][nt], Ah[mt], Bb[nt]);
    }

    int g8 = lane >> 2, t2 = lane & 3;
#pragma unroll
    for (int mt = 0; mt < 2; ++mt) {
        int row = r0 + warp_m*32 + mt*16 + g8;
#pragma unroll
        for (int nt = 0; nt < 8; ++nt) {
            int col = n0 + warp_n*64 + nt*8 + t2*2;
            float2 bias = *(const float2*)(bo + col);
            *(float2*)(y + (size_t)row*D_ + col) =
                make_float2(acc[mt][nt][0] + bias.x, acc[mt][nt][1] + bias.y);
            *(float2*)(y + (size_t)(row + 8)*D_ + col) =
                make_float2(acc[mt][nt][2] + bias.x, acc[mt][nt][3] + bias.y);
        }
    }
}

// ---------------- launcher ----------------
extern "C" void kernel_launch(void* const* d_in, const int* in_sizes, int n_in,
                              void* d_out, int out_size) {
    const float* x  = (const float*)d_in[0];
    const float* Wq = (const float*)d_in[1];
    const float* Wk = (const float*)d_in[2];
    const float* Wv = (const float*)d_in[3];
    const float* Wo = (const float*)d_in[4];
    const float* bo = (const float*)d_in[5];
    const float* Wg = (const float*)d_in[6];
    const float* bg = (const float*)d_in[7];
    const float* dp = (const float*)d_in[8];
    float* y      = (float*)d_out;
    float* sfinal = y + (size_t)BL_ * D_;

    cudaFuncSetAttribute(qkv_mma_kernel,
                         cudaFuncAttributeMaxDynamicSharedMemorySize, QKV_SMEM);
    cudaFuncSetAttribute(out_mma_kernel,
                         cudaFuncAttributeMaxDynamicSharedMemorySize, OUT_SMEM);

    wprep_kernel     <<<768, 256>>>(Wq, Wk, Wv);
    qkv_mma_kernel   <<<BL_/128, 512, QKV_SMEM>>>(x, Wg, bg);
    chunk_sum_kernel <<<dim3(C_, B_), 256>>>(dp);
    chunk_scan_kernel<<<(B_*M_*M_)/256, 256>>>(dp, sfinal);
    chunk_out_kernel <<<dim3(C_, B_), 256>>>(dp);
    out_mma_kernel   <<<dim3(BL_/128, D_/128), 256, OUT_SMEM>>>(Wo, bo, y);
}

// round 9
// speedup vs baseline: 2.4393x; 1.0307x over previous
#include <cuda_runtime.h>
#include <cuda_bf16.h>
#include <cstdint>
#include <math.h>

#define B_  8
#define L_  4096
#define D_  1024
#define M_  64
#define BL_ (B_*L_)
#define C_  64
#define T_  64

typedef unsigned long long u64;
typedef unsigned int u32;
typedef unsigned short u16;

// ---------------- scratch ----------------
__device__ float g_Q   [BL_*M_];
__device__ float g_GK  [BL_*M_];
__device__ float g_GV  [BL_*M_];
__device__ float g_A   [B_*C_*M_*M_];
__device__ float g_Spre[B_*C_*M_*M_];
__device__ float g_O   [BL_*M_];
__device__ u16   g_Wh  [32*192*32];   // split W hi, [it][n][k]
__device__ u16   g_Wl  [32*192*32];   // split W lo

__device__ __forceinline__ float decay_val(const float* dp) {
    return 0.9f + 0.099f / (1.0f + expf(-dp[0]));
}

// ---- warp MMA helpers ----
__device__ __forceinline__ u32 smem_u32(const void* p) {
    u32 a;
    asm("{ .reg .u64 t; cvta.to.shared.u64 t, %1; cvt.u32.u64 %0, t; }" : "=r"(a) : "l"(p));
    return a;
}
__device__ __forceinline__ void ldsm4(u32& r0, u32& r1, u32& r2, u32& r3, u32 a) {
    asm volatile("ldmatrix.sync.aligned.m8n8.x4.shared.b16 {%0,%1,%2,%3},[%4];"
                 : "=r"(r0), "=r"(r1), "=r"(r2), "=r"(r3) : "r"(a));
}
__device__ __forceinline__ void mma_bf16(float* d, const u32* a, const u32* b) {
    asm volatile(
        "mma.sync.aligned.m16n8k16.row.col.f32.bf16.bf16.f32 "
        "{%0,%1,%2,%3},{%4,%5,%6,%7},{%8,%9},{%0,%1,%2,%3};"
        : "+f"(d[0]), "+f"(d[1]), "+f"(d[2]), "+f"(d[3])
        : "r"(a[0]), "r"(a[1]), "r"(a[2]), "r"(a[3]), "r"(b[0]), "r"(b[1]));
}
__device__ __forceinline__ void split2(float x0, float x1, u32& hi, u32& lo) {
    __nv_bfloat162 h = __floats2bfloat162_rn(x0, x1);
    float r0 = x0 - __bfloat162float(h.x);
    float r1 = x1 - __bfloat162float(h.y);
    __nv_bfloat162 l = __floats2bfloat162_rn(r0, r1);
    hi = *(u32*)&h;  lo = *(u32*)&l;
}
__device__ __forceinline__ void split1(float x, u16& hi, u16& lo) {
    __nv_bfloat16 h = __float2bfloat16(x);
    __nv_bfloat16 l = __float2bfloat16(x - __bfloat162float(h));
    hi = *(u16*)&h;  lo = *(u16*)&l;
}
__device__ __forceinline__ void cpasync16(u32 dst, const void* src) {
    asm volatile("cp.async.cg.shared.global [%0], [%1], 16;" :: "r"(dst), "l"(src));
}

// ---------- kernel 0: W prep — split bf16, staged layout [it][n][k] --------
__global__ void wprep_kernel(const float* __restrict__ Wq,
                             const float* __restrict__ Wk,
                             const float* __restrict__ Wv) {
    int idx = blockIdx.x*256 + threadIdx.x;
    int kk = idx & 31;
    int r  = idx >> 5;
    int n  = r % 192;
    int it = r / 192;
    int col = n & 63;
    const float* Wp = (n < 64) ? Wq : (n < 128) ? Wk : Wv;
    float w = Wp[(size_t)(it*32 + kk)*M_ + col];
    u16 hi, lo;
    split1(w, hi, lo);
    g_Wh[idx] = hi;
    g_Wl[idx] = lo;
}

// SMEM layout for qkv (bytes), double-buffered. Row stride 80 B.
#define RS 80
#define XHo(b)  ((b)*10240)
#define XLo(b)  (20480 + (b)*10240)
#define WHo(b)  (40960 + (b)*15360)
#define WLo(b)  (71680 + (b)*15360)
#define WGV_OFF 102400
#define GATE_OFF 106496
#define QKV_SMEM 107008

// ========== kernel 1: fused QKV+gate, warp MMA, double-buffered ====
__global__ void __launch_bounds__(512, 1) qkv_mma_kernel(
        const float* __restrict__ x,
        const float* __restrict__ Wg, const float* __restrict__ bg) {
    extern __shared__ char smem[];
    u32 sb = smem_u32(smem);
    int t = threadIdx.x;
    int lane = t & 31, wid = t >> 5;
    int warp_m = wid >> 2, warp_n = wid & 3;
    int r0 = blockIdx.x * 128;

    if (t < 256) *(float4*)(smem + WGV_OFF + t*16) = *(const float4*)(Wg + t*4);
    const float* wgs = (const float*)(smem + WGV_OFF);

    int rowX = t >> 3;
    int c4   = t & 7;

    int wn[3], wc[3], wterm[3];
#pragma unroll
    for (int rr = 0; rr < 3; ++rr) {
        int idx = t + rr*512;
        wterm[rr] = (idx >= 768);
        int rem = idx - wterm[rr]*768;
        wn[rr] = rem >> 2;
        wc[rr] = rem & 3;
    }

    int laneA_row = lane & 15;
    int laneA_kb  = (lane >> 4) * 16;
    int laneB_n   = (lane & 7) + ((lane >> 4) << 3);
    int laneB_kb  = ((lane >> 3) & 1) * 16;

    float acc[2][6][4];
#pragma unroll
    for (int i = 0; i < 2; ++i)
#pragma unroll
        for (int j = 0; j < 6; ++j)
#pragma unroll
            for (int k = 0; k < 4; ++k) acc[i][j][k] = 0.f;
    float gacc[2] = {0.f, 0.f};

    __syncthreads();

    float4 xr0 = *(const float4*)(x + (size_t)(r0 + rowX)*D_ + c4*4);
    float4 xr1 = *(const float4*)(x + (size_t)(r0 + rowX + 64)*D_ + c4*4);
#pragma unroll
    for (int rr = 0; rr < 3; ++rr) {
        u32 dst = sb + (wterm[rr] ? WLo(0) : WHo(0)) + wn[rr]*RS + wc[rr]*16;
        const u16* src = (wterm[rr] ? g_Wl : g_Wh) + ((0*192 + wn[rr])*32 + wc[rr]*8);
        cpasync16(dst, src);
    }
    asm volatile("cp.async.commit_group;" ::: "memory");

#pragma unroll 1
    for (int it = 0; it < 32; ++it) {
        int buf = it & 1;
        int k0 = it * 32;
        {
            const float* wg4 = wgs + k0 + c4*4;
            gacc[0] += xr0.x*wg4[0] + xr0.y*wg4[1] + xr0.z*wg4[2] + xr0.w*wg4[3];
            gacc[1] += xr1.x*wg4[0] + xr1.y*wg4[1] + xr1.z*wg4[2] + xr1.w*wg4[3];
            u32 h0,l0,h1,l1;
            split2(xr0.x, xr0.y, h0, l0);
            split2(xr0.z, xr0.w, h1, l1);
            int off = rowX*RS + c4*8;
            *(u32*)(smem + XHo(buf) + off)   = h0;
            *(u32*)(smem + XHo(buf) + off+4) = h1;
            *(u32*)(smem + XLo(buf) + off)   = l0;
            *(u32*)(smem + XLo(buf) + off+4) = l1;
            split2(xr1.x, xr1.y, h0, l0);
            split2(xr1.z, xr1.w, h1, l1);
            off = (rowX + 64)*RS + c4*8;
            *(u32*)(smem + XHo(buf) + off)   = h0;
            *(u32*)(smem + XHo(buf) + off+4) = h1;
            *(u32*)(smem + XLo(buf) + off)   = l0;
            *(u32*)(smem + XLo(buf) + off+4) = l1;
        }
        asm volatile("cp.async.wait_group 0;" ::: "memory");
        __syncthreads();
        if (it < 31) {
            int k1 = k0 + 32;
            xr0 = *(const float4*)(x + (size_t)(r0 + rowX)*D_ + k1 + c4*4);
            xr1 = *(const float4*)(x + (size_t)(r0 + rowX + 64)*D_ + k1 + c4*4);
#pragma unroll
            for (int rr = 0; rr < 3; ++rr) {
                u32 dst = sb + (wterm[rr] ? WLo(buf^1) : WHo(buf^1)) + wn[rr]*RS + wc[rr]*16;
                const u16* src = (wterm[rr] ? g_Wl : g_Wh)
                               + (((it+1)*192 + wn[rr])*32 + wc[rr]*8);
                cpasync16(dst, src);
            }
            asm volatile("cp.async.commit_group;" ::: "memory");
        }
#pragma unroll
        for (int ko = 0; ko < 2; ++ko) {
            int kb = ko*32;
            u32 Ah[2][4], Al[2][4], Bb[6][2];
#pragma unroll
            for (int mt = 0; mt < 2; ++mt) {
                u32 aoff = (u32)((warp_m*32 + mt*16 + laneA_row)*RS + kb + laneA_kb);
                ldsm4(Ah[mt][0], Ah[mt][1], Ah[mt][2], Ah[mt][3], sb + XHo(buf) + aoff);
                ldsm4(Al[mt][0], Al[mt][1], Al[mt][2], Al[mt][3], sb + XLo(buf) + aoff);
            }
#pragma unroll
            for (int np = 0; np < 3; ++np) {
                u32 boff = (u32)((warp_n*48 + np*16 + laneB_n)*RS + kb + laneB_kb);
                ldsm4(Bb[2*np][0], Bb[2*np][1], Bb[2*np+1][0], Bb[2*np+1][1],
                      sb + WHo(buf) + boff);
            }
#pragma unroll
            for (int mt = 0; mt < 2; ++mt)
#pragma unroll
                for (int nt = 0; nt < 6; ++nt) mma_bf16(acc[mt][nt], Ah[mt], Bb[nt]);
#pragma unroll
            for (int mt = 0; mt < 2; ++mt)
#pragma unroll
                for (int nt = 0; nt < 6; ++nt) mma_bf16(acc[mt][nt], Al[mt], Bb[nt]);
#pragma unroll
            for (int np = 0; np < 3; ++np) {
                u32 boff = (u32)((warp_n*48 + np*16 + laneB_n)*RS + kb + laneB_kb);
                ldsm4(Bb[2*np][0], Bb[2*np][1], Bb[2*np+1][0], Bb[2*np+1][1],
                      sb + WLo(buf) + boff);
            }
#pragma unroll
            for (int mt = 0; mt < 2; ++mt)
#pragma unroll
                for (int nt = 0; nt < 6; ++nt) mma_bf16(acc[mt][nt], Ah[mt], Bb[nt]);
        }
    }

#pragma unroll
    for (int off = 4; off; off >>= 1)
#pragma unroll
        for (int rep = 0; rep < 2; ++rep)
            gacc[rep] += __shfl_xor_sync(0xffffffffu, gacc[rep], off);
    if ((t & 7) == 0) {
        float bgv = bg[0];
        ((float*)(smem + GATE_OFF))[rowX]      = 1.0f/(1.0f + expf(-(gacc[0] + bgv)));
        ((float*)(smem + GATE_OFF))[rowX + 64] = 1.0f/(1.0f + expf(-(gacc[1] + bgv)));
    }
    __syncthreads();
    const float* gate = (const float*)(smem + GATE_OFF);

    int g8 = lane >> 2, t2 = lane & 3;
#pragma unroll
    for (int mt = 0; mt < 2; ++mt) {
        int rl0 = warp_m*32 + mt*16 + g8;
#pragma unroll
        for (int nt = 0; nt < 6; ++nt) {
            int col = warp_n*48 + nt*8 + t2*2;
            int proj = col >> 6, lc = col & 63;
            float* Out = (proj == 0) ? g_Q : (proj == 1) ? g_GK : g_GV;
            float ga = (proj == 0) ? 1.0f : gate[rl0];
            float gb = (proj == 0) ? 1.0f : gate[rl0 + 8];
            float2 o0 = make_float2(acc[mt][nt][0]*ga, acc[mt][nt][1]*ga);
            float2 o1 = make_float2(acc[mt][nt][2]*gb, acc[mt][nt][3]*gb);
            *(float2*)(Out + (size_t)(r0 + rl0)*M_ + lc)     = o0;
            *(float2*)(Out + (size_t)(r0 + rl0 + 8)*M_ + lc) = o1;
        }
    }
}

// ---- shared chunk-kernel constants: 64x64 bf16 tiles, 144 B row stride ----
#define CRS 144

// --------- kernel 3: chunk summaries via warp MMA (3-term split) -----------
// A_c[i][j] = sum_s d^{63-s} gk[s][i] gv[s][j];  256 thr = 8 warps (4m x 2n)
#define CS_AH 0
#define CS_AL 9216
#define CS_BH 18432
#define CS_BL 27648
#define CS_DP 36864
#define CS_SMEM 37376

__global__ void __launch_bounds__(256) chunk_sum_kernel(const float* __restrict__ dp) {
    extern __shared__ char smem[];
    u32 sb = smem_u32(smem);
    int b = blockIdx.y, c = blockIdx.x;
    int t = threadIdx.x, lane = t & 31, wid = t >> 5;
    int warp_m = wid >> 1, warp_n = wid & 1;
    float d = decay_val(dp);
    float* dpow = (float*)(smem + CS_DP);
    if (t < 64) dpow[t] = powf(d, (float)t);
    __syncthreads();

    size_t base = ((size_t)b*L_ + (size_t)c*T_) * M_;
#pragma unroll
    for (int rep = 0; rep < 4; ++rep) {
        int idx = t + rep*256;
        int s = idx >> 4, c4 = idx & 15;
        float w = dpow[63 - s];
        float4 kv = *(const float4*)(g_GK + base + (size_t)s*M_ + c4*4);
        float4 vv = *(const float4*)(g_GV + base + (size_t)s*M_ + c4*4);
        float kvv[4] = {kv.x*w, kv.y*w, kv.z*w, kv.w*w};
        float vvv[4] = {vv.x, vv.y, vv.z, vv.w};
#pragma unroll
        for (int i = 0; i < 4; ++i) {
            u16 hi, lo;
            int off = (c4*4 + i)*CRS + s*2;
            split1(kvv[i], hi, lo);
            *(u16*)(smem + CS_AH + off) = hi;
            *(u16*)(smem + CS_AL + off) = lo;
            split1(vvv[i], hi, lo);
            *(u16*)(smem + CS_BH + off) = hi;
            *(u16*)(smem + CS_BL + off) = lo;
        }
    }
    __syncthreads();

    int laneA_row = lane & 15;
    int laneA_kb  = (lane >> 4) * 16;
    int laneB_n   = (lane & 7) + ((lane >> 4) << 3);
    int laneB_kb  = ((lane >> 3) & 1) * 16;

    float acc[4][4];
#pragma unroll
    for (int j = 0; j < 4; ++j)
#pragma unroll
        for (int k = 0; k < 4; ++k) acc[j][k] = 0.f;

#pragma unroll
    for (int ko = 0; ko < 4; ++ko) {
        int kb = ko*32;
        u32 Ah[4], Al[4], Bb[4][2];
        u32 aoff = (u32)((warp_m*16 + laneA_row)*CRS + kb + laneA_kb);
        ldsm4(Ah[0], Ah[1], Ah[2], Ah[3], sb + CS_AH + aoff);
        ldsm4(Al[0], Al[1], Al[2], Al[3], sb + CS_AL + aoff);
#pragma unroll
        for (int np = 0; np < 2; ++np) {
            u32 boff = (u32)((warp_n*32 + np*16 + laneB_n)*CRS + kb + laneB_kb);
            ldsm4(Bb[2*np][0], Bb[2*np][1], Bb[2*np+1][0], Bb[2*np+1][1],
                  sb + CS_BH + boff);
        }
#pragma unroll
        for (int nt = 0; nt < 4; ++nt) mma_bf16(acc[nt], Ah, Bb[nt]);
#pragma unroll
        for (int nt = 0; nt < 4; ++nt) mma_bf16(acc[nt], Al, Bb[nt]);
#pragma unroll
        for (int np = 0; np < 2; ++np) {
            u32 boff = (u32)((warp_n*32 + np*16 + laneB_n)*CRS + kb + laneB_kb);
            ldsm4(Bb[2*np][0], Bb[2*np][1], Bb[2*np+1][0], Bb[2*np+1][1],
                  sb + CS_BL + boff);
        }
#pragma unroll
        for (int nt = 0; nt < 4; ++nt) mma_bf16(acc[nt], Ah, Bb[nt]);
    }

    int g8 = lane >> 2, t2 = lane & 3;
    size_t ab = (size_t)(b*C_ + c) * (M_*M_);
#pragma unroll
    for (int nt = 0; nt < 4; ++nt) {
        int j = warp_n*32 + nt*8 + t2*2;
        int i0 = warp_m*16 + g8;
        *(float2*)(g_A + ab + (size_t)i0*M_ + j)     = make_float2(acc[nt][0], acc[nt][1]);
        *(float2*)(g_A + ab + (size_t)(i0+8)*M_ + j) = make_float2(acc[nt][2], acc[nt][3]);
    }
}

// --------- kernel 4: inter-chunk scan (MLP-8) ----------
__global__ void chunk_scan_kernel(const float* __restrict__ dp,
                                  float* __restrict__ sfinal) {
    int gid = blockIdx.x * blockDim.x + threadIdx.x;
    int b = gid >> 12;
    int e = gid & 4095;
    float d  = decay_val(dp);
    float dT = powf(d, 64.0f);
    float S = 0.f;
#pragma unroll 1
    for (int c0 = 0; c0 < C_; c0 += 8) {
        float a[8];
#pragma unroll
        for (int j = 0; j < 8; ++j)
            a[j] = g_A[((size_t)(b*C_ + c0 + j) << 12) + e];
#pragma unroll
        for (int j = 0; j < 8; ++j) {
            g_Spre[((size_t)(b*C_ + c0 + j) << 12) + e] = S;
            S = dT*S + a[j];
        }
    }
    sfinal[((size_t)b << 12) + e] = S;
}

// --------- kernel 5: per-chunk outputs via warp MMA (3-term split) ---------
// O = d^{s+1} Q@Spre + (QK^T ⊙ mask)@GV;  256 thr = 8 warps (4m x 2n)
#define CO_QH 0
#define CO_QL 9216
#define CO_PH 18432
#define CO_PL 27648
#define CO_BH 36864
#define CO_BL 46080
#define CO_DP 55296
#define CO_SMEM 55808

__global__ void __launch_bounds__(256) chunk_out_kernel(const float* __restrict__ dp) {
    extern __shared__ char smem[];
    u32 sb = smem_u32(smem);
    int b = blockIdx.y, c = blockIdx.x;
    int t = threadIdx.x, lane = t & 31, wid = t >> 5;
    int warp_m = wid >> 1, warp_n = wid & 1;
    float d = decay_val(dp);
    float* dpow = (float*)(smem + CO_DP);
    if (t < 65) dpow[t] = powf(d, (float)t);

    size_t rbase = (size_t)b*L_ + (size_t)c*T_;
    size_t sbase = (size_t)(b*C_ + c) * (M_*M_);

    // ---- stage Q (A operand, natural) and GK (B operand, natural) ----
#pragma unroll
    for (int rep = 0; rep < 4; ++rep) {
        int idx = t + rep*256;
        int row = idx >> 4, c4 = idx & 15;
        float4 q = *(const float4*)(g_Q  + (rbase + row)*M_ + c4*4);
        float4 k = *(const float4*)(g_GK + (rbase + row)*M_ + c4*4);
        u32 h0,l0,h1,l1;
        int off = row*CRS + c4*8;
        split2(q.x, q.y, h0, l0);  split2(q.z, q.w, h1, l1);
        *(u32*)(smem + CO_QH + off)   = h0;  *(u32*)(smem + CO_QH + off+4) = h1;
        *(u32*)(smem + CO_QL + off)   = l0;  *(u32*)(smem + CO_QL + off+4) = l1;
        split2(k.x, k.y, h0, l0);  split2(k.z, k.w, h1, l1);
        *(u32*)(smem + CO_BH + off)   = h0;  *(u32*)(smem + CO_BH + off+4) = h1;
        *(u32*)(smem + CO_BL + off)   = l0;  *(u32*)(smem + CO_BL + off+4) = l1;
    }
    __syncthreads();

    int laneA_row = lane & 15;
    int laneA_kb  = (lane >> 4) * 16;
    int laneB_n   = (lane & 7) + ((lane >> 4) << 3);
    int laneB_kb  = ((lane >> 3) & 1) * 16;
    int g8 = lane >> 2, t2 = lane & 3;

    // ---- phase 1: P = Q @ GK^T ----
    float pacc[4][4];
#pragma unroll
    for (int j = 0; j < 4; ++j)
#pragma unroll
        for (int k = 0; k < 4; ++k) pacc[j][k] = 0.f;
#pragma unroll
    for (int ko = 0; ko < 4; ++ko) {
        int kb = ko*32;
        u32 Ah[4], Al[4], Bb[4][2];
        u32 aoff = (u32)((warp_m*16 + laneA_row)*CRS + kb + laneA_kb);
        ldsm4(Ah[0], Ah[1], Ah[2], Ah[3], sb + CO_QH + aoff);
        ldsm4(Al[0], Al[1], Al[2], Al[3], sb + CO_QL + aoff);
#pragma unroll
        for (int np = 0; np < 2; ++np) {
            u32 boff = (u32)((warp_n*32 + np*16 + laneB_n)*CRS + kb + laneB_kb);
            ldsm4(Bb[2*np][0], Bb[2*np][1], Bb[2*np+1][0], Bb[2*np+1][1],
                  sb + CO_BH + boff);
        }
#pragma unroll
        for (int nt = 0; nt < 4; ++nt) mma_bf16(pacc[nt], Ah, Bb[nt]);
#pragma unroll
        for (int nt = 0; nt < 4; ++nt) mma_bf16(pacc[nt], Al, Bb[nt]);
#pragma unroll
        for (int np = 0; np < 2; ++np) {
            u32 boff = (u32)((warp_n*32 + np*16 + laneB_n)*CRS + kb + laneB_kb);
            ldsm4(Bb[2*np][0], Bb[2*np][1], Bb[2*np+1][0], Bb[2*np+1][1],
                  sb + CO_BL + boff);
        }
#pragma unroll
        for (int nt = 0; nt < 4; ++nt) mma_bf16(pacc[nt], Ah, Bb[nt]);
    }
    // ---- mask + decay, store P (split) ----
#pragma unroll
    for (int nt = 0; nt < 4; ++nt) {
        int colb = warp_n*32 + nt*8 + t2*2;
        int ra = warp_m*16 + g8;
        float p0 = (colb   <= ra) ? pacc[nt][0]*dpow[ra - colb]     : 0.f;
        float p1 = (colb+1 <= ra) ? pacc[nt][1]*dpow[ra - colb - 1] : 0.f;
        int rb = ra + 8;
        float p2 = (colb   <= rb) ? pacc[nt][2]*dpow[rb - colb]     : 0.f;
        float p3 = (colb+1 <= rb) ? pacc[nt][3]*dpow[rb - colb - 1] : 0.f;
        u32 hi, lo;
        split2(p0, p1, hi, lo);
        *(u32*)(smem + CO_PH + ra*CRS + colb*2) = hi;
        *(u32*)(smem + CO_PL + ra*CRS + colb*2) = lo;
        split2(p2, p3, hi, lo);
        *(u32*)(smem + CO_PH + rb*CRS + colb*2) = hi;
        *(u32*)(smem + CO_PL + rb*CRS + colb*2) = lo;
    }
    __syncthreads();   // phase-1 B reads done; safe to restage B

    // ---- stage Spre^T into B ----
#pragma unroll
    for (int rep = 0; rep < 4; ++rep) {
        int idx = t + rep*256;
        int m = idx >> 4, c4 = idx & 15;
        float4 v = *(const float4*)(g_Spre + sbase + (size_t)m*M_ + c4*4);
        float vv[4] = {v.x, v.y, v.z, v.w};
#pragma unroll
        for (int i = 0; i < 4; ++i) {
            u16 hi, lo;
            split1(vv[i], hi, lo);
            int off = (c4*4 + i)*CRS + m*2;
            *(u16*)(smem + CO_BH + off) = hi;
            *(u16*)(smem + CO_BL + off) = lo;
        }
    }
    __syncthreads();

    // ---- phase 2: acc = Q @ Spre ----
    float acc[4][4];
#pragma unroll
    for (int j = 0; j < 4; ++j)
#pragma unroll
        for (int k = 0; k < 4; ++k) acc[j][k] = 0.f;
#pragma unroll
    for (int ko = 0; ko < 4; ++ko) {
        int kb = ko*32;
        u32 Ah[4], Al[4], Bb[4][2];
        u32 aoff = (u32)((warp_m*16 + laneA_row)*CRS + kb + laneA_kb);
        ldsm4(Ah[0], Ah[1], Ah[2], Ah[3], sb + CO_QH + aoff);
        ldsm4(Al[0], Al[1], Al[2], Al[3], sb + CO_QL + aoff);
#pragma unroll
        for (int np = 0; np < 2; ++np) {
            u32 boff = (u32)((warp_n*32 + np*16 + laneB_n)*CRS + kb + laneB_kb);
            ldsm4(Bb[2*np][0], Bb[2*np][1], Bb[2*np+1][0], Bb[2*np+1][1],
                  sb + CO_BH + boff);
        }
#pragma unroll
        for (int nt = 0; nt < 4; ++nt) mma_bf16(acc[nt], Ah, Bb[nt]);
#pragma unroll
        for (int nt = 0; nt < 4; ++nt) mma_bf16(acc[nt], Al, Bb[nt]);
#pragma unroll
        for (int np = 0; np < 2; ++np) {
            u32 boff = (u32)((warp_n*32 + np*16 + laneB_n)*CRS + kb + laneB_kb);
            ldsm4(Bb[2*np][0], Bb[2*np][1], Bb[2*np+1][0], Bb[2*np+1][1],
                  sb + CO_BL + boff);
        }
#pragma unroll
        for (int nt = 0; nt < 4; ++nt) mma_bf16(acc[nt], Ah, Bb[nt]);
    }
    // scale by d^{s+1}
    {
        int ra = warp_m*16 + g8;
        float sa = dpow[ra + 1], sbc = dpow[ra + 9];
#pragma unroll
        for (int nt = 0; nt < 4; ++nt) {
            acc[nt][0] *= sa;  acc[nt][1] *= sa;
            acc[nt][2] *= sbc; acc[nt][3] *= sbc;
        }
    }
    __syncthreads();   // phase-2 B reads done

    // ---- stage GV^T into B ----
#pragma unroll
    for (int rep = 0; rep < 4; ++rep) {
        int idx = t + rep*256;
        int s = idx >> 4, c4 = idx & 15;
        float4 v = *(const float4*)(g_GV + (rbase + s)*M_ + c4*4);
        float vv[4] = {v.x, v.y, v.z, v.w};
#pragma unroll
        for (int i = 0; i < 4; ++i) {
            u16 hi, lo;
            split1(vv[i], hi, lo);
            int off = (c4*4 + i)*CRS + s*2;
            *(u16*)(smem + CO_BH + off) = hi;
            *(u16*)(smem + CO_BL + off) = lo;
        }
    }
    __syncthreads();

    // ---- phase 3: acc += P @ GV ----
#pragma unroll
    for (int ko = 0; ko < 4; ++ko) {
        int kb = ko*32;
        u32 Ah[4], Al[4], Bb[4][2];
        u32 aoff = (u32)((warp_m*16 + laneA_row)*CRS + kb + laneA_kb);
        ldsm4(Ah[0], Ah[1], Ah[2], Ah[3], sb + CO_PH + aoff);
        ldsm4(Al[0], Al[1], Al[2], Al[3], sb + CO_PL + aoff);
#pragma unroll
        for (int np = 0; np < 2; ++np) {
            u32 boff = (u32)((warp_n*32 + np*16 + laneB_n)*CRS + kb + laneB_kb);
            ldsm4(Bb[2*np][0], Bb[2*np][1], Bb[2*np+1][0], Bb[2*np+1][1],
                  sb + CO_BH + boff);
        }
#pragma unroll
        for (int nt = 0; nt < 4; ++nt) mma_bf16(acc[nt], Ah, Bb[nt]);
#pragma unroll
        for (int nt = 0; nt < 4; ++nt) mma_bf16(acc[nt], Al, Bb[nt]);
#pragma unroll
        for (int np = 0; np < 2; ++np) {
            u32 boff = (u32)((warp_n*32 + np*16 + laneB_n)*CRS + kb + laneB_kb);
            ldsm4(Bb[2*np][0], Bb[2*np][1], Bb[2*np+1][0], Bb[2*np+1][1],
                  sb + CO_BL + boff);
        }
#pragma unroll
        for (int nt = 0; nt < 4; ++nt) mma_bf16(acc[nt], Ah, Bb[nt]);
    }

    // ---- write O ----
#pragma unroll
    for (int nt = 0; nt < 4; ++nt) {
        int j = warp_n*32 + nt*8 + t2*2;
        int i0 = warp_m*16 + g8;
        *(float2*)(g_O + (rbase + i0)*M_ + j)     = make_float2(acc[nt][0], acc[nt][1]);
        *(float2*)(g_O + (rbase + i0 + 8)*M_ + j) = make_float2(acc[nt][2], acc[nt][3]);
    }
}

// ---------- kernel 6: y = O @ Wo + bo via warp MMA (3-term split) ----------
#define OH_OFF 0
#define OL_OFF 18432
#define WHO_OFF 36864
#define WLO_OFF 55296
#define OUT_SMEM 73728
#define ORS 144

__global__ void __launch_bounds__(256, 2) out_mma_kernel(
        const float* __restrict__ Wo, const float* __restrict__ bo,
        float* __restrict__ y) {
    extern __shared__ char smem[];
    u32 sb = smem_u32(smem);
    int t = threadIdx.x;
    int lane = t & 31, wid = t >> 5;
    int warp_m = wid >> 1, warp_n = wid & 1;
    int r0 = blockIdx.x * 128;
    int n0 = blockIdx.y * 128;

#pragma unroll
    for (int rep = 0; rep < 8; ++rep) {
        int idx = t + rep*256;
        int row = idx >> 4, c4 = idx & 15;
        float4 v = *(const float4*)(g_O + (size_t)(r0 + row)*M_ + c4*4);
        u32 h0,l0,h1,l1;
        split2(v.x, v.y, h0, l0);
        split2(v.z, v.w, h1, l1);
        int off = row*ORS + c4*8;
        *(u32*)(smem + OH_OFF + off)   = h0;
        *(u32*)(smem + OH_OFF + off+4) = h1;
        *(u32*)(smem + OL_OFF + off)   = l0;
        *(u32*)(smem + OL_OFF + off+4) = l1;
    }
#pragma unroll
    for (int p = 0; p < 4; ++p) {
        int idx = t + p*256;
        int kp = idx & 31;
        int nf = idx >> 5;
        float4 a = *(const float4*)(Wo + (size_t)(2*kp)*D_   + n0 + nf*4);
        float4 b = *(const float4*)(Wo + (size_t)(2*kp+1)*D_ + n0 + nf*4);
        float av[4] = {a.x, a.y, a.z, a.w};
        float bv[4] = {b.x, b.y, b.z, b.w};
#pragma unroll
        for (int i = 0; i < 4; ++i) {
            u32 hi, lo;
            split2(av[i], bv[i], hi, lo);
            int off = (nf*4 + i)*ORS + kp*4;
            *(u32*)(smem + WHO_OFF + off) = hi;
            *(u32*)(smem + WLO_OFF + off) = lo;
        }
    }
    __syncthreads();

    int laneA_row = lane & 15;
    int laneA_kb  = (lane >> 4) * 16;
    int laneB_n   = (lane & 7) + ((lane >> 4) << 3);
    int laneB_kb  = ((lane >> 3) & 1) * 16;

    float acc[2][8][4];
#pragma unroll
    for (int i = 0; i < 2; ++i)
#pragma unroll
        for (int j = 0; j < 8; ++j)
#pragma unroll
            for (int k = 0; k < 4; ++k) acc[i][j][k] = 0.f;

#pragma unroll
    for (int ko = 0; ko < 4; ++ko) {
        int kb = ko*32;
        u32 Ah[2][4], Al[2][4], Bb[8][2];
#pragma unroll
        for (int mt = 0; mt < 2; ++mt) {
            u32 aoff = (u32)((warp_m*32 + mt*16 + laneA_row)*ORS + kb + laneA_kb);
            ldsm4(Ah[mt][0], Ah[mt][1], Ah[mt][2], Ah[mt][3], sb + OH_OFF + aoff);
            ldsm4(Al[mt][0], Al[mt][1], Al[mt][2], Al[mt][3], sb + OL_OFF + aoff);
        }
#pragma unroll
        for (int np = 0; np < 4; ++np) {
            u32 boff = (u32)((warp_n*64 + np*16 + laneB_n)*ORS + kb + laneB_kb);
            ldsm4(Bb[2*np][0], Bb[2*np][1], Bb[2*np+1][0], Bb[2*np+1][1],
                  sb + WHO_OFF + boff);
        }
#pragma unroll
        for (int mt = 0; mt < 2; ++mt)
#pragma unroll
            for (int nt = 0; nt < 8; ++nt) mma_bf16(acc[mt][nt], Ah[mt], Bb[nt]);
#pragma unroll
        for (int mt = 0; mt < 2; ++mt)
#pragma unroll
            for (int nt = 0; nt < 8; ++nt) mma_bf16(acc[mt][nt], Al[mt], Bb[nt]);
#pragma unroll
        for (int np = 0; np < 4; ++np) {
            u32 boff = (u32)((warp_n*64 + np*16 + laneB_n)*ORS + kb + laneB_kb);
            ldsm4(Bb[2*np][0], Bb[2*np][1], Bb[2*np+1][0], Bb[2*np+1][1],
                  sb + WLO_OFF + boff);
        }
#pragma unroll
        for (int mt = 0; mt < 2; ++mt)
#pragma unroll
            for (int nt = 0; nt < 8; ++nt) mma_bf16(acc[mt][nt], Ah[mt], Bb[nt]);
    }

    int g8 = lane >> 2, t2 = lane & 3;
#pragma unroll
    for (int mt = 0; mt < 2; ++mt) {
        int row = r0 + warp_m*32 + mt*16 + g8;
#pragma unroll
        for (int nt = 0; nt < 8; ++nt) {
            int col = n0 + warp_n*64 + nt*8 + t2*2;
            float2 bias = *(const float2*)(bo + col);
            *(float2*)(y + (size_t)row*D_ + col) =
                make_float2(acc[mt][nt][0] + bias.x, acc[mt][nt][1] + bias.y);
            *(float2*)(y + (size_t)(row + 8)*D_ + col) =
                make_float2(acc[mt][nt][2] + bias.x, acc[mt][nt][3] + bias.y);
        }
    }
}

// ---------------- launcher ----------------
extern "C" void kernel_launch(void* const* d_in, const int* in_sizes, int n_in,
                              void* d_out, int out_size) {
    const float* x  = (const float*)d_in[0];
    const float* Wq = (const float*)d_in[1];
    const float* Wk = (const float*)d_in[2];
    const float* Wv = (const float*)d_in[3];
    const float* Wo = (const float*)d_in[4];
    const float* bo = (const float*)d_in[5];
    const float* Wg = (const float*)d_in[6];
    const float* bg = (const float*)d_in[7];
    const float* dp = (const float*)d_in[8];
    float* y      = (float*)d_out;
    float* sfinal = y + (size_t)BL_ * D_;

    cudaFuncSetAttribute(qkv_mma_kernel,
                         cudaFuncAttributeMaxDynamicSharedMemorySize, QKV_SMEM);
    cudaFuncSetAttribute(out_mma_kernel,
                         cudaFuncAttributeMaxDynamicSharedMemorySize, OUT_SMEM);
    cudaFuncSetAttribute(chunk_sum_kernel,
                         cudaFuncAttributeMaxDynamicSharedMemorySize, CS_SMEM);
    cudaFuncSetAttribute(chunk_out_kernel,
                         cudaFuncAttributeMaxDynamicSharedMemorySize, CO_SMEM);

    wprep_kernel     <<<768, 256>>>(Wq, Wk, Wv);
    qkv_mma_kernel   <<<BL_/128, 512, QKV_SMEM>>>(x, Wg, bg);
    chunk_sum_kernel <<<dim3(C_, B_), 256, CS_SMEM>>>(dp);
    chunk_scan_kernel<<<(B_*M_*M_)/256, 256>>>(dp, sfinal);
    chunk_out_kernel <<<dim3(C_, B_), 256, CO_SMEM>>>(dp);
    out_mma_kernel   <<<dim3(BL_/128, D_/128), 256, OUT_SMEM>>>(Wo, bo, y);
}

// round 10
// speedup vs baseline: 2.4900x; 1.0208x over previous
#include <cuda_runtime.h>
#include <cuda_bf16.h>
#include <cstdint>
#include <math.h>

#define B_  8
#define L_  4096
#define D_  1024
#define M_  64
#define BL_ (B_*L_)
#define C_  64
#define T_  64

typedef unsigned long long u64;
typedef unsigned int u32;
typedef unsigned short u16;

// ---------------- scratch ----------------
__device__ float g_Q   [BL_*M_];
__device__ float g_GK  [BL_*M_];
__device__ float g_GV  [BL_*M_];
__device__ float g_A   [B_*C_*M_*M_];
__device__ float g_Spre[B_*C_*M_*M_];
__device__ float g_O   [BL_*M_];
__device__ u16   g_Wh  [32*192*32];     // split W hi, [it][n][k]
__device__ u16   g_Wl  [32*192*32];     // split W lo
__device__ u32   g_WoH [8*128*32];      // split Wo hi, [(blk*128+n)][kp] packed pairs
__device__ u32   g_WoL [8*128*32];

__device__ __forceinline__ float decay_val(const float* dp) {
    return 0.9f + 0.099f / (1.0f + expf(-dp[0]));
}

// ---- warp MMA helpers ----
__device__ __forceinline__ u32 smem_u32(const void* p) {
    u32 a;
    asm("{ .reg .u64 t; cvta.to.shared.u64 t, %1; cvt.u32.u64 %0, t; }" : "=r"(a) : "l"(p));
    return a;
}
__device__ __forceinline__ void ldsm4(u32& r0, u32& r1, u32& r2, u32& r3, u32 a) {
    asm volatile("ldmatrix.sync.aligned.m8n8.x4.shared.b16 {%0,%1,%2,%3},[%4];"
                 : "=r"(r0), "=r"(r1), "=r"(r2), "=r"(r3) : "r"(a));
}
__device__ __forceinline__ void mma_bf16(float* d, const u32* a, const u32* b) {
    asm volatile(
        "mma.sync.aligned.m16n8k16.row.col.f32.bf16.bf16.f32 "
        "{%0,%1,%2,%3},{%4,%5,%6,%7},{%8,%9},{%0,%1,%2,%3};"
        : "+f"(d[0]), "+f"(d[1]), "+f"(d[2]), "+f"(d[3])
        : "r"(a[0]), "r"(a[1]), "r"(a[2]), "r"(a[3]), "r"(b[0]), "r"(b[1]));
}
__device__ __forceinline__ void split2(float x0, float x1, u32& hi, u32& lo) {
    __nv_bfloat162 h = __floats2bfloat162_rn(x0, x1);
    float r0 = x0 - __bfloat162float(h.x);
    float r1 = x1 - __bfloat162float(h.y);
    __nv_bfloat162 l = __floats2bfloat162_rn(r0, r1);
    hi = *(u32*)&h;  lo = *(u32*)&l;
}
__device__ __forceinline__ void split1(float x, u16& hi, u16& lo) {
    __nv_bfloat16 h = __float2bfloat16(x);
    __nv_bfloat16 l = __float2bfloat16(x - __bfloat162float(h));
    hi = *(u16*)&h;  lo = *(u16*)&l;
}
__device__ __forceinline__ void cpasync16(u32 dst, const void* src) {
    asm volatile("cp.async.cg.shared.global [%0], [%1], 16;" :: "r"(dst), "l"(src));
}

// ---------- kernel 0a: W prep — split bf16, staged layout [it][n][k] -------
__global__ void wprep_kernel(const float* __restrict__ Wq,
                             const float* __restrict__ Wk,
                             const float* __restrict__ Wv) {
    int idx = blockIdx.x*256 + threadIdx.x;
    int kk = idx & 31;
    int r  = idx >> 5;
    int n  = r % 192;
    int it = r / 192;
    int col = n & 63;
    const float* Wp = (n < 64) ? Wq : (n < 128) ? Wk : Wv;
    float w = Wp[(size_t)(it*32 + kk)*M_ + col];
    u16 hi, lo;
    split1(w, hi, lo);
    g_Wh[idx] = hi;
    g_Wl[idx] = lo;
}

// ---------- kernel 0b: Wo prep — split pairs, staged layout ----------------
__global__ void woprep_kernel(const float* __restrict__ Wo) {
    int idx = blockIdx.x*256 + threadIdx.x;      // 0..32767
    int kp = idx & 31;
    int n  = (idx >> 5) & 127;
    int blk = idx >> 12;
    int ng = blk*128 + n;
    u32 hi, lo;
    split2(Wo[(size_t)(2*kp)*D_ + ng], Wo[(size_t)(2*kp+1)*D_ + ng], hi, lo);
    g_WoH[idx] = hi;
    g_WoL[idx] = lo;
}

// SMEM layout for qkv (bytes), double-buffered, 64-row tiles. Row stride 80 B.
#define RS 80
#define XHo(b)  ((b)*5120)
#define XLo(b)  (10240 + (b)*5120)
#define WHo(b)  (20480 + (b)*15360)
#define WLo(b)  (51200 + (b)*15360)
#define WGV_OFF 81920
#define GATE_OFF 86016
#define QKV_SMEM 86528

// ========== kernel 1: fused QKV+gate, warp MMA, 2 CTAs/SM ====
// 64-row tiles, 256 threads = 8 warps (2m x 4n), warp tile 32m x 48n.
__global__ void __launch_bounds__(256, 2) qkv_mma_kernel(
        const float* __restrict__ x,
        const float* __restrict__ Wg, const float* __restrict__ bg) {
    extern __shared__ char smem[];
    u32 sb = smem_u32(smem);
    int t = threadIdx.x;
    int lane = t & 31, wid = t >> 5;
    int warp_m = wid >> 2, warp_n = wid & 3;
    int r0 = blockIdx.x * 64;

    *(float4*)(smem + WGV_OFF + t*16) = *(const float4*)(Wg + t*4);
    const float* wgs = (const float*)(smem + WGV_OFF);

    int rowX = t >> 3;            // 0..31 (and +32)
    int c4   = t & 7;

    int wn[6], wc[6], wterm[6];
#pragma unroll
    for (int rr = 0; rr < 6; ++rr) {
        int idx = t + rr*256;
        wterm[rr] = (idx >= 768);
        int rem = idx - wterm[rr]*768;
        wn[rr] = rem >> 2;
        wc[rr] = rem & 3;
    }

    int laneA_row = lane & 15;
    int laneA_kb  = (lane >> 4) * 16;
    int laneB_n   = (lane & 7) + ((lane >> 4) << 3);
    int laneB_kb  = ((lane >> 3) & 1) * 16;

    float acc[2][6][4];
#pragma unroll
    for (int i = 0; i < 2; ++i)
#pragma unroll
        for (int j = 0; j < 6; ++j)
#pragma unroll
            for (int k = 0; k < 4; ++k) acc[i][j][k] = 0.f;
    float gacc[2] = {0.f, 0.f};

    __syncthreads();

    float4 xr0 = *(const float4*)(x + (size_t)(r0 + rowX)*D_ + c4*4);
    float4 xr1 = *(const float4*)(x + (size_t)(r0 + rowX + 32)*D_ + c4*4);
#pragma unroll
    for (int rr = 0; rr < 6; ++rr) {
        u32 dst = sb + (wterm[rr] ? WLo(0) : WHo(0)) + wn[rr]*RS + wc[rr]*16;
        const u16* src = (wterm[rr] ? g_Wl : g_Wh) + ((0*192 + wn[rr])*32 + wc[rr]*8);
        cpasync16(dst, src);
    }
    asm volatile("cp.async.commit_group;" ::: "memory");

#pragma unroll 1
    for (int it = 0; it < 32; ++it) {
        int buf = it & 1;
        int k0 = it * 32;
        {
            const float* wg4 = wgs + k0 + c4*4;
            gacc[0] += xr0.x*wg4[0] + xr0.y*wg4[1] + xr0.z*wg4[2] + xr0.w*wg4[3];
            gacc[1] += xr1.x*wg4[0] + xr1.y*wg4[1] + xr1.z*wg4[2] + xr1.w*wg4[3];
            u32 h0,l0,h1,l1;
            split2(xr0.x, xr0.y, h0, l0);
            split2(xr0.z, xr0.w, h1, l1);
            int off = rowX*RS + c4*8;
            *(u32*)(smem + XHo(buf) + off)   = h0;
            *(u32*)(smem + XHo(buf) + off+4) = h1;
            *(u32*)(smem + XLo(buf) + off)   = l0;
            *(u32*)(smem + XLo(buf) + off+4) = l1;
            split2(xr1.x, xr1.y, h0, l0);
            split2(xr1.z, xr1.w, h1, l1);
            off = (rowX + 32)*RS + c4*8;
            *(u32*)(smem + XHo(buf) + off)   = h0;
            *(u32*)(smem + XHo(buf) + off+4) = h1;
            *(u32*)(smem + XLo(buf) + off)   = l0;
            *(u32*)(smem + XLo(buf) + off+4) = l1;
        }
        asm volatile("cp.async.wait_group 0;" ::: "memory");
        __syncthreads();
        if (it < 31) {
            int k1 = k0 + 32;
            xr0 = *(const float4*)(x + (size_t)(r0 + rowX)*D_ + k1 + c4*4);
            xr1 = *(const float4*)(x + (size_t)(r0 + rowX + 32)*D_ + k1 + c4*4);
#pragma unroll
            for (int rr = 0; rr < 6; ++rr) {
                u32 dst = sb + (wterm[rr] ? WLo(buf^1) : WHo(buf^1)) + wn[rr]*RS + wc[rr]*16;
                const u16* src = (wterm[rr] ? g_Wl : g_Wh)
                               + (((it+1)*192 + wn[rr])*32 + wc[rr]*8);
                cpasync16(dst, src);
            }
            asm volatile("cp.async.commit_group;" ::: "memory");
        }
#pragma unroll
        for (int ko = 0; ko < 2; ++ko) {
            int kb = ko*32;
            u32 Ah[2][4], Al[2][4], Bb[6][2];
#pragma unroll
            for (int mt = 0; mt < 2; ++mt) {
                u32 aoff = (u32)((warp_m*32 + mt*16 + laneA_row)*RS + kb + laneA_kb);
                ldsm4(Ah[mt][0], Ah[mt][1], Ah[mt][2], Ah[mt][3], sb + XHo(buf) + aoff);
                ldsm4(Al[mt][0], Al[mt][1], Al[mt][2], Al[mt][3], sb + XLo(buf) + aoff);
            }
#pragma unroll
            for (int np = 0; np < 3; ++np) {
                u32 boff = (u32)((warp_n*48 + np*16 + laneB_n)*RS + kb + laneB_kb);
                ldsm4(Bb[2*np][0], Bb[2*np][1], Bb[2*np+1][0], Bb[2*np+1][1],
                      sb + WHo(buf) + boff);
            }
#pragma unroll
            for (int mt = 0; mt < 2; ++mt)
#pragma unroll
                for (int nt = 0; nt < 6; ++nt) mma_bf16(acc[mt][nt], Ah[mt], Bb[nt]);
#pragma unroll
            for (int mt = 0; mt < 2; ++mt)
#pragma unroll
                for (int nt = 0; nt < 6; ++nt) mma_bf16(acc[mt][nt], Al[mt], Bb[nt]);
#pragma unroll
            for (int np = 0; np < 3; ++np) {
                u32 boff = (u32)((warp_n*48 + np*16 + laneB_n)*RS + kb + laneB_kb);
                ldsm4(Bb[2*np][0], Bb[2*np][1], Bb[2*np+1][0], Bb[2*np+1][1],
                      sb + WLo(buf) + boff);
            }
#pragma unroll
            for (int mt = 0; mt < 2; ++mt)
#pragma unroll
                for (int nt = 0; nt < 6; ++nt) mma_bf16(acc[mt][nt], Ah[mt], Bb[nt]);
        }
    }

    // gates: reduce over the 8 lanes sharing each row
#pragma unroll
    for (int off = 4; off; off >>= 1)
#pragma unroll
        for (int rep = 0; rep < 2; ++rep)
            gacc[rep] += __shfl_xor_sync(0xffffffffu, gacc[rep], off);
    if ((t & 7) == 0) {
        float bgv = bg[0];
        ((float*)(smem + GATE_OFF))[rowX]      = 1.0f/(1.0f + expf(-(gacc[0] + bgv)));
        ((float*)(smem + GATE_OFF))[rowX + 32] = 1.0f/(1.0f + expf(-(gacc[1] + bgv)));
    }
    __syncthreads();
    const float* gate = (const float*)(smem + GATE_OFF);

    int g8 = lane >> 2, t2 = lane & 3;
#pragma unroll
    for (int mt = 0; mt < 2; ++mt) {
        int rl0 = warp_m*32 + mt*16 + g8;
#pragma unroll
        for (int nt = 0; nt < 6; ++nt) {
            int col = warp_n*48 + nt*8 + t2*2;
            int proj = col >> 6, lc = col & 63;
            float* Out = (proj == 0) ? g_Q : (proj == 1) ? g_GK : g_GV;
            float ga = (proj == 0) ? 1.0f : gate[rl0];
            float gb = (proj == 0) ? 1.0f : gate[rl0 + 8];
            float2 o0 = make_float2(acc[mt][nt][0]*ga, acc[mt][nt][1]*ga);
            float2 o1 = make_float2(acc[mt][nt][2]*gb, acc[mt][nt][3]*gb);
            *(float2*)(Out + (size_t)(r0 + rl0)*M_ + lc)     = o0;
            *(float2*)(Out + (size_t)(r0 + rl0 + 8)*M_ + lc) = o1;
        }
    }
}

// ---- shared chunk-kernel constants: 64x64 bf16 tiles, 144 B row stride ----
#define CRS 144

// --------- kernel 3: chunk summaries via warp MMA (3-term split) -----------
#define CS_AH 0
#define CS_AL 9216
#define CS_BH 18432
#define CS_BL 27648
#define CS_DP 36864
#define CS_SMEM 37376

__global__ void __launch_bounds__(256) chunk_sum_kernel(const float* __restrict__ dp) {
    extern __shared__ char smem[];
    u32 sb = smem_u32(smem);
    int b = blockIdx.y, c = blockIdx.x;
    int t = threadIdx.x, lane = t & 31, wid = t >> 5;
    int warp_m = wid >> 1, warp_n = wid & 1;
    float d = decay_val(dp);
    float* dpow = (float*)(smem + CS_DP);
    if (t < 64) dpow[t] = powf(d, (float)t);
    __syncthreads();

    size_t base = ((size_t)b*L_ + (size_t)c*T_) * M_;
#pragma unroll
    for (int rep = 0; rep < 4; ++rep) {
        int idx = t + rep*256;
        int s = idx >> 4, c4 = idx & 15;
        float w = dpow[63 - s];
        float4 kv = *(const float4*)(g_GK + base + (size_t)s*M_ + c4*4);
        float4 vv = *(const float4*)(g_GV + base + (size_t)s*M_ + c4*4);
        float kvv[4] = {kv.x*w, kv.y*w, kv.z*w, kv.w*w};
        float vvv[4] = {vv.x, vv.y, vv.z, vv.w};
#pragma unroll
        for (int i = 0; i < 4; ++i) {
            u16 hi, lo;
            int off = (c4*4 + i)*CRS + s*2;
            split1(kvv[i], hi, lo);
            *(u16*)(smem + CS_AH + off) = hi;
            *(u16*)(smem + CS_AL + off) = lo;
            split1(vvv[i], hi, lo);
            *(u16*)(smem + CS_BH + off) = hi;
            *(u16*)(smem + CS_BL + off) = lo;
        }
    }
    __syncthreads();

    int laneA_row = lane & 15;
    int laneA_kb  = (lane >> 4) * 16;
    int laneB_n   = (lane & 7) + ((lane >> 4) << 3);
    int laneB_kb  = ((lane >> 3) & 1) * 16;

    float acc[4][4];
#pragma unroll
    for (int j = 0; j < 4; ++j)
#pragma unroll
        for (int k = 0; k < 4; ++k) acc[j][k] = 0.f;

#pragma unroll
    for (int ko = 0; ko < 4; ++ko) {
        int kb = ko*32;
        u32 Ah[4], Al[4], Bb[4][2];
        u32 aoff = (u32)((warp_m*16 + laneA_row)*CRS + kb + laneA_kb);
        ldsm4(Ah[0], Ah[1], Ah[2], Ah[3], sb + CS_AH + aoff);
        ldsm4(Al[0], Al[1], Al[2], Al[3], sb + CS_AL + aoff);
#pragma unroll
        for (int np = 0; np < 2; ++np) {
            u32 boff = (u32)((warp_n*32 + np*16 + laneB_n)*CRS + kb + laneB_kb);
            ldsm4(Bb[2*np][0], Bb[2*np][1], Bb[2*np+1][0], Bb[2*np+1][1],
                  sb + CS_BH + boff);
        }
#pragma unroll
        for (int nt = 0; nt < 4; ++nt) mma_bf16(acc[nt], Ah, Bb[nt]);
#pragma unroll
        for (int nt = 0; nt < 4; ++nt) mma_bf16(acc[nt], Al, Bb[nt]);
#pragma unroll
        for (int np = 0; np < 2; ++np) {
            u32 boff = (u32)((warp_n*32 + np*16 + laneB_n)*CRS + kb + laneB_kb);
            ldsm4(Bb[2*np][0], Bb[2*np][1], Bb[2*np+1][0], Bb[2*np+1][1],
                  sb + CS_BL + boff);
        }
#pragma unroll
        for (int nt = 0; nt < 4; ++nt) mma_bf16(acc[nt], Ah, Bb[nt]);
    }

    int g8 = lane >> 2, t2 = lane & 3;
    size_t ab = (size_t)(b*C_ + c) * (M_*M_);
#pragma unroll
    for (int nt = 0; nt < 4; ++nt) {
        int j = warp_n*32 + nt*8 + t2*2;
        int i0 = warp_m*16 + g8;
        *(float2*)(g_A + ab + (size_t)i0*M_ + j)     = make_float2(acc[nt][0], acc[nt][1]);
        *(float2*)(g_A + ab + (size_t)(i0+8)*M_ + j) = make_float2(acc[nt][2], acc[nt][3]);
    }
}

// --------- kernel 4: inter-chunk scan (MLP-8) ----------
__global__ void chunk_scan_kernel(const float* __restrict__ dp,
                                  float* __restrict__ sfinal) {
    int gid = blockIdx.x * blockDim.x + threadIdx.x;
    int b = gid >> 12;
    int e = gid & 4095;
    float d  = decay_val(dp);
    float dT = powf(d, 64.0f);
    float S = 0.f;
#pragma unroll 1
    for (int c0 = 0; c0 < C_; c0 += 8) {
        float a[8];
#pragma unroll
        for (int j = 0; j < 8; ++j)
            a[j] = g_A[((size_t)(b*C_ + c0 + j) << 12) + e];
#pragma unroll
        for (int j = 0; j < 8; ++j) {
            g_Spre[((size_t)(b*C_ + c0 + j) << 12) + e] = S;
            S = dT*S + a[j];
        }
    }
    sfinal[((size_t)b << 12) + e] = S;
}

// --------- kernel 5: per-chunk outputs via warp MMA (3-term split) ---------
#define CO_QH 0
#define CO_QL 9216
#define CO_PH 18432
#define CO_PL 27648
#define CO_BH 36864
#define CO_BL 46080
#define CO_DP 55296
#define CO_SMEM 55808

__global__ void __launch_bounds__(256) chunk_out_kernel(const float* __restrict__ dp) {
    extern __shared__ char smem[];
    u32 sb = smem_u32(smem);
    int b = blockIdx.y, c = blockIdx.x;
    int t = threadIdx.x, lane = t & 31, wid = t >> 5;
    int warp_m = wid >> 1, warp_n = wid & 1;
    float d = decay_val(dp);
    float* dpow = (float*)(smem + CO_DP);
    if (t < 65) dpow[t] = powf(d, (float)t);

    size_t rbase = (size_t)b*L_ + (size_t)c*T_;
    size_t sbase = (size_t)(b*C_ + c) * (M_*M_);

#pragma unroll
    for (int rep = 0; rep < 4; ++rep) {
        int idx = t + rep*256;
        int row = idx >> 4, c4 = idx & 15;
        float4 q = *(const float4*)(g_Q  + (rbase + row)*M_ + c4*4);
        float4 k = *(const float4*)(g_GK + (rbase + row)*M_ + c4*4);
        u32 h0,l0,h1,l1;
        int off = row*CRS + c4*8;
        split2(q.x, q.y, h0, l0);  split2(q.z, q.w, h1, l1);
        *(u32*)(smem + CO_QH + off)   = h0;  *(u32*)(smem + CO_QH + off+4) = h1;
        *(u32*)(smem + CO_QL + off)   = l0;  *(u32*)(smem + CO_QL + off+4) = l1;
        split2(k.x, k.y, h0, l0);  split2(k.z, k.w, h1, l1);
        *(u32*)(smem + CO_BH + off)   = h0;  *(u32*)(smem + CO_BH + off+4) = h1;
        *(u32*)(smem + CO_BL + off)   = l0;  *(u32*)(smem + CO_BL + off+4) = l1;
    }
    __syncthreads();

    int laneA_row = lane & 15;
    int laneA_kb  = (lane >> 4) * 16;
    int laneB_n   = (lane & 7) + ((lane >> 4) << 3);
    int laneB_kb  = ((lane >> 3) & 1) * 16;
    int g8 = lane >> 2, t2 = lane & 3;

    // phase 1: P = Q @ GK^T
    float pacc[4][4];
#pragma unroll
    for (int j = 0; j < 4; ++j)
#pragma unroll
        for (int k = 0; k < 4; ++k) pacc[j][k] = 0.f;
#pragma unroll
    for (int ko = 0; ko < 4; ++ko) {
        int kb = ko*32;
        u32 Ah[4], Al[4], Bb[4][2];
        u32 aoff = (u32)((warp_m*16 + laneA_row)*CRS + kb + laneA_kb);
        ldsm4(Ah[0], Ah[1], Ah[2], Ah[3], sb + CO_QH + aoff);
        ldsm4(Al[0], Al[1], Al[2], Al[3], sb + CO_QL + aoff);
#pragma unroll
        for (int np = 0; np < 2; ++np) {
            u32 boff = (u32)((warp_n*32 + np*16 + laneB_n)*CRS + kb + laneB_kb);
            ldsm4(Bb[2*np][0], Bb[2*np][1], Bb[2*np+1][0], Bb[2*np+1][1],
                  sb + CO_BH + boff);
        }
#pragma unroll
        for (int nt = 0; nt < 4; ++nt) mma_bf16(pacc[nt], Ah, Bb[nt]);
#pragma unroll
        for (int nt = 0; nt < 4; ++nt) mma_bf16(pacc[nt], Al, Bb[nt]);
#pragma unroll
        for (int np = 0; np < 2; ++np) {
            u32 boff = (u32)((warp_n*32 + np*16 + laneB_n)*CRS + kb + laneB_kb);
            ldsm4(Bb[2*np][0], Bb[2*np][1], Bb[2*np+1][0], Bb[2*np+1][1],
                  sb + CO_BL + boff);
        }
#pragma unroll
        for (int nt = 0; nt < 4; ++nt) mma_bf16(pacc[nt], Ah, Bb[nt]);
    }
#pragma unroll
    for (int nt = 0; nt < 4; ++nt) {
        int colb = warp_n*32 + nt*8 + t2*2;
        int ra = warp_m*16 + g8;
        float p0 = (colb   <= ra) ? pacc[nt][0]*dpow[ra - colb]     : 0.f;
        float p1 = (colb+1 <= ra) ? pacc[nt][1]*dpow[ra - colb - 1] : 0.f;
        int rb = ra + 8;
        float p2 = (colb   <= rb) ? pacc[nt][2]*dpow[rb - colb]     : 0.f;
        float p3 = (colb+1 <= rb) ? pacc[nt][3]*dpow[rb - colb - 1] : 0.f;
        u32 hi, lo;
        split2(p0, p1, hi, lo);
        *(u32*)(smem + CO_PH + ra*CRS + colb*2) = hi;
        *(u32*)(smem + CO_PL + ra*CRS + colb*2) = lo;
        split2(p2, p3, hi, lo);
        *(u32*)(smem + CO_PH + rb*CRS + colb*2) = hi;
        *(u32*)(smem + CO_PL + rb*CRS + colb*2) = lo;
    }
    __syncthreads();

    // stage Spre^T into B
#pragma unroll
    for (int rep = 0; rep < 4; ++rep) {
        int idx = t + rep*256;
        int m = idx >> 4, c4 = idx & 15;
        float4 v = *(const float4*)(g_Spre + sbase + (size_t)m*M_ + c4*4);
        float vv[4] = {v.x, v.y, v.z, v.w};
#pragma unroll
        for (int i = 0; i < 4; ++i) {
            u16 hi, lo;
            split1(vv[i], hi, lo);
            int off = (c4*4 + i)*CRS + m*2;
            *(u16*)(smem + CO_BH + off) = hi;
            *(u16*)(smem + CO_BL + off) = lo;
        }
    }
    __syncthreads();

    // phase 2: acc = Q @ Spre
    float acc[4][4];
#pragma unroll
    for (int j = 0; j < 4; ++j)
#pragma unroll
        for (int k = 0; k < 4; ++k) acc[j][k] = 0.f;
#pragma unroll
    for (int ko = 0; ko < 4; ++ko) {
        int kb = ko*32;
        u32 Ah[4], Al[4], Bb[4][2];
        u32 aoff = (u32)((warp_m*16 + laneA_row)*CRS + kb + laneA_kb);
        ldsm4(Ah[0], Ah[1], Ah[2], Ah[3], sb + CO_QH + aoff);
        ldsm4(Al[0], Al[1], Al[2], Al[3], sb + CO_QL + aoff);
#pragma unroll
        for (int np = 0; np < 2; ++np) {
            u32 boff = (u32)((warp_n*32 + np*16 + laneB_n)*CRS + kb + laneB_kb);
            ldsm4(Bb[2*np][0], Bb[2*np][1], Bb[2*np+1][0], Bb[2*np+1][1],
                  sb + CO_BH + boff);
        }
#pragma unroll
        for (int nt = 0; nt < 4; ++nt) mma_bf16(acc[nt], Ah, Bb[nt]);
#pragma unroll
        for (int nt = 0; nt < 4; ++nt) mma_bf16(acc[nt], Al, Bb[nt]);
#pragma unroll
        for (int np = 0; np < 2; ++np) {
            u32 boff = (u32)((warp_n*32 + np*16 + laneB_n)*CRS + kb + laneB_kb);
            ldsm4(Bb[2*np][0], Bb[2*np][1], Bb[2*np+1][0], Bb[2*np+1][1],
                  sb + CO_BL + boff);
        }
#pragma unroll
        for (int nt = 0; nt < 4; ++nt) mma_bf16(acc[nt], Ah, Bb[nt]);
    }
    {
        int ra = warp_m*16 + g8;
        float sa = dpow[ra + 1], sbc = dpow[ra + 9];
#pragma unroll
        for (int nt = 0; nt < 4; ++nt) {
            acc[nt][0] *= sa;  acc[nt][1] *= sa;
            acc[nt][2] *= sbc; acc[nt][3] *= sbc;
        }
    }
    __syncthreads();

    // stage GV^T into B
#pragma unroll
    for (int rep = 0; rep < 4; ++rep) {
        int idx = t + rep*256;
        int s = idx >> 4, c4 = idx & 15;
        float4 v = *(const float4*)(g_GV + (rbase + s)*M_ + c4*4);
        float vv[4] = {v.x, v.y, v.z, v.w};
#pragma unroll
        for (int i = 0; i < 4; ++i) {
            u16 hi, lo;
            split1(vv[i], hi, lo);
            int off = (c4*4 + i)*CRS + s*2;
            *(u16*)(smem + CO_BH + off) = hi;
            *(u16*)(smem + CO_BL + off) = lo;
        }
    }
    __syncthreads();

    // phase 3: acc += P @ GV
#pragma unroll
    for (int ko = 0; ko < 4; ++ko) {
        int kb = ko*32;
        u32 Ah[4], Al[4], Bb[4][2];
        u32 aoff = (u32)((warp_m*16 + laneA_row)*CRS + kb + laneA_kb);
        ldsm4(Ah[0], Ah[1], Ah[2], Ah[3], sb + CO_PH + aoff);
        ldsm4(Al[0], Al[1], Al[2], Al[3], sb + CO_PL + aoff);
#pragma unroll
        for (int np = 0; np < 2; ++np) {
            u32 boff = (u32)((warp_n*32 + np*16 + laneB_n)*CRS + kb + laneB_kb);
            ldsm4(Bb[2*np][0], Bb[2*np][1], Bb[2*np+1][0], Bb[2*np+1][1],
                  sb + CO_BH + boff);
        }
#pragma unroll
        for (int nt = 0; nt < 4; ++nt) mma_bf16(acc[nt], Ah, Bb[nt]);
#pragma unroll
        for (int nt = 0; nt < 4; ++nt) mma_bf16(acc[nt], Al, Bb[nt]);
#pragma unroll
        for (int np = 0; np < 2; ++np) {
            u32 boff = (u32)((warp_n*32 + np*16 + laneB_n)*CRS + kb + laneB_kb);
            ldsm4(Bb[2*np][0], Bb[2*np][1], Bb[2*np+1][0], Bb[2*np+1][1],
                  sb + CO_BL + boff);
        }
#pragma unroll
        for (int nt = 0; nt < 4; ++nt) mma_bf16(acc[nt], Ah, Bb[nt]);
    }

#pragma unroll
    for (int nt = 0; nt < 4; ++nt) {
        int j = warp_n*32 + nt*8 + t2*2;
        int i0 = warp_m*16 + g8;
        *(float2*)(g_O + (rbase + i0)*M_ + j)     = make_float2(acc[nt][0], acc[nt][1]);
        *(float2*)(g_O + (rbase + i0 + 8)*M_ + j) = make_float2(acc[nt][2], acc[nt][3]);
    }
}

// ---------- kernel 6: y = O @ Wo + bo via warp MMA (3-term split) ----------
#define OH_OFF 0
#define OL_OFF 18432
#define WHO_OFF 36864
#define WLO_OFF 55296
#define OUT_SMEM 73728
#define ORS 144

__global__ void __launch_bounds__(256, 2) out_mma_kernel(
        const float* __restrict__ bo, float* __restrict__ y) {
    extern __shared__ char smem[];
    u32 sb = smem_u32(smem);
    int t = threadIdx.x;
    int lane = t & 31, wid = t >> 5;
    int warp_m = wid >> 1, warp_n = wid & 1;
    int r0 = blockIdx.x * 128;
    int n0 = blockIdx.y * 128;
    int blk = blockIdx.y;

    // ---- issue Wo staging via cp.async (presplit, 8 chunks/thread) ----
#pragma unroll
    for (int p = 0; p < 4; ++p) {
        int idx = t + p*256;              // 0..1023: row(128) x chunk(8)
        int row = idx >> 3, ch = idx & 7;
        u32 dsth = sb + WHO_OFF + row*ORS + ch*16;
        u32 dstl = sb + WLO_OFF + row*ORS + ch*16;
        const u32* srch = g_WoH + ((blk*128 + row)*32 + ch*4);
        const u32* srcl = g_WoL + ((blk*128 + row)*32 + ch*4);
        cpasync16(dsth, srch);
        cpasync16(dstl, srcl);
    }
    asm volatile("cp.async.commit_group;" ::: "memory");

    // ---- stage O[128 x 64] hi/lo (overlaps Wo copies) ----
#pragma unroll
    for (int rep = 0; rep < 8; ++rep) {
        int idx = t + rep*256;
        int row = idx >> 4, c4 = idx & 15;
        float4 v = *(const float4*)(g_O + (size_t)(r0 + row)*M_ + c4*4);
        u32 h0,l0,h1,l1;
        split2(v.x, v.y, h0, l0);
        split2(v.z, v.w, h1, l1);
        int off = row*ORS + c4*8;
        *(u32*)(smem + OH_OFF + off)   = h0;
        *(u32*)(smem + OH_OFF + off+4) = h1;
        *(u32*)(smem + OL_OFF + off)   = l0;
        *(u32*)(smem + OL_OFF + off+4) = l1;
    }
    asm volatile("cp.async.wait_group 0;" ::: "memory");
    __syncthreads();

    int laneA_row = lane & 15;
    int laneA_kb  = (lane >> 4) * 16;
    int laneB_n   = (lane & 7) + ((lane >> 4) << 3);
    int laneB_kb  = ((lane >> 3) & 1) * 16;

    float acc[2][8][4];
#pragma unroll
    for (int i = 0; i < 2; ++i)
#pragma unroll
        for (int j = 0; j < 8; ++j)
#pragma unroll
            for (int k = 0; k < 4; ++k) acc[i][j][k] = 0.f;

#pragma unroll
    for (int ko = 0; ko < 4; ++ko) {
        int kb = ko*32;
        u32 Ah[2][4], Al[2][4], Bb[8][2];
#pragma unroll
        for (int mt = 0; mt < 2; ++mt) {
            u32 aoff = (u32)((warp_m*32 + mt*16 + laneA_row)*ORS + kb + laneA_kb);
            ldsm4(Ah[mt][0], Ah[mt][1], Ah[mt][2], Ah[mt][3], sb + OH_OFF + aoff);
            ldsm4(Al[mt][0], Al[mt][1], Al[mt][2], Al[mt][3], sb + OL_OFF + aoff);
        }
#pragma unroll
        for (int np = 0; np < 4; ++np) {
            u32 boff = (u32)((warp_n*64 + np*16 + laneB_n)*ORS + kb + laneB_kb);
            ldsm4(Bb[2*np][0], Bb[2*np][1], Bb[2*np+1][0], Bb[2*np+1][1],
                  sb + WHO_OFF + boff);
        }
#pragma unroll
        for (int mt = 0; mt < 2; ++mt)
#pragma unroll
            for (int nt = 0; nt < 8; ++nt) mma_bf16(acc[mt][nt], Ah[mt], Bb[nt]);
#pragma unroll
        for (int mt = 0; mt < 2; ++mt)
#pragma unroll
            for (int nt = 0; nt < 8; ++nt) mma_bf16(acc[mt][nt], Al[mt], Bb[nt]);
#pragma unroll
        for (int np = 0; np < 4; ++np) {
            u32 boff = (u32)((warp_n*64 + np*16 + laneB_n)*ORS + kb + laneB_kb);
            ldsm4(Bb[2*np][0], Bb[2*np][1], Bb[2*np+1][0], Bb[2*np+1][1],
                  sb + WLO_OFF + boff);
        }
#pragma unroll
        for (int mt = 0; mt < 2; ++mt)
#pragma unroll
            for (int nt = 0; nt < 8; ++nt) mma_bf16(acc[mt][nt], Ah[mt], Bb[nt]);
    }

    int g8 = lane >> 2, t2 = lane & 3;
#pragma unroll
    for (int mt = 0; mt < 2; ++mt) {
        int row = r0 + warp_m*32 + mt*16 + g8;
#pragma unroll
        for (int nt = 0; nt < 8; ++nt) {
            int col = n0 + warp_n*64 + nt*8 + t2*2;
            float2 bias = *(const float2*)(bo + col);
            *(float2*)(y + (size_t)row*D_ + col) =
                make_float2(acc[mt][nt][0] + bias.x, acc[mt][nt][1] + bias.y);
            *(float2*)(y + (size_t)(row + 8)*D_ + col) =
                make_float2(acc[mt][nt][2] + bias.x, acc[mt][nt][3] + bias.y);
        }
    }
}

// ---------------- launcher ----------------
extern "C" void kernel_launch(void* const* d_in, const int* in_sizes, int n_in,
                              void* d_out, int out_size) {
    const float* x  = (const float*)d_in[0];
    const float* Wq = (const float*)d_in[1];
    const float* Wk = (const float*)d_in[2];
    const float* Wv = (const float*)d_in[3];
    const float* Wo = (const float*)d_in[4];
    const float* bo = (const float*)d_in[5];
    const float* Wg = (const float*)d_in[6];
    const float* bg = (const float*)d_in[7];
    const float* dp = (const float*)d_in[8];
    float* y      = (float*)d_out;
    float* sfinal = y + (size_t)BL_ * D_;

    cudaFuncSetAttribute(qkv_mma_kernel,
                         cudaFuncAttributeMaxDynamicSharedMemorySize, QKV_SMEM);
    cudaFuncSetAttribute(out_mma_kernel,
                         cudaFuncAttributeMaxDynamicSharedMemorySize, OUT_SMEM);
    cudaFuncSetAttribute(chunk_sum_kernel,
                         cudaFuncAttributeMaxDynamicSharedMemorySize, CS_SMEM);
    cudaFuncSetAttribute(chunk_out_kernel,
                         cudaFuncAttributeMaxDynamicSharedMemorySize, CO_SMEM);

    wprep_kernel     <<<768, 256>>>(Wq, Wk, Wv);
    woprep_kernel    <<<128, 256>>>(Wo);
    qkv_mma_kernel   <<<BL_/64, 256, QKV_SMEM>>>(x, Wg, bg);
    chunk_sum_kernel <<<dim3(C_, B_), 256, CS_SMEM>>>(dp);
    chunk_scan_kernel<<<(B_*M_*M_)/256, 256>>>(dp, sfinal);
    chunk_out_kernel <<<dim3(C_, B_), 256, CO_SMEM>>>(dp);
    out_mma_kernel   <<<dim3(BL_/128, D_/128), 256, OUT_SMEM>>>(bo, y);
}